// round 1
// baseline (speedup 1.0000x reference)
#include <cuda_runtime.h>
#include <cuda_bf16.h>
#include <cstdint>

#define LL   2048
#define HH   3072
#define NHH  24
#define DD   128
#define MLPD 12288
#define W1N  21504   // 3H + MLP
#define CATN 15360   // H + MLP
#define QKVN 9216    // 3H

typedef unsigned long long u64;

// ---------------- f32x2 packed helpers (sm_100+/sm_103a) ----------------
__device__ __forceinline__ u64 pk2(float lo, float hi){
    u64 r; asm("mov.b64 %0, {%1,%2};" : "=l"(r) : "f"(lo), "f"(hi)); return r;
}
__device__ __forceinline__ void up2(u64 p, float& lo, float& hi){
    asm("mov.b64 {%0,%1}, %2;" : "=f"(lo), "=f"(hi) : "l"(p));
}
__device__ __forceinline__ u64 ffma2(u64 a, u64 b, u64 c){
    u64 d; asm("fma.rn.f32x2 %0, %1, %2, %3;" : "=l"(d) : "l"(a), "l"(b), "l"(c)); return d;
}
__device__ __forceinline__ u64 fmul2(u64 a, u64 b){
    u64 d; asm("mul.rn.f32x2 %0, %1, %2;" : "=l"(d) : "l"(a), "l"(b)); return d;
}

// ---------------- scratch (device globals: no allocation allowed) --------
__device__ float g_sv[HH];
__device__ float g_mod[3*HH];
__device__ float g_xmod[(size_t)LL*HH];
__device__ float g_h[(size_t)LL*W1N];      // GEMM1 output (qkv | mlp)
__device__ float g_q[(size_t)NHH*LL*DD];
__device__ float g_k[(size_t)NHH*LL*DD];
__device__ float g_v[(size_t)NHH*LL*DD];
__device__ float g_cat[(size_t)LL*CATN];   // [attn_out | gelu(mlp)]

// ---------------- K1: silu(vec) ----------------
__global__ void silu_k(const float* __restrict__ vec){
    int i = blockIdx.x*256 + threadIdx.x;
    if (i < HH){
        float t = vec[i];
        g_sv[i] = t / (1.f + expf(-t));
    }
}

// ---------------- K2: mod = silu(vec) @ mod_w + mod_b (GEMV) -------------
__global__ __launch_bounds__(256) void mod_gemv(const float* __restrict__ W,
                                                const float* __restrict__ b){
    const int j = blockIdx.x*256 + threadIdx.x;   // 0..9215
    __shared__ float svs[256];
    float acc = b[j];
    for (int c0 = 0; c0 < HH; c0 += 256){
        __syncthreads();
        svs[threadIdx.x] = g_sv[c0 + threadIdx.x];
        __syncthreads();
        #pragma unroll 8
        for (int i = 0; i < 256; i++)
            acc = fmaf(svs[i], W[(size_t)(c0+i)*QKVN + j], acc);
    }
    g_mod[j] = acc;
}

// ---------------- K3: LayerNorm + modulate -------------------------------
__global__ __launch_bounds__(256) void ln_mod(const float* __restrict__ x,
                                              const float* __restrict__ lns,
                                              const float* __restrict__ lnb){
    const int l = blockIdx.x;
    const int tid = threadIdx.x;
    __shared__ float xs[HH];
    __shared__ float rsum[16];
    float s = 0.f, ss = 0.f;
    for (int i = tid; i < HH; i += 256){
        float v = x[(size_t)l*HH + i];
        xs[i] = v; s += v; ss = fmaf(v, v, ss);
    }
    #pragma unroll
    for (int w = 1; w < 32; w <<= 1){
        s  += __shfl_xor_sync(0xffffffffu, s,  w);
        ss += __shfl_xor_sync(0xffffffffu, ss, w);
    }
    int wid = tid >> 5;
    if ((tid & 31) == 0){ rsum[wid] = s; rsum[wid + 8] = ss; }
    __syncthreads();
    s = 0.f; ss = 0.f;
    #pragma unroll
    for (int w = 0; w < 8; w++){ s += rsum[w]; ss += rsum[w + 8]; }
    const float mu   = s  * (1.f/(float)HH);
    const float var  = ss * (1.f/(float)HH) - mu*mu;
    const float rstd = rsqrtf(var + 1e-6f);
    for (int i = tid; i < HH; i += 256){
        float xn = (xs[i] - mu) * rstd * lns[i] + lnb[i];
        float sc = g_mod[HH + i];     // scale
        float sh = g_mod[i];          // shift
        g_xmod[(size_t)l*HH + i] = (1.f + sc) * xn + sh;
    }
}

// ---------------- K4: fp32 GEMM (f32x2 FMA), 128x128x16 tiles ------------
// C[M,N] = A[M,K] @ B[K,N] + bias[N], optional gated residual epilogue:
//   if gate: C = xres + gate * (acc + bias)
__global__ __launch_bounds__(256, 2)
void gemm_kernel(const float* __restrict__ A, const float* __restrict__ B,
                 const float* __restrict__ bias, float* __restrict__ C,
                 int M, int N, int K,
                 const float* __restrict__ xres, const float* __restrict__ gate)
{
    __shared__ __align__(16) float As[16*132];
    __shared__ __align__(16) float Bs[16*132];
    const int tid = threadIdx.x;
    const int wr = tid >> 4;          // 0..15 (row group: 8 rows)
    const int wc = tid & 15;          // 0..15 (col group: cols 2wc+32j)
    const int m0g = blockIdx.y * 128;
    const int n0g = blockIdx.x * 128;

    u64 c2[8][4];
    #pragma unroll
    for (int i = 0; i < 8; i++)
        #pragma unroll
        for (int j = 0; j < 4; j++) c2[i][j] = 0ULL;

    const int mA = tid >> 2;          // 0..63
    const int k4 = tid & 3;           // float4 index along K
    const int kB = tid >> 5;          // 0..7
    const int n4 = tid & 31;          // float4 index along N

    for (int k0 = 0; k0 < K; k0 += 16){
        // A tile (128 x 16), transposed store
        #pragma unroll
        for (int t = 0; t < 2; t++){
            int m = mA + t*64;
            const float4 a4 = *(const float4*)(A + (size_t)(m0g + m)*K + k0 + k4*4);
            As[(k4*4+0)*132 + m] = a4.x;
            As[(k4*4+1)*132 + m] = a4.y;
            As[(k4*4+2)*132 + m] = a4.z;
            As[(k4*4+3)*132 + m] = a4.w;
        }
        // B tile (16 x 128), direct store
        #pragma unroll
        for (int t = 0; t < 2; t++){
            int kk = kB + t*8;
            *(float4*)(Bs + kk*132 + n4*4) =
                *(const float4*)(B + (size_t)(k0+kk)*N + n0g + n4*4);
        }
        __syncthreads();
        #pragma unroll
        for (int kk = 0; kk < 16; kk++){
            float a[8];
            *(float4*)(a)     = *(const float4*)(As + kk*132 + wr*8);
            *(float4*)(a + 4) = *(const float4*)(As + kk*132 + wr*8 + 4);
            u64 b2[4];
            #pragma unroll
            for (int j = 0; j < 4; j++)
                b2[j] = *(const u64*)(Bs + kk*132 + wc*2 + j*32);
            #pragma unroll
            for (int i = 0; i < 8; i++){
                u64 ad = pk2(a[i], a[i]);
                #pragma unroll
                for (int j = 0; j < 4; j++)
                    c2[i][j] = ffma2(ad, b2[j], c2[i][j]);
            }
        }
        __syncthreads();
    }
    #pragma unroll
    for (int i = 0; i < 8; i++){
        int m = m0g + wr*8 + i;
        #pragma unroll
        for (int j = 0; j < 4; j++){
            int n = n0g + wc*2 + j*32;
            float lo, hi; up2(c2[i][j], lo, hi);
            lo += bias[n]; hi += bias[n+1];
            if (gate){
                lo = xres[(size_t)m*N + n]     + gate[n]   * lo;
                hi = xres[(size_t)m*N + n + 1] + gate[n+1] * hi;
            }
            *(float2*)(C + (size_t)m*N + n) = make_float2(lo, hi);
        }
    }
}

// ---------------- K5: qkv split + RMSNorm + RoPE -------------------------
__global__ void qkv_post(const float* __restrict__ pe,
                         const float* __restrict__ qsc,
                         const float* __restrict__ ksc){
    const int l  = blockIdx.x;
    const int nh = blockIdx.y;
    const int d2 = threadIdx.x;                 // 0..63 (pair index)
    const float* hp = g_h + (size_t)l*W1N + nh*DD;
    float qe = hp[2*d2],        qo = hp[2*d2+1];
    float ke = hp[HH + 2*d2],   ko = hp[HH + 2*d2+1];
    float ve = hp[2*HH + 2*d2], vo = hp[2*HH + 2*d2+1];

    float sq = qe*qe + qo*qo;
    float sk = ke*ke + ko*ko;
    #pragma unroll
    for (int w = 1; w < 32; w <<= 1){
        sq += __shfl_xor_sync(0xffffffffu, sq, w);
        sk += __shfl_xor_sync(0xffffffffu, sk, w);
    }
    __shared__ float red[4];
    int wid = d2 >> 5;
    if ((d2 & 31) == 0){ red[wid*2] = sq; red[wid*2+1] = sk; }
    __syncthreads();
    sq = red[0] + red[2];
    sk = red[1] + red[3];
    const float rq = rsqrtf(sq * (1.f/128.f) + 1e-6f);
    const float rk = rsqrtf(sk * (1.f/128.f) + 1e-6f);
    qe *= rq * qsc[2*d2]; qo *= rq * qsc[2*d2+1];
    ke *= rk * ksc[2*d2]; ko *= rk * ksc[2*d2+1];
    // pe layout (l, d2, 2, 2): [cos, -sin, sin, cos]
    const float4 r = *(const float4*)(pe + ((size_t)l*64 + d2)*4);
    float qe2 = r.x*qe + r.y*qo;
    float qo2 = r.z*qe + r.w*qo;
    float ke2 = r.x*ke + r.y*ko;
    float ko2 = r.z*ke + r.w*ko;
    size_t o = ((size_t)nh*LL + l)*DD + 2*d2;
    g_q[o] = qe2; g_q[o+1] = qo2;
    g_k[o] = ke2; g_k[o+1] = ko2;
    g_v[o] = ve;  g_v[o+1] = vo;
}

// ---------------- K6: flash attention (fp32, f32x2) ----------------------
// 64 q-rows per block, 64-row K/V tiles, online softmax.
#define ATT_SMEM ((3*64*130 + 64*65)*4)
__global__ __launch_bounds__(256, 1)
void attn_kernel(){
    extern __shared__ __align__(16) float sm[];
    float* Qs = sm;               // [64][130]
    float* Ks = sm + 64*130;      // [64][130]
    float* Vs = sm + 2*64*130;    // [64][130]
    float* Ss = sm + 3*64*130;    // [64][65]

    const int tid = threadIdx.x;
    const int tr = tid >> 4;      // 0..15 : rows 16i+tr
    const int tc = tid & 15;      // 0..15 : s-cols 16j+tc, o-cols 2tc+32j
    const int nh = blockIdx.y;
    const int q0 = blockIdx.x * 64;
    const float* Qh = g_q + (size_t)nh*LL*DD;
    const float* Kh = g_k + (size_t)nh*LL*DD;
    const float* Vh = g_v + (size_t)nh*LL*DD;

    const float qscale = 0.08838834764831845f;   // 1/sqrt(128)
    for (int idx = tid; idx < 64*64; idx += 256){
        int r = idx >> 6, c = (idx & 63)*2;
        float2 v = *(const float2*)(Qh + (size_t)(q0 + r)*DD + c);
        Qs[r*130 + c]     = v.x * qscale;
        Qs[r*130 + c + 1] = v.y * qscale;
    }

    u64 o2[4][4];
    #pragma unroll
    for (int i = 0; i < 4; i++)
        #pragma unroll
        for (int j = 0; j < 4; j++) o2[i][j] = 0ULL;
    float m_run[4], l_run[4];
    #pragma unroll
    for (int i = 0; i < 4; i++){ m_run[i] = -1e30f; l_run[i] = 0.f; }

    for (int kt = 0; kt < LL/64; kt++){
        __syncthreads();
        const int kbase = kt*64;
        for (int idx = tid; idx < 64*64; idx += 256){
            int r = idx >> 6, c = (idx & 63)*2;
            *(float2*)(Ks + r*130 + c) = *(const float2*)(Kh + (size_t)(kbase + r)*DD + c);
            *(float2*)(Vs + r*130 + c) = *(const float2*)(Vh + (size_t)(kbase + r)*DD + c);
        }
        __syncthreads();

        // S = Q @ K^T (pairs over d)
        u64 s2[4][4];
        #pragma unroll
        for (int i = 0; i < 4; i++)
            #pragma unroll
            for (int j = 0; j < 4; j++) s2[i][j] = 0ULL;
        #pragma unroll 4
        for (int dp = 0; dp < 64; dp++){
            u64 q2[4], k2[4];
            #pragma unroll
            for (int i = 0; i < 4; i++) q2[i] = *(const u64*)(Qs + (16*i+tr)*130 + dp*2);
            #pragma unroll
            for (int j = 0; j < 4; j++) k2[j] = *(const u64*)(Ks + (16*j+tc)*130 + dp*2);
            #pragma unroll
            for (int i = 0; i < 4; i++)
                #pragma unroll
                for (int j = 0; j < 4; j++)
                    s2[i][j] = ffma2(q2[i], k2[j], s2[i][j]);
        }
        // online softmax per row
        #pragma unroll
        for (int i = 0; i < 4; i++){
            float s[4];
            #pragma unroll
            for (int j = 0; j < 4; j++){ float lo, hi; up2(s2[i][j], lo, hi); s[j] = lo + hi; }
            float mx = fmaxf(fmaxf(s[0], s[1]), fmaxf(s[2], s[3]));
            #pragma unroll
            for (int w = 1; w < 16; w <<= 1) mx = fmaxf(mx, __shfl_xor_sync(0xffffffffu, mx, w));
            float mnew  = fmaxf(m_run[i], mx);
            float alpha = __expf(m_run[i] - mnew);
            m_run[i] = mnew;
            float rs = 0.f;
            #pragma unroll
            for (int j = 0; j < 4; j++){ s[j] = __expf(s[j] - mnew); rs += s[j]; }
            #pragma unroll
            for (int w = 1; w < 16; w <<= 1) rs += __shfl_xor_sync(0xffffffffu, rs, w);
            l_run[i] = l_run[i]*alpha + rs;
            u64 a2 = pk2(alpha, alpha);
            #pragma unroll
            for (int j = 0; j < 4; j++) o2[i][j] = fmul2(o2[i][j], a2);
            #pragma unroll
            for (int j = 0; j < 4; j++) Ss[(16*i+tr)*65 + 16*j + tc] = s[j];
        }
        __syncthreads();
        // O += P @ V
        #pragma unroll 2
        for (int kk = 0; kk < 64; kk++){
            u64 v2[4];
            #pragma unroll
            for (int j = 0; j < 4; j++) v2[j] = *(const u64*)(Vs + kk*130 + 2*tc + 32*j);
            #pragma unroll
            for (int i = 0; i < 4; i++){
                float p = Ss[(16*i+tr)*65 + kk];
                u64 p2 = pk2(p, p);
                #pragma unroll
                for (int j = 0; j < 4; j++) o2[i][j] = ffma2(p2, v2[j], o2[i][j]);
            }
        }
    }
    // write normalized O into g_cat[:, nh*128 + d]
    #pragma unroll
    for (int i = 0; i < 4; i++){
        float rl = 1.0f / l_run[i];
        int row = q0 + 16*i + tr;
        #pragma unroll
        for (int j = 0; j < 4; j++){
            float lo, hi; up2(o2[i][j], lo, hi);
            *(float2*)(g_cat + (size_t)row*CATN + nh*DD + 2*tc + 32*j)
                = make_float2(lo*rl, hi*rl);
        }
    }
}

// ---------------- K7: gelu(mlp) -> g_cat[:, H:] --------------------------
__global__ void gelu_k(){
    int idx = blockIdx.x*256 + threadIdx.x;
    if (idx < LL*MLPD){
        int l = idx / MLPD, m = idx - l*MLPD;
        float v = g_h[(size_t)l*W1N + QKVN + m];
        float c = 0.7978845608028654f * (v + 0.044715f*v*v*v);
        g_cat[(size_t)l*CATN + HH + m] = 0.5f*v*(1.f + tanhf(c));
    }
}

// ---------------- launch --------------------------------------------------
extern "C" void kernel_launch(void* const* d_in, const int* in_sizes, int n_in,
                              void* d_out, int out_size){
    (void)in_sizes; (void)n_in; (void)out_size;
    const float* x       = (const float*)d_in[0];
    const float* vec     = (const float*)d_in[1];
    const float* pe      = (const float*)d_in[2];
    const float* mod_w   = (const float*)d_in[3];
    const float* mod_b   = (const float*)d_in[4];
    const float* ln_s    = (const float*)d_in[5];
    const float* ln_b    = (const float*)d_in[6];
    const float* w1      = (const float*)d_in[7];
    const float* b1      = (const float*)d_in[8];
    const float* q_scale = (const float*)d_in[9];
    const float* k_scale = (const float*)d_in[10];
    const float* w2      = (const float*)d_in[11];
    const float* b2      = (const float*)d_in[12];
    float* out = (float*)d_out;

    float *p_xmod, *p_h, *p_cat, *p_mod;
    cudaGetSymbolAddress((void**)&p_xmod, g_xmod);
    cudaGetSymbolAddress((void**)&p_h,    g_h);
    cudaGetSymbolAddress((void**)&p_cat,  g_cat);
    cudaGetSymbolAddress((void**)&p_mod,  g_mod);

    cudaFuncSetAttribute(attn_kernel, cudaFuncAttributeMaxDynamicSharedMemorySize, ATT_SMEM);

    silu_k  <<<(HH+255)/256, 256>>>(vec);
    mod_gemv<<<QKVN/256, 256>>>(mod_w, mod_b);
    ln_mod  <<<LL, 256>>>(x, ln_s, ln_b);
    gemm_kernel<<<dim3(W1N/128, LL/128), 256>>>(p_xmod, w1, b1, p_h,
                                                LL, W1N, HH, nullptr, nullptr);
    qkv_post<<<dim3(LL, NHH), 64>>>(pe, q_scale, k_scale);
    attn_kernel<<<dim3(LL/64, NHH), 256, ATT_SMEM>>>();
    gelu_k  <<<(LL*MLPD + 255)/256, 256>>>();
    gemm_kernel<<<dim3(HH/128, LL/128), 256>>>(p_cat, w2, b2, out,
                                               LL, HH, CATN, x, p_mod + 2*HH);
}

// round 2
// speedup vs baseline: 1.0003x; 1.0003x over previous
#include <cuda_runtime.h>
#include <cuda_bf16.h>
#include <cstdint>

#define LL   2048
#define HH   3072
#define NHH  24
#define DD   128
#define MLPD 12288
#define W1N  21504   // 3H + MLP
#define CATN 15360   // H + MLP
#define QKVN 9216    // 3H

typedef unsigned long long u64;

// ---------------- f32x2 packed helpers (sm_100+/sm_103a) ----------------
__device__ __forceinline__ u64 pk2(float lo, float hi){
    u64 r; asm("mov.b64 %0, {%1,%2};" : "=l"(r) : "f"(lo), "f"(hi)); return r;
}
__device__ __forceinline__ void up2(u64 p, float& lo, float& hi){
    asm("mov.b64 {%0,%1}, %2;" : "=f"(lo), "=f"(hi) : "l"(p));
}
__device__ __forceinline__ u64 ffma2(u64 a, u64 b, u64 c){
    u64 d; asm("fma.rn.f32x2 %0, %1, %2, %3;" : "=l"(d) : "l"(a), "l"(b), "l"(c)); return d;
}
__device__ __forceinline__ u64 fmul2(u64 a, u64 b){
    u64 d; asm("mul.rn.f32x2 %0, %1, %2;" : "=l"(d) : "l"(a), "l"(b)); return d;
}

// ---------------- scratch (device globals: no allocation allowed) --------
__device__ float g_sv[HH];
__device__ float g_mod[3*HH];
__device__ float g_xmod[(size_t)LL*HH];
__device__ float g_h[(size_t)LL*W1N];      // GEMM1 output (qkv | mlp)
__device__ float g_q[(size_t)NHH*LL*DD];
__device__ float g_k[(size_t)NHH*LL*DD];
__device__ float g_v[(size_t)NHH*LL*DD];
__device__ float g_cat[(size_t)LL*CATN];   // [attn_out | gelu(mlp)]

// ---------------- K1: silu(vec) ----------------
__global__ void silu_k(const float* __restrict__ vec){
    int i = blockIdx.x*256 + threadIdx.x;
    if (i < HH){
        float t = vec[i];
        g_sv[i] = t / (1.f + expf(-t));
    }
}

// ---------------- K2: mod = silu(vec) @ mod_w + mod_b (GEMV) -------------
__global__ __launch_bounds__(256) void mod_gemv(const float* __restrict__ W,
                                                const float* __restrict__ b){
    const int j = blockIdx.x*256 + threadIdx.x;   // 0..9215
    __shared__ float svs[256];
    float acc = b[j];
    for (int c0 = 0; c0 < HH; c0 += 256){
        __syncthreads();
        svs[threadIdx.x] = g_sv[c0 + threadIdx.x];
        __syncthreads();
        #pragma unroll 8
        for (int i = 0; i < 256; i++)
            acc = fmaf(svs[i], W[(size_t)(c0+i)*QKVN + j], acc);
    }
    g_mod[j] = acc;
}

// ---------------- K3: LayerNorm + modulate -------------------------------
__global__ __launch_bounds__(256) void ln_mod(const float* __restrict__ x,
                                              const float* __restrict__ lns,
                                              const float* __restrict__ lnb){
    const int l = blockIdx.x;
    const int tid = threadIdx.x;
    __shared__ float xs[HH];
    __shared__ float rsum[16];
    float s = 0.f, ss = 0.f;
    for (int i = tid; i < HH; i += 256){
        float v = x[(size_t)l*HH + i];
        xs[i] = v; s += v; ss = fmaf(v, v, ss);
    }
    #pragma unroll
    for (int w = 1; w < 32; w <<= 1){
        s  += __shfl_xor_sync(0xffffffffu, s,  w);
        ss += __shfl_xor_sync(0xffffffffu, ss, w);
    }
    int wid = tid >> 5;
    if ((tid & 31) == 0){ rsum[wid] = s; rsum[wid + 8] = ss; }
    __syncthreads();
    s = 0.f; ss = 0.f;
    #pragma unroll
    for (int w = 0; w < 8; w++){ s += rsum[w]; ss += rsum[w + 8]; }
    const float mu   = s  * (1.f/(float)HH);
    const float var  = ss * (1.f/(float)HH) - mu*mu;
    const float rstd = rsqrtf(var + 1e-6f);
    for (int i = tid; i < HH; i += 256){
        float xn = (xs[i] - mu) * rstd * lns[i] + lnb[i];
        float sc = g_mod[HH + i];     // scale
        float sh = g_mod[i];          // shift
        g_xmod[(size_t)l*HH + i] = (1.f + sc) * xn + sh;
    }
}

// ---------------- K4: fp32 GEMM (f32x2 FMA), 128x128x16 tiles ------------
// C[M,N] = A[M,K] @ B[K,N] + bias[N], optional gated residual epilogue:
//   if gate: C = xres + gate * (acc + bias)
__global__ __launch_bounds__(256, 2)
void gemm_kernel(const float* __restrict__ A, const float* __restrict__ B,
                 const float* __restrict__ bias, float* __restrict__ C,
                 int M, int N, int K,
                 const float* __restrict__ xres, const float* __restrict__ gate)
{
    __shared__ __align__(16) float As[16*132];
    __shared__ __align__(16) float Bs[16*132];
    const int tid = threadIdx.x;
    const int wr = tid >> 4;          // 0..15 (row group: 8 rows)
    const int wc = tid & 15;          // 0..15 (col group: cols 2wc+32j)
    const int m0g = blockIdx.y * 128;
    const int n0g = blockIdx.x * 128;

    u64 c2[8][4];
    #pragma unroll
    for (int i = 0; i < 8; i++)
        #pragma unroll
        for (int j = 0; j < 4; j++) c2[i][j] = 0ULL;

    const int mA = tid >> 2;          // 0..63
    const int k4 = tid & 3;           // float4 index along K
    const int kB = tid >> 5;          // 0..7
    const int n4 = tid & 31;          // float4 index along N

    for (int k0 = 0; k0 < K; k0 += 16){
        // A tile (128 x 16), transposed store
        #pragma unroll
        for (int t = 0; t < 2; t++){
            int m = mA + t*64;
            const float4 a4 = *(const float4*)(A + (size_t)(m0g + m)*K + k0 + k4*4);
            As[(k4*4+0)*132 + m] = a4.x;
            As[(k4*4+1)*132 + m] = a4.y;
            As[(k4*4+2)*132 + m] = a4.z;
            As[(k4*4+3)*132 + m] = a4.w;
        }
        // B tile (16 x 128), direct store
        #pragma unroll
        for (int t = 0; t < 2; t++){
            int kk = kB + t*8;
            *(float4*)(Bs + kk*132 + n4*4) =
                *(const float4*)(B + (size_t)(k0+kk)*N + n0g + n4*4);
        }
        __syncthreads();
        #pragma unroll
        for (int kk = 0; kk < 16; kk++){
            float a[8];
            *(float4*)(a)     = *(const float4*)(As + kk*132 + wr*8);
            *(float4*)(a + 4) = *(const float4*)(As + kk*132 + wr*8 + 4);
            u64 b2[4];
            #pragma unroll
            for (int j = 0; j < 4; j++)
                b2[j] = *(const u64*)(Bs + kk*132 + wc*2 + j*32);
            #pragma unroll
            for (int i = 0; i < 8; i++){
                u64 ad = pk2(a[i], a[i]);
                #pragma unroll
                for (int j = 0; j < 4; j++)
                    c2[i][j] = ffma2(ad, b2[j], c2[i][j]);
            }
        }
        __syncthreads();
    }
    #pragma unroll
    for (int i = 0; i < 8; i++){
        int m = m0g + wr*8 + i;
        #pragma unroll
        for (int j = 0; j < 4; j++){
            int n = n0g + wc*2 + j*32;
            float lo, hi; up2(c2[i][j], lo, hi);
            lo += bias[n]; hi += bias[n+1];
            if (gate){
                lo = xres[(size_t)m*N + n]     + gate[n]   * lo;
                hi = xres[(size_t)m*N + n + 1] + gate[n+1] * hi;
            }
            *(float2*)(C + (size_t)m*N + n) = make_float2(lo, hi);
        }
    }
}

// ---------------- K5: qkv split + RMSNorm + RoPE -------------------------
__global__ void qkv_post(const float* __restrict__ pe,
                         const float* __restrict__ qsc,
                         const float* __restrict__ ksc){
    const int l  = blockIdx.x;
    const int nh = blockIdx.y;
    const int d2 = threadIdx.x;                 // 0..63 (pair index)
    const float* hp = g_h + (size_t)l*W1N + nh*DD;
    float qe = hp[2*d2],        qo = hp[2*d2+1];
    float ke = hp[HH + 2*d2],   ko = hp[HH + 2*d2+1];
    float ve = hp[2*HH + 2*d2], vo = hp[2*HH + 2*d2+1];

    float sq = qe*qe + qo*qo;
    float sk = ke*ke + ko*ko;
    #pragma unroll
    for (int w = 1; w < 32; w <<= 1){
        sq += __shfl_xor_sync(0xffffffffu, sq, w);
        sk += __shfl_xor_sync(0xffffffffu, sk, w);
    }
    __shared__ float red[4];
    int wid = d2 >> 5;
    if ((d2 & 31) == 0){ red[wid*2] = sq; red[wid*2+1] = sk; }
    __syncthreads();
    sq = red[0] + red[2];
    sk = red[1] + red[3];
    const float rq = rsqrtf(sq * (1.f/128.f) + 1e-6f);
    const float rk = rsqrtf(sk * (1.f/128.f) + 1e-6f);
    qe *= rq * qsc[2*d2]; qo *= rq * qsc[2*d2+1];
    ke *= rk * ksc[2*d2]; ko *= rk * ksc[2*d2+1];
    // pe layout (l, d2, 2, 2): [cos, -sin, sin, cos]
    const float4 r = *(const float4*)(pe + ((size_t)l*64 + d2)*4);
    float qe2 = r.x*qe + r.y*qo;
    float qo2 = r.z*qe + r.w*qo;
    float ke2 = r.x*ke + r.y*ko;
    float ko2 = r.z*ke + r.w*ko;
    size_t o = ((size_t)nh*LL + l)*DD + 2*d2;
    g_q[o] = qe2; g_q[o+1] = qo2;
    g_k[o] = ke2; g_k[o+1] = ko2;
    g_v[o] = ve;  g_v[o+1] = vo;
}

// ---------------- K6: flash attention (fp32, f32x2) ----------------------
// 64 q-rows per block, 64-row K/V tiles, online softmax.
#define ATT_SMEM ((3*64*130 + 64*65)*4)
__global__ __launch_bounds__(256, 1)
void attn_kernel(){
    extern __shared__ __align__(16) float sm[];
    float* Qs = sm;               // [64][130]
    float* Ks = sm + 64*130;      // [64][130]
    float* Vs = sm + 2*64*130;    // [64][130]
    float* Ss = sm + 3*64*130;    // [64][65]

    const int tid = threadIdx.x;
    const int tr = tid >> 4;      // 0..15 : rows 16i+tr
    const int tc = tid & 15;      // 0..15 : s-cols 16j+tc, o-cols 2tc+32j
    const int nh = blockIdx.y;
    const int q0 = blockIdx.x * 64;
    const float* Qh = g_q + (size_t)nh*LL*DD;
    const float* Kh = g_k + (size_t)nh*LL*DD;
    const float* Vh = g_v + (size_t)nh*LL*DD;

    const float qscale = 0.08838834764831845f;   // 1/sqrt(128)
    for (int idx = tid; idx < 64*64; idx += 256){
        int r = idx >> 6, c = (idx & 63)*2;
        float2 v = *(const float2*)(Qh + (size_t)(q0 + r)*DD + c);
        Qs[r*130 + c]     = v.x * qscale;
        Qs[r*130 + c + 1] = v.y * qscale;
    }

    u64 o2[4][4];
    #pragma unroll
    for (int i = 0; i < 4; i++)
        #pragma unroll
        for (int j = 0; j < 4; j++) o2[i][j] = 0ULL;
    float m_run[4], l_run[4];
    #pragma unroll
    for (int i = 0; i < 4; i++){ m_run[i] = -1e30f; l_run[i] = 0.f; }

    for (int kt = 0; kt < LL/64; kt++){
        __syncthreads();
        const int kbase = kt*64;
        for (int idx = tid; idx < 64*64; idx += 256){
            int r = idx >> 6, c = (idx & 63)*2;
            *(float2*)(Ks + r*130 + c) = *(const float2*)(Kh + (size_t)(kbase + r)*DD + c);
            *(float2*)(Vs + r*130 + c) = *(const float2*)(Vh + (size_t)(kbase + r)*DD + c);
        }
        __syncthreads();

        // S = Q @ K^T (pairs over d)
        u64 s2[4][4];
        #pragma unroll
        for (int i = 0; i < 4; i++)
            #pragma unroll
            for (int j = 0; j < 4; j++) s2[i][j] = 0ULL;
        #pragma unroll 4
        for (int dp = 0; dp < 64; dp++){
            u64 q2[4], k2[4];
            #pragma unroll
            for (int i = 0; i < 4; i++) q2[i] = *(const u64*)(Qs + (16*i+tr)*130 + dp*2);
            #pragma unroll
            for (int j = 0; j < 4; j++) k2[j] = *(const u64*)(Ks + (16*j+tc)*130 + dp*2);
            #pragma unroll
            for (int i = 0; i < 4; i++)
                #pragma unroll
                for (int j = 0; j < 4; j++)
                    s2[i][j] = ffma2(q2[i], k2[j], s2[i][j]);
        }
        // online softmax per row
        #pragma unroll
        for (int i = 0; i < 4; i++){
            float s[4];
            #pragma unroll
            for (int j = 0; j < 4; j++){ float lo, hi; up2(s2[i][j], lo, hi); s[j] = lo + hi; }
            float mx = fmaxf(fmaxf(s[0], s[1]), fmaxf(s[2], s[3]));
            #pragma unroll
            for (int w = 1; w < 16; w <<= 1) mx = fmaxf(mx, __shfl_xor_sync(0xffffffffu, mx, w));
            float mnew  = fmaxf(m_run[i], mx);
            float alpha = __expf(m_run[i] - mnew);
            m_run[i] = mnew;
            float rs = 0.f;
            #pragma unroll
            for (int j = 0; j < 4; j++){ s[j] = __expf(s[j] - mnew); rs += s[j]; }
            #pragma unroll
            for (int w = 1; w < 16; w <<= 1) rs += __shfl_xor_sync(0xffffffffu, rs, w);
            l_run[i] = l_run[i]*alpha + rs;
            u64 a2 = pk2(alpha, alpha);
            #pragma unroll
            for (int j = 0; j < 4; j++) o2[i][j] = fmul2(o2[i][j], a2);
            #pragma unroll
            for (int j = 0; j < 4; j++) Ss[(16*i+tr)*65 + 16*j + tc] = s[j];
        }
        __syncthreads();
        // O += P @ V
        #pragma unroll 2
        for (int kk = 0; kk < 64; kk++){
            u64 v2[4];
            #pragma unroll
            for (int j = 0; j < 4; j++) v2[j] = *(const u64*)(Vs + kk*130 + 2*tc + 32*j);
            #pragma unroll
            for (int i = 0; i < 4; i++){
                float p = Ss[(16*i+tr)*65 + kk];
                u64 p2 = pk2(p, p);
                #pragma unroll
                for (int j = 0; j < 4; j++) o2[i][j] = ffma2(p2, v2[j], o2[i][j]);
            }
        }
    }
    // write normalized O into g_cat[:, nh*128 + d]
    #pragma unroll
    for (int i = 0; i < 4; i++){
        float rl = 1.0f / l_run[i];
        int row = q0 + 16*i + tr;
        #pragma unroll
        for (int j = 0; j < 4; j++){
            float lo, hi; up2(o2[i][j], lo, hi);
            *(float2*)(g_cat + (size_t)row*CATN + nh*DD + 2*tc + 32*j)
                = make_float2(lo*rl, hi*rl);
        }
    }
}

// ---------------- K7: gelu(mlp) -> g_cat[:, H:] --------------------------
__global__ void gelu_k(){
    int idx = blockIdx.x*256 + threadIdx.x;
    if (idx < LL*MLPD){
        int l = idx / MLPD, m = idx - l*MLPD;
        float v = g_h[(size_t)l*W1N + QKVN + m];
        float c = 0.7978845608028654f * (v + 0.044715f*v*v*v);
        g_cat[(size_t)l*CATN + HH + m] = 0.5f*v*(1.f + tanhf(c));
    }
}

// ---------------- launch --------------------------------------------------
extern "C" void kernel_launch(void* const* d_in, const int* in_sizes, int n_in,
                              void* d_out, int out_size){
    (void)in_sizes; (void)n_in; (void)out_size;
    const float* x       = (const float*)d_in[0];
    const float* vec     = (const float*)d_in[1];
    const float* pe      = (const float*)d_in[2];
    const float* mod_w   = (const float*)d_in[3];
    const float* mod_b   = (const float*)d_in[4];
    const float* ln_s    = (const float*)d_in[5];
    const float* ln_b    = (const float*)d_in[6];
    const float* w1      = (const float*)d_in[7];
    const float* b1      = (const float*)d_in[8];
    const float* q_scale = (const float*)d_in[9];
    const float* k_scale = (const float*)d_in[10];
    const float* w2      = (const float*)d_in[11];
    const float* b2      = (const float*)d_in[12];
    float* out = (float*)d_out;

    float *p_xmod, *p_h, *p_cat, *p_mod;
    cudaGetSymbolAddress((void**)&p_xmod, g_xmod);
    cudaGetSymbolAddress((void**)&p_h,    g_h);
    cudaGetSymbolAddress((void**)&p_cat,  g_cat);
    cudaGetSymbolAddress((void**)&p_mod,  g_mod);

    cudaFuncSetAttribute(attn_kernel, cudaFuncAttributeMaxDynamicSharedMemorySize, ATT_SMEM);

    silu_k  <<<(HH+255)/256, 256>>>(vec);
    mod_gemv<<<QKVN/256, 256>>>(mod_w, mod_b);
    ln_mod  <<<LL, 256>>>(x, ln_s, ln_b);
    gemm_kernel<<<dim3(W1N/128, LL/128), 256>>>(p_xmod, w1, b1, p_h,
                                                LL, W1N, HH, nullptr, nullptr);
    qkv_post<<<dim3(LL, NHH), 64>>>(pe, q_scale, k_scale);
    attn_kernel<<<dim3(LL/64, NHH), 256, ATT_SMEM>>>();
    gelu_k  <<<(LL*MLPD + 255)/256, 256>>>();
    gemm_kernel<<<dim3(HH/128, LL/128), 256>>>(p_cat, w2, b2, out,
                                               LL, HH, CATN, x, p_mod + 2*HH);
}

// round 4
// speedup vs baseline: 1.7878x; 1.7872x over previous
#include <cuda_runtime.h>
#include <cuda_bf16.h>
#include <cstdint>

#define LL   2048
#define HH   3072
#define NHH  24
#define DD   128
#define MLPD 12288
#define W1N  21504
#define CATN 15360
#define QKVN 9216

typedef unsigned long long u64;

__device__ __forceinline__ u64 pk2(float lo, float hi){
    u64 r; asm("mov.b64 %0, {%1,%2};" : "=l"(r) : "f"(lo), "f"(hi)); return r;
}
__device__ __forceinline__ void up2(u64 p, float& lo, float& hi){
    asm("mov.b64 {%0,%1}, %2;" : "=f"(lo), "=f"(hi) : "l"(p));
}
__device__ __forceinline__ u64 ffma2(u64 a, u64 b, u64 c){
    u64 d; asm("fma.rn.f32x2 %0, %1, %2, %3;" : "=l"(d) : "l"(a), "l"(b), "l"(c)); return d;
}
__device__ __forceinline__ u64 fmul2(u64 a, u64 b){
    u64 d; asm("mul.rn.f32x2 %0, %1, %2;" : "=l"(d) : "l"(a), "l"(b)); return d;
}
__device__ __forceinline__ float to_tf32(float x){
    float r; asm("cvt.rna.tf32.f32 %0, %1;" : "=f"(r) : "f"(x)); return r;
}
__device__ __forceinline__ uint32_t smem_u32(const void* p){
    uint32_t a; asm("{ .reg .u64 t; cvta.to.shared.u64 t, %1; cvt.u32.u64 %0, t; }" : "=r"(a) : "l"(p));
    return a;
}

// tf32 m16n8k8 warp MMA (sm_80+ family ISA; compiles for sm_103)
__device__ __forceinline__ void mma_t32(float* c, const uint32_t* a, const uint32_t* b){
    asm volatile("mma.sync.aligned.m16n8k8.row.col.f32.tf32.tf32.f32 "
        "{%0,%1,%2,%3}, {%4,%5,%6,%7}, {%8,%9}, {%0,%1,%2,%3};"
        : "+f"(c[0]), "+f"(c[1]), "+f"(c[2]), "+f"(c[3])
        : "r"(a[0]), "r"(a[1]), "r"(a[2]), "r"(a[3]), "r"(b[0]), "r"(b[1]));
}

// ---------------- scratch ----------------
__device__ float g_sv[HH];
__device__ float g_mod[3*HH];
__device__ float g_xmod[(size_t)LL*HH];
__device__ float g_h[(size_t)LL*W1N];
__device__ float g_q[(size_t)NHH*LL*DD];
__device__ float g_k[(size_t)NHH*LL*DD];
__device__ float g_v[(size_t)NHH*LL*DD];
__device__ float g_cat[(size_t)LL*CATN];
__device__ float g_w1t[(size_t)W1N*HH];
__device__ float g_w2t[(size_t)HH*CATN];

// ---------------- transpose + tf32 round: out[C][R] = rna(in[R][C]) ------
__global__ void transpose_tf32(const float* __restrict__ in, float* __restrict__ out,
                               int R, int C){
    __shared__ float t[32][33];
    const int bx = blockIdx.x * 32;   // C
    const int by = blockIdx.y * 32;   // R
    const int tx = threadIdx.x, ty = threadIdx.y;
    #pragma unroll
    for (int i = 0; i < 32; i += 8)
        t[ty+i][tx] = in[(size_t)(by+ty+i)*C + bx+tx];
    __syncthreads();
    #pragma unroll
    for (int i = 0; i < 32; i += 8)
        out[(size_t)(bx+ty+i)*R + by+tx] = to_tf32(t[tx][ty+i]);
}

// ---------------- silu ----------------
__global__ void silu_k(const float* __restrict__ vec){
    int i = blockIdx.x*256 + threadIdx.x;
    if (i < HH){
        float t = vec[i];
        g_sv[i] = t / (1.f + expf(-t));
    }
}

// ---------------- mod GEMV ----------------
__global__ __launch_bounds__(256) void mod_gemv(const float* __restrict__ W,
                                                const float* __restrict__ b){
    const int j = blockIdx.x*256 + threadIdx.x;
    __shared__ float svs[256];
    float acc = b[j];
    for (int c0 = 0; c0 < HH; c0 += 256){
        __syncthreads();
        svs[threadIdx.x] = g_sv[c0 + threadIdx.x];
        __syncthreads();
        #pragma unroll 8
        for (int i = 0; i < 256; i++)
            acc = fmaf(svs[i], W[(size_t)(c0+i)*QKVN + j], acc);
    }
    g_mod[j] = acc;
}

// ---------------- LayerNorm + modulate (tf32-rounded output) --------------
__global__ __launch_bounds__(256) void ln_mod(const float* __restrict__ x,
                                              const float* __restrict__ lns,
                                              const float* __restrict__ lnb){
    const int l = blockIdx.x;
    const int tid = threadIdx.x;
    __shared__ float xs[HH];
    __shared__ float rsum[16];
    float s = 0.f, ss = 0.f;
    for (int i = tid; i < HH; i += 256){
        float v = x[(size_t)l*HH + i];
        xs[i] = v; s += v; ss = fmaf(v, v, ss);
    }
    #pragma unroll
    for (int w = 1; w < 32; w <<= 1){
        s  += __shfl_xor_sync(0xffffffffu, s,  w);
        ss += __shfl_xor_sync(0xffffffffu, ss, w);
    }
    int wid = tid >> 5;
    if ((tid & 31) == 0){ rsum[wid] = s; rsum[wid + 8] = ss; }
    __syncthreads();
    s = 0.f; ss = 0.f;
    #pragma unroll
    for (int w = 0; w < 8; w++){ s += rsum[w]; ss += rsum[w + 8]; }
    const float mu   = s  * (1.f/(float)HH);
    const float var  = ss * (1.f/(float)HH) - mu*mu;
    const float rstd = rsqrtf(var + 1e-6f);
    for (int i = tid; i < HH; i += 256){
        float xn = (xs[i] - mu) * rstd * lns[i] + lnb[i];
        g_xmod[(size_t)l*HH + i] = to_tf32((1.f + g_mod[HH+i]) * xn + g_mod[i]);
    }
}

// ---------------- tf32 mma.sync GEMM --------------------------------------
// C[M,N] = A[M,K] @ Bt[N,K]^T + bias ; optional: C = xres + gate*(acc+bias)
// CTA tile 256x128, warp tile 64x64 (8 warps = 4m x 2n), K-chunk 16.
// smem per stage: 384 rows x 20 floats (A rows 0..255, B rows 256..383).
#define MG_STRIDE 20
#define MG_STAGE  (384*MG_STRIDE)          // floats
#define MG_SMEM   (2*MG_STAGE*4)           // bytes = 61440

__global__ __launch_bounds__(256, 1)
void mma_gemm(const float* __restrict__ A, const float* __restrict__ Bt,
              const float* __restrict__ bias, float* __restrict__ C,
              int N, int K, int NIT,
              const float* __restrict__ xres, const float* __restrict__ gate)
{
    extern __shared__ float smd[];
    const uint32_t smb = smem_u32(smd);
    const int tid  = threadIdx.x;
    const int wid  = tid >> 5;
    const int lane = tid & 31;
    const int g    = lane >> 2;        // group 0..7
    const int tig  = lane & 3;         // thread-in-group
    const int m0 = blockIdx.x * 256;
    const int n0 = blockIdx.y * 128;
    const int m0w = (wid & 3) * 64;    // warp m offset in tile
    const int n0w = (wid >> 2) * 64;   // warp n offset in tile

    // ---- loader setup: 1536 cp.async(16B) per chunk, 6 per thread ----
    const float* gp[6];
    uint32_t sof[6];
    #pragma unroll
    for (int i = 0; i < 6; i++){
        int idx = i*256 + tid;
        int row = idx >> 2;            // 0..383
        int seg = idx & 3;             // 16B segment within 64B row-chunk
        if (row < 256) gp[i] = A  + (size_t)(m0 + row)*K + seg*4;
        else           gp[i] = Bt + (size_t)(n0 + row - 256)*K + seg*4;
        sof[i] = (uint32_t)((row*MG_STRIDE + seg*4) * 4);
    }

#define MG_LOAD(IT, ST) do { \
        const uint32_t _sb = smb + (uint32_t)(ST)*(MG_STAGE*4); \
        _Pragma("unroll") \
        for (int _i = 0; _i < 6; _i++){ \
            asm volatile("cp.async.cg.shared.global [%0], [%1], 16;" \
                :: "r"(_sb + sof[_i]), "l"(gp[_i] + (size_t)(IT)*16) : "memory"); \
        } \
        asm volatile("cp.async.commit_group;" ::: "memory"); \
    } while(0)

    float c[4][8][4];
    #pragma unroll
    for (int mt = 0; mt < 4; mt++)
        #pragma unroll
        for (int nt = 0; nt < 8; nt++)
            #pragma unroll
            for (int q = 0; q < 4; q++) c[mt][nt][q] = 0.f;

    MG_LOAD(0, 0);

    for (int it = 0; it < NIT; ++it){
        const int st = it & 1;
        if (it + 1 < NIT){
            MG_LOAD(it + 1, st ^ 1);
            asm volatile("cp.async.wait_group 1;" ::: "memory");
        } else {
            asm volatile("cp.async.wait_group 0;" ::: "memory");
        }
        __syncthreads();

        const uint32_t* As = (const uint32_t*)(smd + st*MG_STAGE);
        const uint32_t* Bs = As + 256*MG_STRIDE;

        #pragma unroll
        for (int k8 = 0; k8 < 16; k8 += 8){
            uint32_t a[4][4];
            #pragma unroll
            for (int mt = 0; mt < 4; mt++){
                const uint32_t* ap = As + (m0w + mt*16 + g)*MG_STRIDE + k8 + tig;
                a[mt][0] = ap[0];
                a[mt][1] = ap[8*MG_STRIDE];
                a[mt][2] = ap[4];
                a[mt][3] = ap[8*MG_STRIDE + 4];
            }
            uint32_t b[8][2];
            #pragma unroll
            for (int nt = 0; nt < 8; nt++){
                const uint32_t* bp = Bs + (n0w + nt*8 + g)*MG_STRIDE + k8 + tig;
                b[nt][0] = bp[0];
                b[nt][1] = bp[4];
            }
            #pragma unroll
            for (int mt = 0; mt < 4; mt++)
                #pragma unroll
                for (int nt = 0; nt < 8; nt++)
                    mma_t32(c[mt][nt], a[mt], b[nt]);
        }
        __syncthreads();
    }

    // ---- epilogue ----
    #pragma unroll
    for (int mt = 0; mt < 4; mt++){
        const int m = m0 + m0w + mt*16 + g;
        #pragma unroll
        for (int nt = 0; nt < 8; nt++){
            const int n = n0 + n0w + nt*8 + 2*tig;
            const float b0 = __ldg(bias + n), b1 = __ldg(bias + n + 1);
            float v0 = c[mt][nt][0] + b0, v1 = c[mt][nt][1] + b1;
            float v2 = c[mt][nt][2] + b0, v3 = c[mt][nt][3] + b1;
            if (gate){
                const float g0 = __ldg(gate + n), g1 = __ldg(gate + n + 1);
                v0 = xres[(size_t)m*N + n]       + g0*v0;
                v1 = xres[(size_t)m*N + n + 1]   + g1*v1;
                v2 = xres[(size_t)(m+8)*N + n]   + g0*v2;
                v3 = xres[(size_t)(m+8)*N + n+1] + g1*v3;
            }
            *(float2*)(C + (size_t)m*N + n)     = make_float2(v0, v1);
            *(float2*)(C + (size_t)(m+8)*N + n) = make_float2(v2, v3);
        }
    }
}

// ---------------- qkv split + RMSNorm + RoPE -------------------------
__global__ void qkv_post(const float* __restrict__ pe,
                         const float* __restrict__ qsc,
                         const float* __restrict__ ksc){
    const int l  = blockIdx.x;
    const int nh = blockIdx.y;
    const int d2 = threadIdx.x;
    const float* hp = g_h + (size_t)l*W1N + nh*DD;
    float qe = hp[2*d2],        qo = hp[2*d2+1];
    float ke = hp[HH + 2*d2],   ko = hp[HH + 2*d2+1];
    float ve = hp[2*HH + 2*d2], vo = hp[2*HH + 2*d2+1];

    float sq = qe*qe + qo*qo;
    float sk = ke*ke + ko*ko;
    #pragma unroll
    for (int w = 1; w < 32; w <<= 1){
        sq += __shfl_xor_sync(0xffffffffu, sq, w);
        sk += __shfl_xor_sync(0xffffffffu, sk, w);
    }
    __shared__ float red[4];
    int wid = d2 >> 5;
    if ((d2 & 31) == 0){ red[wid*2] = sq; red[wid*2+1] = sk; }
    __syncthreads();
    sq = red[0] + red[2];
    sk = red[1] + red[3];
    const float rq = rsqrtf(sq * (1.f/128.f) + 1e-6f);
    const float rk = rsqrtf(sk * (1.f/128.f) + 1e-6f);
    qe *= rq * qsc[2*d2]; qo *= rq * qsc[2*d2+1];
    ke *= rk * ksc[2*d2]; ko *= rk * ksc[2*d2+1];
    const float4 r = *(const float4*)(pe + ((size_t)l*64 + d2)*4);
    float qe2 = r.x*qe + r.y*qo;
    float qo2 = r.z*qe + r.w*qo;
    float ke2 = r.x*ke + r.y*ko;
    float ko2 = r.z*ke + r.w*ko;
    size_t o = ((size_t)nh*LL + l)*DD + 2*d2;
    g_q[o] = qe2; g_q[o+1] = qo2;
    g_k[o] = ke2; g_k[o+1] = ko2;
    g_v[o] = ve;  g_v[o+1] = vo;
}

// ---------------- flash attention (fp32, f32x2) ----------------------
#define ATT_SMEM ((3*64*130 + 64*65)*4)
__global__ __launch_bounds__(256, 1)
void attn_kernel(){
    extern __shared__ __align__(16) float sm[];
    float* Qs = sm;
    float* Ks = sm + 64*130;
    float* Vs = sm + 2*64*130;
    float* Ss = sm + 3*64*130;

    const int tid = threadIdx.x;
    const int tr = tid >> 4;
    const int tc = tid & 15;
    const int nh = blockIdx.y;
    const int q0 = blockIdx.x * 64;
    const float* Qh = g_q + (size_t)nh*LL*DD;
    const float* Kh = g_k + (size_t)nh*LL*DD;
    const float* Vh = g_v + (size_t)nh*LL*DD;

    const float qscale = 0.08838834764831845f;
    for (int idx = tid; idx < 64*64; idx += 256){
        int r = idx >> 6, c = (idx & 63)*2;
        float2 v = *(const float2*)(Qh + (size_t)(q0 + r)*DD + c);
        Qs[r*130 + c]     = v.x * qscale;
        Qs[r*130 + c + 1] = v.y * qscale;
    }

    u64 o2[4][4];
    #pragma unroll
    for (int i = 0; i < 4; i++)
        #pragma unroll
        for (int j = 0; j < 4; j++) o2[i][j] = 0ULL;
    float m_run[4], l_run[4];
    #pragma unroll
    for (int i = 0; i < 4; i++){ m_run[i] = -1e30f; l_run[i] = 0.f; }

    for (int kt = 0; kt < LL/64; kt++){
        __syncthreads();
        const int kbase = kt*64;
        for (int idx = tid; idx < 64*64; idx += 256){
            int r = idx >> 6, c = (idx & 63)*2;
            *(float2*)(Ks + r*130 + c) = *(const float2*)(Kh + (size_t)(kbase + r)*DD + c);
            *(float2*)(Vs + r*130 + c) = *(const float2*)(Vh + (size_t)(kbase + r)*DD + c);
        }
        __syncthreads();

        u64 s2[4][4];
        #pragma unroll
        for (int i = 0; i < 4; i++)
            #pragma unroll
            for (int j = 0; j < 4; j++) s2[i][j] = 0ULL;
        #pragma unroll 4
        for (int dp = 0; dp < 64; dp++){
            u64 q2[4], k2[4];
            #pragma unroll
            for (int i = 0; i < 4; i++) q2[i] = *(const u64*)(Qs + (16*i+tr)*130 + dp*2);
            #pragma unroll
            for (int j = 0; j < 4; j++) k2[j] = *(const u64*)(Ks + (16*j+tc)*130 + dp*2);
            #pragma unroll
            for (int i = 0; i < 4; i++)
                #pragma unroll
                for (int j = 0; j < 4; j++)
                    s2[i][j] = ffma2(q2[i], k2[j], s2[i][j]);
        }
        #pragma unroll
        for (int i = 0; i < 4; i++){
            float s[4];
            #pragma unroll
            for (int j = 0; j < 4; j++){ float lo, hi; up2(s2[i][j], lo, hi); s[j] = lo + hi; }
            float mx = fmaxf(fmaxf(s[0], s[1]), fmaxf(s[2], s[3]));
            #pragma unroll
            for (int w = 1; w < 16; w <<= 1) mx = fmaxf(mx, __shfl_xor_sync(0xffffffffu, mx, w));
            float mnew  = fmaxf(m_run[i], mx);
            float alpha = __expf(m_run[i] - mnew);
            m_run[i] = mnew;
            float rs = 0.f;
            #pragma unroll
            for (int j = 0; j < 4; j++){ s[j] = __expf(s[j] - mnew); rs += s[j]; }
            #pragma unroll
            for (int w = 1; w < 16; w <<= 1) rs += __shfl_xor_sync(0xffffffffu, rs, w);
            l_run[i] = l_run[i]*alpha + rs;
            u64 a2 = pk2(alpha, alpha);
            #pragma unroll
            for (int j = 0; j < 4; j++) o2[i][j] = fmul2(o2[i][j], a2);
            #pragma unroll
            for (int j = 0; j < 4; j++) Ss[(16*i+tr)*65 + 16*j + tc] = s[j];
        }
        __syncthreads();
        #pragma unroll 2
        for (int kk = 0; kk < 64; kk++){
            u64 v2[4];
            #pragma unroll
            for (int j = 0; j < 4; j++) v2[j] = *(const u64*)(Vs + kk*130 + 2*tc + 32*j);
            #pragma unroll
            for (int i = 0; i < 4; i++){
                float p = Ss[(16*i+tr)*65 + kk];
                u64 p2 = pk2(p, p);
                #pragma unroll
                for (int j = 0; j < 4; j++) o2[i][j] = ffma2(p2, v2[j], o2[i][j]);
            }
        }
    }
    #pragma unroll
    for (int i = 0; i < 4; i++){
        float rl = 1.0f / l_run[i];
        int row = q0 + 16*i + tr;
        #pragma unroll
        for (int j = 0; j < 4; j++){
            float lo, hi; up2(o2[i][j], lo, hi);
            *(float2*)(g_cat + (size_t)row*CATN + nh*DD + 2*tc + 32*j)
                = make_float2(to_tf32(lo*rl), to_tf32(hi*rl));
        }
    }
}

// ---------------- gelu(mlp) -> g_cat[:, H:], tf32-rounded ---------------
__global__ void gelu_k(){
    int idx = blockIdx.x*256 + threadIdx.x;
    if (idx < LL*MLPD){
        int l = idx / MLPD, m = idx - l*MLPD;
        float v = g_h[(size_t)l*W1N + QKVN + m];
        float c = 0.7978845608028654f * (v + 0.044715f*v*v*v);
        g_cat[(size_t)l*CATN + HH + m] = to_tf32(0.5f*v*(1.f + tanhf(c)));
    }
}

// ---------------- launch --------------------------------------------------
extern "C" void kernel_launch(void* const* d_in, const int* in_sizes, int n_in,
                              void* d_out, int out_size){
    (void)in_sizes; (void)n_in; (void)out_size;
    const float* x       = (const float*)d_in[0];
    const float* vec     = (const float*)d_in[1];
    const float* pe      = (const float*)d_in[2];
    const float* mod_w   = (const float*)d_in[3];
    const float* mod_b   = (const float*)d_in[4];
    const float* ln_s    = (const float*)d_in[5];
    const float* ln_b    = (const float*)d_in[6];
    const float* w1      = (const float*)d_in[7];
    const float* b1      = (const float*)d_in[8];
    const float* q_scale = (const float*)d_in[9];
    const float* k_scale = (const float*)d_in[10];
    const float* w2      = (const float*)d_in[11];
    const float* b2      = (const float*)d_in[12];
    float* out = (float*)d_out;

    float *p_xmod, *p_h, *p_cat, *p_mod, *p_w1t, *p_w2t;
    cudaGetSymbolAddress((void**)&p_xmod, g_xmod);
    cudaGetSymbolAddress((void**)&p_h,    g_h);
    cudaGetSymbolAddress((void**)&p_cat,  g_cat);
    cudaGetSymbolAddress((void**)&p_mod,  g_mod);
    cudaGetSymbolAddress((void**)&p_w1t,  g_w1t);
    cudaGetSymbolAddress((void**)&p_w2t,  g_w2t);

    cudaFuncSetAttribute(attn_kernel, cudaFuncAttributeMaxDynamicSharedMemorySize, ATT_SMEM);
    cudaFuncSetAttribute(mma_gemm, cudaFuncAttributeMaxDynamicSharedMemorySize, MG_SMEM);

    transpose_tf32<<<dim3(W1N/32, HH/32), dim3(32,8)>>>(w1, p_w1t, HH, W1N);
    transpose_tf32<<<dim3(HH/32, CATN/32), dim3(32,8)>>>(w2, p_w2t, CATN, HH);
    silu_k  <<<(HH+255)/256, 256>>>(vec);
    mod_gemv<<<QKVN/256, 256>>>(mod_w, mod_b);
    ln_mod  <<<LL, 256>>>(x, ln_s, ln_b);
    mma_gemm<<<dim3(LL/256, W1N/128), 256, MG_SMEM>>>(p_xmod, p_w1t, b1, p_h,
                                                      W1N, HH, HH/16, nullptr, nullptr);
    qkv_post<<<dim3(LL, NHH), 64>>>(pe, q_scale, k_scale);
    attn_kernel<<<dim3(LL/64, NHH), 256, ATT_SMEM>>>();
    gelu_k  <<<(LL*MLPD + 255)/256, 256>>>();
    mma_gemm<<<dim3(LL/256, HH/128), 256, MG_SMEM>>>(p_cat, p_w2t, b2, out,
                                                     HH, CATN, CATN/16, x, p_mod + 2*HH);
}

// round 5
// speedup vs baseline: 2.3220x; 1.2988x over previous
#include <cuda_runtime.h>
#include <cuda_bf16.h>
#include <cstdint>

#define LL   2048
#define HH   3072
#define NHH  24
#define DD   128
#define MLPD 12288
#define W1N  21504
#define CATN 15360
#define QKVN 9216

typedef unsigned long long u64;

__device__ __forceinline__ float to_tf32(float x){
    float r; asm("cvt.rna.tf32.f32 %0, %1;" : "=f"(r) : "f"(x)); return r;
}
__device__ __forceinline__ uint32_t smem_u32(const void* p){
    uint32_t a; asm("{ .reg .u64 t; cvta.to.shared.u64 t, %1; cvt.u32.u64 %0, t; }" : "=r"(a) : "l"(p));
    return a;
}

// tf32 m16n8k8 warp MMA
__device__ __forceinline__ void mma_t32(float* c, const uint32_t* a, const uint32_t* b){
    asm volatile("mma.sync.aligned.m16n8k8.row.col.f32.tf32.tf32.f32 "
        "{%0,%1,%2,%3}, {%4,%5,%6,%7}, {%8,%9}, {%0,%1,%2,%3};"
        : "+f"(c[0]), "+f"(c[1]), "+f"(c[2]), "+f"(c[3])
        : "r"(a[0]), "r"(a[1]), "r"(a[2]), "r"(a[3]), "r"(b[0]), "r"(b[1]));
}

// ---------------- scratch ----------------
__device__ float g_sv[HH];
__device__ float g_mod[3*HH];
__device__ float g_xmod[(size_t)LL*HH];
__device__ float g_h[(size_t)LL*W1N];
__device__ float g_q[(size_t)NHH*LL*DD];
__device__ float g_k[(size_t)NHH*LL*DD];
__device__ float g_v[(size_t)NHH*LL*DD];
__device__ float g_cat[(size_t)LL*CATN];
__device__ float g_w1t[(size_t)W1N*HH];
__device__ float g_w2t[(size_t)HH*CATN];

// ---------------- transpose + tf32 round ------
__global__ void transpose_tf32(const float* __restrict__ in, float* __restrict__ out,
                               int R, int C){
    __shared__ float t[32][33];
    const int bx = blockIdx.x * 32;
    const int by = blockIdx.y * 32;
    const int tx = threadIdx.x, ty = threadIdx.y;
    #pragma unroll
    for (int i = 0; i < 32; i += 8)
        t[ty+i][tx] = in[(size_t)(by+ty+i)*C + bx+tx];
    __syncthreads();
    #pragma unroll
    for (int i = 0; i < 32; i += 8)
        out[(size_t)(bx+ty+i)*R + by+tx] = to_tf32(t[tx][ty+i]);
}

// ---------------- silu ----------------
__global__ void silu_k(const float* __restrict__ vec){
    int i = blockIdx.x*256 + threadIdx.x;
    if (i < HH){
        float t = vec[i];
        g_sv[i] = t / (1.f + expf(-t));
    }
}

// ---------------- mod init + K-split GEMV ----------------
__global__ void mod_init(const float* __restrict__ b){
    int i = blockIdx.x*256 + threadIdx.x;
    if (i < QKVN) g_mod[i] = b[i];
}
__global__ __launch_bounds__(256) void mod_gemv(const float* __restrict__ W){
    const int j  = blockIdx.x*256 + threadIdx.x;
    const int k0 = blockIdx.y*256;
    __shared__ float svs[256];
    svs[threadIdx.x] = g_sv[k0 + threadIdx.x];
    __syncthreads();
    float acc = 0.f;
    #pragma unroll 8
    for (int i = 0; i < 256; i++)
        acc = fmaf(svs[i], W[(size_t)(k0+i)*QKVN + j], acc);
    atomicAdd(&g_mod[j], acc);
}

// ---------------- LayerNorm + modulate (tf32-rounded output) --------------
__global__ __launch_bounds__(256) void ln_mod(const float* __restrict__ x,
                                              const float* __restrict__ lns,
                                              const float* __restrict__ lnb){
    const int l = blockIdx.x;
    const int tid = threadIdx.x;
    __shared__ float xs[HH];
    __shared__ float rsum[16];
    float s = 0.f, ss = 0.f;
    for (int i = tid; i < HH; i += 256){
        float v = x[(size_t)l*HH + i];
        xs[i] = v; s += v; ss = fmaf(v, v, ss);
    }
    #pragma unroll
    for (int w = 1; w < 32; w <<= 1){
        s  += __shfl_xor_sync(0xffffffffu, s,  w);
        ss += __shfl_xor_sync(0xffffffffu, ss, w);
    }
    int wid = tid >> 5;
    if ((tid & 31) == 0){ rsum[wid] = s; rsum[wid + 8] = ss; }
    __syncthreads();
    s = 0.f; ss = 0.f;
    #pragma unroll
    for (int w = 0; w < 8; w++){ s += rsum[w]; ss += rsum[w + 8]; }
    const float mu   = s  * (1.f/(float)HH);
    const float var  = ss * (1.f/(float)HH) - mu*mu;
    const float rstd = rsqrtf(var + 1e-6f);
    for (int i = tid; i < HH; i += 256){
        float xn = (xs[i] - mu) * rstd * lns[i] + lnb[i];
        g_xmod[(size_t)l*HH + i] = to_tf32((1.f + g_mod[HH+i]) * xn + g_mod[i]);
    }
}

// ---------------- tf32 mma.sync GEMM (unchanged from R4) ------------------
#define MG_STRIDE 20
#define MG_STAGE  (384*MG_STRIDE)
#define MG_SMEM   (2*MG_STAGE*4)

__global__ __launch_bounds__(256, 1)
void mma_gemm(const float* __restrict__ A, const float* __restrict__ Bt,
              const float* __restrict__ bias, float* __restrict__ C,
              int N, int K, int NIT,
              const float* __restrict__ xres, const float* __restrict__ gate)
{
    extern __shared__ float smd[];
    const uint32_t smb = smem_u32(smd);
    const int tid  = threadIdx.x;
    const int wid  = tid >> 5;
    const int lane = tid & 31;
    const int g    = lane >> 2;
    const int tig  = lane & 3;
    const int m0 = blockIdx.x * 256;
    const int n0 = blockIdx.y * 128;
    const int m0w = (wid & 3) * 64;
    const int n0w = (wid >> 2) * 64;

    const float* gp[6];
    uint32_t sof[6];
    #pragma unroll
    for (int i = 0; i < 6; i++){
        int idx = i*256 + tid;
        int row = idx >> 2;
        int seg = idx & 3;
        if (row < 256) gp[i] = A  + (size_t)(m0 + row)*K + seg*4;
        else           gp[i] = Bt + (size_t)(n0 + row - 256)*K + seg*4;
        sof[i] = (uint32_t)((row*MG_STRIDE + seg*4) * 4);
    }

#define MG_LOAD(IT, ST) do { \
        const uint32_t _sb = smb + (uint32_t)(ST)*(MG_STAGE*4); \
        _Pragma("unroll") \
        for (int _i = 0; _i < 6; _i++){ \
            asm volatile("cp.async.cg.shared.global [%0], [%1], 16;" \
                :: "r"(_sb + sof[_i]), "l"(gp[_i] + (size_t)(IT)*16) : "memory"); \
        } \
        asm volatile("cp.async.commit_group;" ::: "memory"); \
    } while(0)

    float c[4][8][4];
    #pragma unroll
    for (int mt = 0; mt < 4; mt++)
        #pragma unroll
        for (int nt = 0; nt < 8; nt++)
            #pragma unroll
            for (int q = 0; q < 4; q++) c[mt][nt][q] = 0.f;

    MG_LOAD(0, 0);

    for (int it = 0; it < NIT; ++it){
        const int st = it & 1;
        if (it + 1 < NIT){
            MG_LOAD(it + 1, st ^ 1);
            asm volatile("cp.async.wait_group 1;" ::: "memory");
        } else {
            asm volatile("cp.async.wait_group 0;" ::: "memory");
        }
        __syncthreads();

        const uint32_t* As = (const uint32_t*)(smd + st*MG_STAGE);
        const uint32_t* Bs = As + 256*MG_STRIDE;

        #pragma unroll
        for (int k8 = 0; k8 < 16; k8 += 8){
            uint32_t a[4][4];
            #pragma unroll
            for (int mt = 0; mt < 4; mt++){
                const uint32_t* ap = As + (m0w + mt*16 + g)*MG_STRIDE + k8 + tig;
                a[mt][0] = ap[0];
                a[mt][1] = ap[8*MG_STRIDE];
                a[mt][2] = ap[4];
                a[mt][3] = ap[8*MG_STRIDE + 4];
            }
            uint32_t b[8][2];
            #pragma unroll
            for (int nt = 0; nt < 8; nt++){
                const uint32_t* bp = Bs + (n0w + nt*8 + g)*MG_STRIDE + k8 + tig;
                b[nt][0] = bp[0];
                b[nt][1] = bp[4];
            }
            #pragma unroll
            for (int mt = 0; mt < 4; mt++)
                #pragma unroll
                for (int nt = 0; nt < 8; nt++)
                    mma_t32(c[mt][nt], a[mt], b[nt]);
        }
        __syncthreads();
    }

    #pragma unroll
    for (int mt = 0; mt < 4; mt++){
        const int m = m0 + m0w + mt*16 + g;
        #pragma unroll
        for (int nt = 0; nt < 8; nt++){
            const int n = n0 + n0w + nt*8 + 2*tig;
            const float b0 = __ldg(bias + n), b1 = __ldg(bias + n + 1);
            float v0 = c[mt][nt][0] + b0, v1 = c[mt][nt][1] + b1;
            float v2 = c[mt][nt][2] + b0, v3 = c[mt][nt][3] + b1;
            if (gate){
                const float g0 = __ldg(gate + n), g1 = __ldg(gate + n + 1);
                v0 = xres[(size_t)m*N + n]       + g0*v0;
                v1 = xres[(size_t)m*N + n + 1]   + g1*v1;
                v2 = xres[(size_t)(m+8)*N + n]   + g0*v2;
                v3 = xres[(size_t)(m+8)*N + n+1] + g1*v3;
            }
            *(float2*)(C + (size_t)m*N + n)     = make_float2(v0, v1);
            *(float2*)(C + (size_t)(m+8)*N + n) = make_float2(v2, v3);
        }
    }
}

// ---------------- qkv split + RMSNorm + RoPE -------------------------
__global__ void qkv_post(const float* __restrict__ pe,
                         const float* __restrict__ qsc,
                         const float* __restrict__ ksc){
    const int l  = blockIdx.x;
    const int nh = blockIdx.y;
    const int d2 = threadIdx.x;
    const float* hp = g_h + (size_t)l*W1N + nh*DD;
    float qe = hp[2*d2],        qo = hp[2*d2+1];
    float ke = hp[HH + 2*d2],   ko = hp[HH + 2*d2+1];
    float ve = hp[2*HH + 2*d2], vo = hp[2*HH + 2*d2+1];

    float sq = qe*qe + qo*qo;
    float sk = ke*ke + ko*ko;
    #pragma unroll
    for (int w = 1; w < 32; w <<= 1){
        sq += __shfl_xor_sync(0xffffffffu, sq, w);
        sk += __shfl_xor_sync(0xffffffffu, sk, w);
    }
    __shared__ float red[4];
    int wid = d2 >> 5;
    if ((d2 & 31) == 0){ red[wid*2] = sq; red[wid*2+1] = sk; }
    __syncthreads();
    sq = red[0] + red[2];
    sk = red[1] + red[3];
    const float rq = rsqrtf(sq * (1.f/128.f) + 1e-6f);
    const float rk = rsqrtf(sk * (1.f/128.f) + 1e-6f);
    qe *= rq * qsc[2*d2]; qo *= rq * qsc[2*d2+1];
    ke *= rk * ksc[2*d2]; ko *= rk * ksc[2*d2+1];
    const float4 r = *(const float4*)(pe + ((size_t)l*64 + d2)*4);
    float qe2 = r.x*qe + r.y*qo;
    float qo2 = r.z*qe + r.w*qo;
    float ke2 = r.x*ke + r.y*ko;
    float ko2 = r.z*ke + r.w*ko;
    size_t o = ((size_t)nh*LL + l)*DD + 2*d2;
    g_q[o] = qe2; g_q[o+1] = qo2;
    g_k[o] = ke2; g_k[o+1] = ko2;
    g_v[o] = ve;  g_v[o+1] = vo;
}

// ---------------- flash attention, tf32 mma.sync --------------------------
// 128 q-rows/CTA, 8 warps x 16 rows, K/V tiles of 64, online softmax in regs.
#define AT_S3 132                    // Q/K stride (floats)
#define AT_SV 136                    // V stride (conflict-free B-frag loads)
#define AT_SP 68                     // P stride
#define ATM_SMEM ((128*AT_S3 + 64*AT_S3 + 64*AT_SV + 128*AT_SP)*4)

__global__ __launch_bounds__(256, 1)
void attn_mma(){
    extern __shared__ __align__(16) float sm[];
    float* Qs = sm;
    float* Ks = Qs + 128*AT_S3;
    float* Vs = Ks + 64*AT_S3;
    float* Ps = Vs + 64*AT_SV;

    const int tid  = threadIdx.x;
    const int wid  = tid >> 5;
    const int lane = tid & 31;
    const int g    = lane >> 2;
    const int tig  = lane & 3;
    const int nh = blockIdx.y;
    const int q0 = blockIdx.x * 128;
    const float* Qh = g_q + (size_t)nh*LL*DD;
    const float* Kh = g_k + (size_t)nh*LL*DD;
    const float* Vh = g_v + (size_t)nh*LL*DD;
    const float qscale = 0.08838834764831845f;   // 1/sqrt(128)

    // Q tile: scale + tf32-round
    #pragma unroll 4
    for (int idx = tid; idx < 128*32; idx += 256){
        int r = idx >> 5, c4 = (idx & 31)*4;
        float4 v = *(const float4*)(Qh + (size_t)(q0+r)*DD + c4);
        v.x = to_tf32(v.x*qscale); v.y = to_tf32(v.y*qscale);
        v.z = to_tf32(v.z*qscale); v.w = to_tf32(v.w*qscale);
        *(float4*)(Qs + r*AT_S3 + c4) = v;
    }

    float o[16][4];
    #pragma unroll
    for (int nt = 0; nt < 16; nt++)
        #pragma unroll
        for (int q = 0; q < 4; q++) o[nt][q] = 0.f;
    float m0 = -1e30f, m1 = -1e30f, l0 = 0.f, l1 = 0.f;

    const float* Aq = Qs + (wid*16)*AT_S3;
    float* Pw = Ps + (wid*16)*AT_SP;

    for (int kt = 0; kt < LL/64; kt++){
        __syncthreads();
        const int kb = kt*64;
        #pragma unroll 2
        for (int idx = tid; idx < 64*32; idx += 256){
            int r = idx >> 5, c4 = (idx & 31)*4;
            float4 k4 = *(const float4*)(Kh + (size_t)(kb+r)*DD + c4);
            k4.x = to_tf32(k4.x); k4.y = to_tf32(k4.y);
            k4.z = to_tf32(k4.z); k4.w = to_tf32(k4.w);
            *(float4*)(Ks + r*AT_S3 + c4) = k4;
            float4 v4 = *(const float4*)(Vh + (size_t)(kb+r)*DD + c4);
            v4.x = to_tf32(v4.x); v4.y = to_tf32(v4.y);
            v4.z = to_tf32(v4.z); v4.w = to_tf32(v4.w);
            *(float4*)(Vs + r*AT_SV + c4) = v4;
        }
        __syncthreads();

        // S = Q @ K^T : per warp 16x64, K-dim 128
        float s[8][4];
        #pragma unroll
        for (int nt = 0; nt < 8; nt++)
            #pragma unroll
            for (int q = 0; q < 4; q++) s[nt][q] = 0.f;

        #pragma unroll
        for (int ks = 0; ks < 16; ks++){
            const int kk = ks*8;
            uint32_t a[4];
            a[0] = __float_as_uint(Aq[ g     *AT_S3 + kk + tig]);
            a[1] = __float_as_uint(Aq[(g+8)  *AT_S3 + kk + tig]);
            a[2] = __float_as_uint(Aq[ g     *AT_S3 + kk + tig + 4]);
            a[3] = __float_as_uint(Aq[(g+8)  *AT_S3 + kk + tig + 4]);
            #pragma unroll
            for (int nt = 0; nt < 8; nt++){
                const float* bp = Ks + (nt*8 + g)*AT_S3 + kk + tig;
                uint32_t b[2] = { __float_as_uint(bp[0]), __float_as_uint(bp[4]) };
                mma_t32(s[nt], a, b);
            }
        }

        // online softmax (rows g, g+8 of this warp's 16)
        float mx0 = -1e30f, mx1 = -1e30f;
        #pragma unroll
        for (int nt = 0; nt < 8; nt++){
            mx0 = fmaxf(mx0, fmaxf(s[nt][0], s[nt][1]));
            mx1 = fmaxf(mx1, fmaxf(s[nt][2], s[nt][3]));
        }
        mx0 = fmaxf(mx0, __shfl_xor_sync(0xffffffffu, mx0, 1));
        mx0 = fmaxf(mx0, __shfl_xor_sync(0xffffffffu, mx0, 2));
        mx1 = fmaxf(mx1, __shfl_xor_sync(0xffffffffu, mx1, 1));
        mx1 = fmaxf(mx1, __shfl_xor_sync(0xffffffffu, mx1, 2));
        const float mn0 = fmaxf(m0, mx0), mn1 = fmaxf(m1, mx1);
        const float al0 = __expf(m0 - mn0), al1 = __expf(m1 - mn1);
        m0 = mn0; m1 = mn1;
        float rs0 = 0.f, rs1 = 0.f;
        #pragma unroll
        for (int nt = 0; nt < 8; nt++){
            float p0 = __expf(s[nt][0] - mn0);
            float p1 = __expf(s[nt][1] - mn0);
            float p2 = __expf(s[nt][2] - mn1);
            float p3 = __expf(s[nt][3] - mn1);
            rs0 += p0 + p1; rs1 += p2 + p3;
            Pw[ g   *AT_SP + nt*8 + 2*tig]     = to_tf32(p0);
            Pw[ g   *AT_SP + nt*8 + 2*tig + 1] = to_tf32(p1);
            Pw[(g+8)*AT_SP + nt*8 + 2*tig]     = to_tf32(p2);
            Pw[(g+8)*AT_SP + nt*8 + 2*tig + 1] = to_tf32(p3);
        }
        rs0 += __shfl_xor_sync(0xffffffffu, rs0, 1);
        rs0 += __shfl_xor_sync(0xffffffffu, rs0, 2);
        rs1 += __shfl_xor_sync(0xffffffffu, rs1, 1);
        rs1 += __shfl_xor_sync(0xffffffffu, rs1, 2);
        l0 = l0*al0 + rs0;
        l1 = l1*al1 + rs1;
        #pragma unroll
        for (int nt = 0; nt < 16; nt++){
            o[nt][0] *= al0; o[nt][1] *= al0;
            o[nt][2] *= al1; o[nt][3] *= al1;
        }
        __syncwarp();

        // O += P @ V : per warp 16x128, K-dim 64 (B frags direct from V tile)
        #pragma unroll
        for (int ks = 0; ks < 8; ks++){
            const int kk = ks*8;
            uint32_t a[4];
            a[0] = __float_as_uint(Pw[ g   *AT_SP + kk + tig]);
            a[1] = __float_as_uint(Pw[(g+8)*AT_SP + kk + tig]);
            a[2] = __float_as_uint(Pw[ g   *AT_SP + kk + tig + 4]);
            a[3] = __float_as_uint(Pw[(g+8)*AT_SP + kk + tig + 4]);
            #pragma unroll
            for (int nt = 0; nt < 16; nt++){
                const float* vp = Vs + (kk + tig)*AT_SV + nt*8 + g;
                uint32_t b[2] = { __float_as_uint(vp[0]),
                                  __float_as_uint(vp[4*AT_SV]) };
                mma_t32(o[nt], a, b);
            }
        }
        __syncwarp();
    }

    // epilogue: normalize, tf32-round (input to GEMM2), write to g_cat
    const float rl0 = 1.0f / l0, rl1 = 1.0f / l1;
    const int r0 = q0 + wid*16 + g, r1 = r0 + 8;
    #pragma unroll
    for (int nt = 0; nt < 16; nt++){
        const int col = nh*DD + nt*8 + 2*tig;
        *(float2*)(g_cat + (size_t)r0*CATN + col)
            = make_float2(to_tf32(o[nt][0]*rl0), to_tf32(o[nt][1]*rl0));
        *(float2*)(g_cat + (size_t)r1*CATN + col)
            = make_float2(to_tf32(o[nt][2]*rl1), to_tf32(o[nt][3]*rl1));
    }
}

// ---------------- gelu(mlp) -> g_cat[:, H:], tf32-rounded ---------------
__global__ void gelu_k(){
    int idx = blockIdx.x*256 + threadIdx.x;
    if (idx < LL*MLPD){
        int l = idx / MLPD, m = idx - l*MLPD;
        float v = g_h[(size_t)l*W1N + QKVN + m];
        float c = 0.7978845608028654f * (v + 0.044715f*v*v*v);
        g_cat[(size_t)l*CATN + HH + m] = to_tf32(0.5f*v*(1.f + tanhf(c)));
    }
}

// ---------------- launch --------------------------------------------------
extern "C" void kernel_launch(void* const* d_in, const int* in_sizes, int n_in,
                              void* d_out, int out_size){
    (void)in_sizes; (void)n_in; (void)out_size;
    const float* x       = (const float*)d_in[0];
    const float* vec     = (const float*)d_in[1];
    const float* pe      = (const float*)d_in[2];
    const float* mod_w   = (const float*)d_in[3];
    const float* mod_b   = (const float*)d_in[4];
    const float* ln_s    = (const float*)d_in[5];
    const float* ln_b    = (const float*)d_in[6];
    const float* w1      = (const float*)d_in[7];
    const float* b1      = (const float*)d_in[8];
    const float* q_scale = (const float*)d_in[9];
    const float* k_scale = (const float*)d_in[10];
    const float* w2      = (const float*)d_in[11];
    const float* b2      = (const float*)d_in[12];
    float* out = (float*)d_out;

    float *p_xmod, *p_h, *p_cat, *p_mod, *p_w1t, *p_w2t;
    cudaGetSymbolAddress((void**)&p_xmod, g_xmod);
    cudaGetSymbolAddress((void**)&p_h,    g_h);
    cudaGetSymbolAddress((void**)&p_cat,  g_cat);
    cudaGetSymbolAddress((void**)&p_mod,  g_mod);
    cudaGetSymbolAddress((void**)&p_w1t,  g_w1t);
    cudaGetSymbolAddress((void**)&p_w2t,  g_w2t);

    cudaFuncSetAttribute(attn_mma, cudaFuncAttributeMaxDynamicSharedMemorySize, ATM_SMEM);
    cudaFuncSetAttribute(mma_gemm, cudaFuncAttributeMaxDynamicSharedMemorySize, MG_SMEM);

    transpose_tf32<<<dim3(W1N/32, HH/32), dim3(32,8)>>>(w1, p_w1t, HH, W1N);
    transpose_tf32<<<dim3(HH/32, CATN/32), dim3(32,8)>>>(w2, p_w2t, CATN, HH);
    silu_k  <<<(HH+255)/256, 256>>>(vec);
    mod_init<<<QKVN/256, 256>>>(mod_b);
    mod_gemv<<<dim3(QKVN/256, HH/256), 256>>>(mod_w);
    ln_mod  <<<LL, 256>>>(x, ln_s, ln_b);
    mma_gemm<<<dim3(LL/256, W1N/128), 256, MG_SMEM>>>(p_xmod, p_w1t, b1, p_h,
                                                      W1N, HH, HH/16, nullptr, nullptr);
    qkv_post<<<dim3(LL, NHH), 64>>>(pe, q_scale, k_scale);
    attn_mma<<<dim3(LL/128, NHH), 256, ATM_SMEM>>>();
    gelu_k  <<<(LL*MLPD + 255)/256, 256>>>();
    mma_gemm<<<dim3(LL/256, HH/128), 256, MG_SMEM>>>(p_cat, p_w2t, b2, out,
                                                     HH, CATN, CATN/16, x, p_mod + 2*HH);
}

// round 7
// speedup vs baseline: 5.0213x; 2.1625x over previous
#include <cuda_runtime.h>
#include <cuda_fp16.h>
#include <cstdint>
#include <cstring>

#define LL   2048
#define HH   3072
#define NHH  24
#define DD   128
#define MLPD 12288
#define W1N  21504
#define CATN 15360
#define QKVN 9216

typedef unsigned long long u64;

__device__ __forceinline__ uint32_t h2_u32(__half2 h){
    uint32_t u; memcpy(&u, &h, 4); return u;
}
__device__ __forceinline__ uint32_t smem_u32(const void* p){
    uint32_t a; asm("{ .reg .u64 t; cvta.to.shared.u64 t, %1; cvt.u32.u64 %0, t; }" : "=r"(a) : "l"(p));
    return a;
}
// fp16 m16n8k16 warp MMA, fp32 accum
__device__ __forceinline__ void mma_f16(float* c, const uint32_t* a, const uint32_t* b){
    asm volatile("mma.sync.aligned.m16n8k16.row.col.f32.f16.f16.f32 "
        "{%0,%1,%2,%3}, {%4,%5,%6,%7}, {%8,%9}, {%0,%1,%2,%3};"
        : "+f"(c[0]), "+f"(c[1]), "+f"(c[2]), "+f"(c[3])
        : "r"(a[0]), "r"(a[1]), "r"(a[2]), "r"(a[3]), "r"(b[0]), "r"(b[1]));
}
__device__ __forceinline__ void ldsm_x4(uint32_t* r, uint32_t a){
    asm volatile("ldmatrix.sync.aligned.m8n8.x4.shared.b16 {%0,%1,%2,%3}, [%4];"
        : "=r"(r[0]), "=r"(r[1]), "=r"(r[2]), "=r"(r[3]) : "r"(a));
}
__device__ __forceinline__ void ldsm_x2(uint32_t* r, uint32_t a){
    asm volatile("ldmatrix.sync.aligned.m8n8.x2.shared.b16 {%0,%1}, [%2];"
        : "=r"(r[0]), "=r"(r[1]) : "r"(a));
}
__device__ __forceinline__ void ldsm_x2t(uint32_t* r, uint32_t a){
    asm volatile("ldmatrix.sync.aligned.m8n8.x2.trans.shared.b16 {%0,%1}, [%2];"
        : "=r"(r[0]), "=r"(r[1]) : "r"(a));
}

// ---------------- scratch ----------------
__device__ float  g_sv[HH];
__device__ float  g_mod[3*HH];
__device__ __half g_xmodh[(size_t)LL*HH];
__device__ float  g_h[(size_t)LL*W1N];
__device__ __half g_qh[(size_t)NHH*LL*DD];
__device__ __half g_kh[(size_t)NHH*LL*DD];
__device__ __half g_vh[(size_t)NHH*LL*DD];
__device__ __half g_cath[(size_t)LL*CATN];
__device__ __half g_w1t[(size_t)W1N*HH];
__device__ __half g_w2t[(size_t)HH*CATN];

// ---------------- transpose + fp16 convert: out[C][R] = h(in[R][C]) ------
__global__ void transpose_f16(const float* __restrict__ in, __half* __restrict__ out,
                              int R, int C){
    __shared__ float t[32][33];
    const int bx = blockIdx.x * 32;
    const int by = blockIdx.y * 32;
    const int tx = threadIdx.x, ty = threadIdx.y;
    #pragma unroll
    for (int i = 0; i < 32; i += 8)
        t[ty+i][tx] = in[(size_t)(by+ty+i)*C + bx+tx];
    __syncthreads();
    #pragma unroll
    for (int i = 0; i < 32; i += 8)
        out[(size_t)(bx+ty+i)*R + by+tx] = __float2half(t[tx][ty+i]);
}

// ---------------- silu ----------------
__global__ void silu_k(const float* __restrict__ vec){
    int i = blockIdx.x*256 + threadIdx.x;
    if (i < HH){
        float t = vec[i];
        g_sv[i] = t / (1.f + expf(-t));
    }
}

// ---------------- mod init + K-split GEMV ----------------
__global__ void mod_init(const float* __restrict__ b){
    int i = blockIdx.x*256 + threadIdx.x;
    if (i < QKVN) g_mod[i] = b[i];
}
__global__ __launch_bounds__(256) void mod_gemv(const float* __restrict__ W){
    const int j  = blockIdx.x*256 + threadIdx.x;
    const int k0 = blockIdx.y*256;
    __shared__ float svs[256];
    svs[threadIdx.x] = g_sv[k0 + threadIdx.x];
    __syncthreads();
    float acc = 0.f;
    #pragma unroll 8
    for (int i = 0; i < 256; i++)
        acc = fmaf(svs[i], W[(size_t)(k0+i)*QKVN + j], acc);
    atomicAdd(&g_mod[j], acc);
}

// ---------------- LayerNorm + modulate (half output) ----------------------
__global__ __launch_bounds__(256) void ln_mod(const float* __restrict__ x,
                                              const float* __restrict__ lns,
                                              const float* __restrict__ lnb){
    const int l = blockIdx.x;
    const int tid = threadIdx.x;
    __shared__ float xs[HH];
    __shared__ float rsum[16];
    float s = 0.f, ss = 0.f;
    for (int i = tid; i < HH; i += 256){
        float v = x[(size_t)l*HH + i];
        xs[i] = v; s += v; ss = fmaf(v, v, ss);
    }
    #pragma unroll
    for (int w = 1; w < 32; w <<= 1){
        s  += __shfl_xor_sync(0xffffffffu, s,  w);
        ss += __shfl_xor_sync(0xffffffffu, ss, w);
    }
    int wid = tid >> 5;
    if ((tid & 31) == 0){ rsum[wid] = s; rsum[wid + 8] = ss; }
    __syncthreads();
    s = 0.f; ss = 0.f;
    #pragma unroll
    for (int w = 0; w < 8; w++){ s += rsum[w]; ss += rsum[w + 8]; }
    const float mu   = s  * (1.f/(float)HH);
    const float var  = ss * (1.f/(float)HH) - mu*mu;
    const float rstd = rsqrtf(var + 1e-6f);
    for (int i = tid; i < HH; i += 256){
        float xn = (xs[i] - mu) * rstd * lns[i] + lnb[i];
        g_xmodh[(size_t)l*HH + i] = __float2half((1.f + g_mod[HH+i]) * xn + g_mod[i]);
    }
}

// ---------------- fp16 mma.sync GEMM with ldmatrix ------------------------
// C[M,N] = A[M,K] @ Bt[N,K]^T + bias ; optional: C = xres + gate*(acc+bias)
// CTA 256x128, warp 64x64 (8 warps = 4m x 2n), K-chunk 64 halves (128B/row).
#define MGF_RB    144
#define MGF_STAGE (384*MGF_RB)
#define MGF_SMEM  (2*MGF_STAGE)

__global__ __launch_bounds__(256, 1)
void mma_gemm_f16(const __half* __restrict__ A, const __half* __restrict__ Bt,
                  const float* __restrict__ bias, float* __restrict__ C,
                  int N, int K, int NIT,
                  const float* __restrict__ xres, const float* __restrict__ gate)
{
    extern __shared__ char smc[];
    const uint32_t smb = smem_u32(smc);
    const int tid  = threadIdx.x;
    const int wid  = tid >> 5;
    const int lane = tid & 31;
    const int g    = lane >> 2;
    const int tig  = lane & 3;
    const int m0 = blockIdx.x * 256;
    const int n0 = blockIdx.y * 128;
    const int m0w = (wid & 3) * 64;
    const int n0w = (wid >> 2) * 64;

    const char* gp[12];
    uint32_t sof[12];
    #pragma unroll
    for (int i = 0; i < 12; i++){
        int idx = i*256 + tid;
        int row = idx >> 3;
        int seg = idx & 7;
        if (row < 256) gp[i] = (const char*)(A  + (size_t)(m0 + row)*K) + seg*16;
        else           gp[i] = (const char*)(Bt + (size_t)(n0 + row - 256)*K) + seg*16;
        sof[i] = (uint32_t)(row*MGF_RB + seg*16);
    }

#define MGF_LOAD(IT, ST) do { \
        const uint32_t _sb = smb + (uint32_t)(ST)*MGF_STAGE; \
        _Pragma("unroll") \
        for (int _i = 0; _i < 12; _i++){ \
            asm volatile("cp.async.cg.shared.global [%0], [%1], 16;" \
                :: "r"(_sb + sof[_i]), "l"(gp[_i] + (size_t)(IT)*128) : "memory"); \
        } \
        asm volatile("cp.async.commit_group;" ::: "memory"); \
    } while(0)

    float c[4][8][4];
    #pragma unroll
    for (int mt = 0; mt < 4; mt++)
        #pragma unroll
        for (int nt = 0; nt < 8; nt++)
            #pragma unroll
            for (int q = 0; q < 4; q++) c[mt][nt][q] = 0.f;

    const uint32_t aoff = (uint32_t)((lane & 15)*MGF_RB + ((lane >> 4) & 1)*16);
    const uint32_t boff = (uint32_t)(256*MGF_RB + (lane & 7)*MGF_RB + ((lane >> 3) & 1)*16);

    MGF_LOAD(0, 0);

    for (int it = 0; it < NIT; ++it){
        const int st = it & 1;
        if (it + 1 < NIT){
            MGF_LOAD(it + 1, st ^ 1);
            asm volatile("cp.async.wait_group 1;" ::: "memory");
        } else {
            asm volatile("cp.async.wait_group 0;" ::: "memory");
        }
        __syncthreads();

        const uint32_t sb = smb + (uint32_t)st*MGF_STAGE;
        #pragma unroll
        for (int k16 = 0; k16 < 4; k16++){
            uint32_t a[4][4];
            #pragma unroll
            for (int mt = 0; mt < 4; mt++)
                ldsm_x4(a[mt], sb + (uint32_t)((m0w + mt*16)*MGF_RB) + aoff + k16*32);
            uint32_t b[8][2];
            #pragma unroll
            for (int nt = 0; nt < 8; nt++)
                ldsm_x2(b[nt], sb + (uint32_t)((n0w + nt*8)*MGF_RB) + boff + k16*32);
            #pragma unroll
            for (int mt = 0; mt < 4; mt++)
                #pragma unroll
                for (int nt = 0; nt < 8; nt++)
                    mma_f16(c[mt][nt], a[mt], b[nt]);
        }
        __syncthreads();
    }

    #pragma unroll
    for (int mt = 0; mt < 4; mt++){
        const int m = m0 + m0w + mt*16 + g;
        #pragma unroll
        for (int nt = 0; nt < 8; nt++){
            const int n = n0 + n0w + nt*8 + 2*tig;
            const float b0 = __ldg(bias + n), b1 = __ldg(bias + n + 1);
            float v0 = c[mt][nt][0] + b0, v1 = c[mt][nt][1] + b1;
            float v2 = c[mt][nt][2] + b0, v3 = c[mt][nt][3] + b1;
            if (gate){
                const float g0 = __ldg(gate + n), g1 = __ldg(gate + n + 1);
                v0 = xres[(size_t)m*N + n]       + g0*v0;
                v1 = xres[(size_t)m*N + n + 1]   + g1*v1;
                v2 = xres[(size_t)(m+8)*N + n]   + g0*v2;
                v3 = xres[(size_t)(m+8)*N + n+1] + g1*v3;
            }
            *(float2*)(C + (size_t)m*N + n)     = make_float2(v0, v1);
            *(float2*)(C + (size_t)(m+8)*N + n) = make_float2(v2, v3);
        }
    }
}

// ---------------- qkv split + RMSNorm + RoPE -> half ----------------------
__global__ void qkv_post(const float* __restrict__ pe,
                         const float* __restrict__ qsc,
                         const float* __restrict__ ksc){
    const int l  = blockIdx.x;
    const int nh = blockIdx.y;
    const int d2 = threadIdx.x;
    const float* hp = g_h + (size_t)l*W1N + nh*DD;
    float qe = hp[2*d2],        qo = hp[2*d2+1];
    float ke = hp[HH + 2*d2],   ko = hp[HH + 2*d2+1];
    float ve = hp[2*HH + 2*d2], vo = hp[2*HH + 2*d2+1];

    float sq = qe*qe + qo*qo;
    float sk = ke*ke + ko*ko;
    #pragma unroll
    for (int w = 1; w < 32; w <<= 1){
        sq += __shfl_xor_sync(0xffffffffu, sq, w);
        sk += __shfl_xor_sync(0xffffffffu, sk, w);
    }
    __shared__ float red[4];
    int wid = d2 >> 5;
    if ((d2 & 31) == 0){ red[wid*2] = sq; red[wid*2+1] = sk; }
    __syncthreads();
    sq = red[0] + red[2];
    sk = red[1] + red[3];
    const float rq = rsqrtf(sq * (1.f/128.f) + 1e-6f);
    const float rk = rsqrtf(sk * (1.f/128.f) + 1e-6f);
    qe *= rq * qsc[2*d2]; qo *= rq * qsc[2*d2+1];
    ke *= rk * ksc[2*d2]; ko *= rk * ksc[2*d2+1];
    const float4 r = *(const float4*)(pe + ((size_t)l*64 + d2)*4);
    const float qscale = 0.08838834764831845f;   // 1/sqrt(128), folded into q
    float qe2 = (r.x*qe + r.y*qo) * qscale;
    float qo2 = (r.z*qe + r.w*qo) * qscale;
    float ke2 = r.x*ke + r.y*ko;
    float ko2 = r.z*ke + r.w*ko;
    size_t o = ((size_t)nh*LL + l)*DD + 2*d2;
    g_qh[o] = __float2half(qe2); g_qh[o+1] = __float2half(qo2);
    g_kh[o] = __float2half(ke2); g_kh[o+1] = __float2half(ko2);
    g_vh[o] = __float2half(ve);  g_vh[o+1] = __float2half(vo);
}

// ---------------- flash attention, fp16 mma.sync + ldmatrix ----------------
#define AQ_RB 272
#define AP_RB 144
#define AQ_OFF 0
#define AK_OFF (128*AQ_RB)
#define AV_OFF (AK_OFF + 64*AQ_RB)
#define AP_OFF (AV_OFF + 64*AQ_RB)
#define ATF_SMEM (AP_OFF + 128*AP_RB)

__global__ __launch_bounds__(256, 1)
void attn_f16(){
    extern __shared__ char smc[];
    const uint32_t smb = smem_u32(smc);
    const int tid  = threadIdx.x;
    const int wid  = tid >> 5;
    const int lane = tid & 31;
    const int g    = lane >> 2;
    const int tig  = lane & 3;
    const int nh = blockIdx.y;
    const int q0 = blockIdx.x * 128;
    const __half* Qh = g_qh + (size_t)nh*LL*DD;
    const __half* Kh = g_kh + (size_t)nh*LL*DD;
    const __half* Vh = g_vh + (size_t)nh*LL*DD;

    #pragma unroll
    for (int i = 0; i < 8; i++){
        int idx = i*256 + tid;
        int r = idx >> 4, s = idx & 15;
        uint4 v = *(const uint4*)((const char*)(Qh + (size_t)(q0+r)*DD) + s*16);
        *(uint4*)(smc + AQ_OFF + r*AQ_RB + s*16) = v;
    }

    float o[16][4];
    #pragma unroll
    for (int nt = 0; nt < 16; nt++)
        #pragma unroll
        for (int q = 0; q < 4; q++) o[nt][q] = 0.f;
    float m0 = -1e30f, m1 = -1e30f, l0 = 0.f, l1 = 0.f;

    const uint32_t aoffQ = smb + AQ_OFF + (uint32_t)((wid*16 + (lane & 15))*AQ_RB + ((lane >> 4) & 1)*16);
    const uint32_t boffK = smb + AK_OFF + (uint32_t)((lane & 7)*AQ_RB + ((lane >> 3) & 1)*16);
    const uint32_t aoffP = smb + AP_OFF + (uint32_t)((wid*16 + (lane & 15))*AP_RB + ((lane >> 4) & 1)*16);
    const uint32_t boffV = smb + AV_OFF + (uint32_t)((lane & 15)*AQ_RB);
    char* Pw = smc + AP_OFF + wid*16*AP_RB;

    for (int kt = 0; kt < LL/64; kt++){
        __syncthreads();
        const int kb = kt*64;
        #pragma unroll
        for (int i = 0; i < 4; i++){
            int idx = i*256 + tid;
            int r = idx >> 4, s = idx & 15;
            uint4 kv = *(const uint4*)((const char*)(Kh + (size_t)(kb+r)*DD) + s*16);
            *(uint4*)(smc + AK_OFF + r*AQ_RB + s*16) = kv;
            uint4 vv = *(const uint4*)((const char*)(Vh + (size_t)(kb+r)*DD) + s*16);
            *(uint4*)(smc + AV_OFF + r*AQ_RB + s*16) = vv;
        }
        __syncthreads();

        float s[8][4];
        #pragma unroll
        for (int nt = 0; nt < 8; nt++)
            #pragma unroll
            for (int q = 0; q < 4; q++) s[nt][q] = 0.f;
        #pragma unroll
        for (int k16 = 0; k16 < 8; k16++){
            uint32_t a[4];
            ldsm_x4(a, aoffQ + k16*32);
            #pragma unroll
            for (int nt = 0; nt < 8; nt++){
                uint32_t b[2];
                ldsm_x2(b, boffK + (uint32_t)(nt*8*AQ_RB) + k16*32);
                mma_f16(s[nt], a, b);
            }
        }

        float mx0 = -1e30f, mx1 = -1e30f;
        #pragma unroll
        for (int nt = 0; nt < 8; nt++){
            mx0 = fmaxf(mx0, fmaxf(s[nt][0], s[nt][1]));
            mx1 = fmaxf(mx1, fmaxf(s[nt][2], s[nt][3]));
        }
        mx0 = fmaxf(mx0, __shfl_xor_sync(0xffffffffu, mx0, 1));
        mx0 = fmaxf(mx0, __shfl_xor_sync(0xffffffffu, mx0, 2));
        mx1 = fmaxf(mx1, __shfl_xor_sync(0xffffffffu, mx1, 1));
        mx1 = fmaxf(mx1, __shfl_xor_sync(0xffffffffu, mx1, 2));
        const float mn0 = fmaxf(m0, mx0), mn1 = fmaxf(m1, mx1);
        const float al0 = __expf(m0 - mn0), al1 = __expf(m1 - mn1);
        m0 = mn0; m1 = mn1;
        float rs0 = 0.f, rs1 = 0.f;
        #pragma unroll
        for (int nt = 0; nt < 8; nt++){
            float p0 = __expf(s[nt][0] - mn0);
            float p1 = __expf(s[nt][1] - mn0);
            float p2 = __expf(s[nt][2] - mn1);
            float p3 = __expf(s[nt][3] - mn1);
            rs0 += p0 + p1; rs1 += p2 + p3;
            *(uint32_t*)(Pw +  g   *AP_RB + (nt*8 + 2*tig)*2)
                = h2_u32(__floats2half2_rn(p0, p1));
            *(uint32_t*)(Pw + (g+8)*AP_RB + (nt*8 + 2*tig)*2)
                = h2_u32(__floats2half2_rn(p2, p3));
        }
        rs0 += __shfl_xor_sync(0xffffffffu, rs0, 1);
        rs0 += __shfl_xor_sync(0xffffffffu, rs0, 2);
        rs1 += __shfl_xor_sync(0xffffffffu, rs1, 1);
        rs1 += __shfl_xor_sync(0xffffffffu, rs1, 2);
        l0 = l0*al0 + rs0;
        l1 = l1*al1 + rs1;
        #pragma unroll
        for (int nt = 0; nt < 16; nt++){
            o[nt][0] *= al0; o[nt][1] *= al0;
            o[nt][2] *= al1; o[nt][3] *= al1;
        }
        __syncwarp();

        #pragma unroll
        for (int k16 = 0; k16 < 4; k16++){
            uint32_t a[4];
            ldsm_x4(a, aoffP + k16*32);
            #pragma unroll
            for (int nt = 0; nt < 16; nt++){
                uint32_t b[2];
                ldsm_x2t(b, boffV + (uint32_t)(k16*16*AQ_RB) + nt*16);
                mma_f16(o[nt], a, b);
            }
        }
        __syncwarp();
    }

    const float rl0 = 1.0f / l0, rl1 = 1.0f / l1;
    const int r0 = q0 + wid*16 + g, r1 = r0 + 8;
    #pragma unroll
    for (int nt = 0; nt < 16; nt++){
        const int col = nh*DD + nt*8 + 2*tig;
        *(uint32_t*)(g_cath + (size_t)r0*CATN + col)
            = h2_u32(__floats2half2_rn(o[nt][0]*rl0, o[nt][1]*rl0));
        *(uint32_t*)(g_cath + (size_t)r1*CATN + col)
            = h2_u32(__floats2half2_rn(o[nt][2]*rl1, o[nt][3]*rl1));
    }
}

// ---------------- gelu(mlp) -> g_cat[:, H:], half --------------------------
__global__ void gelu_k(){
    int idx = blockIdx.x*256 + threadIdx.x;
    if (idx < LL*MLPD){
        int l = idx / MLPD, m = idx - l*MLPD;
        float v = g_h[(size_t)l*W1N + QKVN + m];
        float c = 0.7978845608028654f * (v + 0.044715f*v*v*v);
        g_cath[(size_t)l*CATN + HH + m] = __float2half(0.5f*v*(1.f + tanhf(c)));
    }
}

// ---------------- launch --------------------------------------------------
extern "C" void kernel_launch(void* const* d_in, const int* in_sizes, int n_in,
                              void* d_out, int out_size){
    (void)in_sizes; (void)n_in; (void)out_size;
    const float* x       = (const float*)d_in[0];
    const float* vec     = (const float*)d_in[1];
    const float* pe      = (const float*)d_in[2];
    const float* mod_w   = (const float*)d_in[3];
    const float* mod_b   = (const float*)d_in[4];
    const float* ln_s    = (const float*)d_in[5];
    const float* ln_b    = (const float*)d_in[6];
    const float* w1      = (const float*)d_in[7];
    const float* b1      = (const float*)d_in[8];
    const float* q_scale = (const float*)d_in[9];
    const float* k_scale = (const float*)d_in[10];
    const float* w2      = (const float*)d_in[11];
    const float* b2      = (const float*)d_in[12];
    float* out = (float*)d_out;

    float *p_h, *p_mod;
    __half *p_xmodh, *p_cath, *p_w1t, *p_w2t;
    cudaGetSymbolAddress((void**)&p_xmodh, g_xmodh);
    cudaGetSymbolAddress((void**)&p_h,     g_h);
    cudaGetSymbolAddress((void**)&p_cath,  g_cath);
    cudaGetSymbolAddress((void**)&p_mod,   g_mod);
    cudaGetSymbolAddress((void**)&p_w1t,   g_w1t);
    cudaGetSymbolAddress((void**)&p_w2t,   g_w2t);

    cudaFuncSetAttribute(attn_f16, cudaFuncAttributeMaxDynamicSharedMemorySize, ATF_SMEM);
    cudaFuncSetAttribute(mma_gemm_f16, cudaFuncAttributeMaxDynamicSharedMemorySize, MGF_SMEM);

    transpose_f16<<<dim3(W1N/32, HH/32), dim3(32,8)>>>(w1, p_w1t, HH, W1N);
    transpose_f16<<<dim3(HH/32, CATN/32), dim3(32,8)>>>(w2, p_w2t, CATN, HH);
    silu_k  <<<(HH+255)/256, 256>>>(vec);
    mod_init<<<QKVN/256, 256>>>(mod_b);
    mod_gemv<<<dim3(QKVN/256, HH/256), 256>>>(mod_w);
    ln_mod  <<<LL, 256>>>(x, ln_s, ln_b);
    mma_gemm_f16<<<dim3(LL/256, W1N/128), 256, MGF_SMEM>>>(p_xmodh, p_w1t, b1, p_h,
                                                           W1N, HH, HH/64, nullptr, nullptr);
    qkv_post<<<dim3(LL, NHH), 64>>>(pe, q_scale, k_scale);
    attn_f16<<<dim3(LL/128, NHH), 256, ATF_SMEM>>>();
    gelu_k  <<<(LL*MLPD + 255)/256, 256>>>();
    mma_gemm_f16<<<dim3(LL/256, HH/128), 256, MGF_SMEM>>>(p_cath, p_w2t, b2, out,
                                                          HH, CATN, CATN/64, x, p_mod + 2*HH);
}

// round 8
// speedup vs baseline: 5.3999x; 1.0754x over previous
#include <cuda_runtime.h>
#include <cuda_fp16.h>
#include <cstdint>
#include <cstring>

#define LL   2048
#define HH   3072
#define NHH  24
#define DD   128
#define MLPD 12288
#define W1N  21504
#define CATN 15360
#define QKVN 9216

__device__ __forceinline__ uint32_t h2_u32(__half2 h){
    uint32_t u; memcpy(&u, &h, 4); return u;
}
__device__ __forceinline__ uint32_t smem_u32(const void* p){
    uint32_t a; asm("{ .reg .u64 t; cvta.to.shared.u64 t, %1; cvt.u32.u64 %0, t; }" : "=r"(a) : "l"(p));
    return a;
}
__device__ __forceinline__ float gelu_f(float v){
    float c = 0.7978845608028654f * (v + 0.044715f*v*v*v);
    return 0.5f*v*(1.f + tanhf(c));
}
// fp16 m16n8k16 warp MMA, fp32 accum
__device__ __forceinline__ void mma_f16(float* c, const uint32_t* a, const uint32_t* b){
    asm volatile("mma.sync.aligned.m16n8k16.row.col.f32.f16.f16.f32 "
        "{%0,%1,%2,%3}, {%4,%5,%6,%7}, {%8,%9}, {%0,%1,%2,%3};"
        : "+f"(c[0]), "+f"(c[1]), "+f"(c[2]), "+f"(c[3])
        : "r"(a[0]), "r"(a[1]), "r"(a[2]), "r"(a[3]), "r"(b[0]), "r"(b[1]));
}
__device__ __forceinline__ void ldsm_x4(uint32_t* r, uint32_t a){
    asm volatile("ldmatrix.sync.aligned.m8n8.x4.shared.b16 {%0,%1,%2,%3}, [%4];"
        : "=r"(r[0]), "=r"(r[1]), "=r"(r[2]), "=r"(r[3]) : "r"(a));
}
__device__ __forceinline__ void ldsm_x2(uint32_t* r, uint32_t a){
    asm volatile("ldmatrix.sync.aligned.m8n8.x2.shared.b16 {%0,%1}, [%2];"
        : "=r"(r[0]), "=r"(r[1]) : "r"(a));
}
__device__ __forceinline__ void ldsm_x2t(uint32_t* r, uint32_t a){
    asm volatile("ldmatrix.sync.aligned.m8n8.x2.trans.shared.b16 {%0,%1}, [%2];"
        : "=r"(r[0]), "=r"(r[1]) : "r"(a));
}

// ---------------- scratch ----------------
__device__ float  g_sv[HH];
__device__ float  g_mod[3*HH];
__device__ __half g_xmodh[(size_t)LL*HH];
__device__ float  g_h3[(size_t)LL*QKVN];     // qkv (fp32, for RMSNorm precision)
__device__ __half g_qh[(size_t)NHH*LL*DD];
__device__ __half g_kh[(size_t)NHH*LL*DD];
__device__ __half g_vh[(size_t)NHH*LL*DD];
__device__ __half g_cath[(size_t)LL*CATN];
__device__ __half g_w1h[(size_t)HH*W1N];     // fp16 copy, [K][N]
__device__ __half g_w2h[(size_t)CATN*HH];    // fp16 copy, [K][N]

// ---------------- fp32 -> fp16 convert (same layout) ----------------------
__global__ void conv_f16(const float4* __restrict__ in, uint2* __restrict__ out, int n4){
    int i = blockIdx.x*256 + threadIdx.x;
    if (i < n4){
        float4 v = in[i];
        __half2 a = __floats2half2_rn(v.x, v.y);
        __half2 b = __floats2half2_rn(v.z, v.w);
        uint2 o; memcpy(&o.x, &a, 4); memcpy(&o.y, &b, 4);
        out[i] = o;
    }
}

// ---------------- silu + mod init ----------------
__global__ void silu_init(const float* __restrict__ vec, const float* __restrict__ b){
    int i = blockIdx.x*256 + threadIdx.x;
    if (i < HH){
        float t = vec[i];
        g_sv[i] = t / (1.f + expf(-t));
    }
    if (i < QKVN) g_mod[i] = b[i];
}

// ---------------- K-split GEMV ----------------
__global__ __launch_bounds__(256) void mod_gemv(const float* __restrict__ W){
    const int j  = blockIdx.x*256 + threadIdx.x;
    const int k0 = blockIdx.y*256;
    __shared__ float svs[256];
    svs[threadIdx.x] = g_sv[k0 + threadIdx.x];
    __syncthreads();
    float acc = 0.f;
    #pragma unroll 8
    for (int i = 0; i < 256; i++)
        acc = fmaf(svs[i], W[(size_t)(k0+i)*QKVN + j], acc);
    atomicAdd(&g_mod[j], acc);
}

// ---------------- LayerNorm + modulate (half output) ----------------------
__global__ __launch_bounds__(256) void ln_mod(const float* __restrict__ x,
                                              const float* __restrict__ lns,
                                              const float* __restrict__ lnb){
    const int l = blockIdx.x;
    const int tid = threadIdx.x;
    __shared__ float xs[HH];
    __shared__ float rsum[16];
    float s = 0.f, ss = 0.f;
    for (int i = tid; i < HH; i += 256){
        float v = x[(size_t)l*HH + i];
        xs[i] = v; s += v; ss = fmaf(v, v, ss);
    }
    #pragma unroll
    for (int w = 1; w < 32; w <<= 1){
        s  += __shfl_xor_sync(0xffffffffu, s,  w);
        ss += __shfl_xor_sync(0xffffffffu, ss, w);
    }
    int wid = tid >> 5;
    if ((tid & 31) == 0){ rsum[wid] = s; rsum[wid + 8] = ss; }
    __syncthreads();
    s = 0.f; ss = 0.f;
    #pragma unroll
    for (int w = 0; w < 8; w++){ s += rsum[w]; ss += rsum[w + 8]; }
    const float mu   = s  * (1.f/(float)HH);
    const float var  = ss * (1.f/(float)HH) - mu*mu;
    const float rstd = rsqrtf(var + 1e-6f);
    for (int i = tid; i < HH; i += 256){
        float xn = (xs[i] - mu) * rstd * lns[i] + lnb[i];
        g_xmodh[(size_t)l*HH + i] = __float2half((1.f + g_mod[HH+i]) * xn + g_mod[i]);
    }
}

// ---------------- fp16 mma.sync GEMM, B in [K][N] via trans ldmatrix ------
// CTA 256x128, warp 64x64 (8 warps = 4m x 2n), K-chunk 64.
// smem/stage: A [256][64h] rows stride 144B at 0; B [64][128h] rows 272B at 36864.
// epi 1: n<QKVN -> g_h3 fp32 ; else gelu -> g_cath half (GEMM1)
// epi 2: Cf = xres + gate*(acc+bias)                     (GEMM2)
#define MG_ARB   144
#define MG_BRB   272
#define MG_BOFF  (256*MG_ARB)                 // 36864
#define MG_STAGE (MG_BOFF + 64*MG_BRB)        // 54272
#define MG_SMEM  (2*MG_STAGE)                 // 108544

__global__ __launch_bounds__(256, 1)
void mma_gemm_f16(const __half* __restrict__ A, const __half* __restrict__ B,
                  const float* __restrict__ bias, float* __restrict__ Cf,
                  int N, int K, int NIT,
                  const float* __restrict__ xres, const float* __restrict__ gate,
                  int epi)
{
    extern __shared__ char smc[];
    const uint32_t smb = smem_u32(smc);
    const int tid  = threadIdx.x;
    const int wid  = tid >> 5;
    const int lane = tid & 31;
    const int g    = lane >> 2;
    const int tig  = lane & 3;
    const int m0 = blockIdx.x * 256;
    const int n0 = blockIdx.y * 128;
    const int m0w = (wid & 3) * 64;
    const int n0w = (wid >> 2) * 64;

    const char* gp[12];
    uint32_t sof[12];
    size_t gstep[12];
    #pragma unroll
    for (int i = 0; i < 12; i++){
        int idx = i*256 + tid;
        if (idx < 2048){                       // A: 256 rows x 8 segs
            int row = idx >> 3, seg = idx & 7;
            gp[i]   = (const char*)(A + (size_t)(m0 + row)*K) + seg*16;
            sof[i]  = (uint32_t)(row*MG_ARB + seg*16);
            gstep[i] = 128;                    // 64 halves per chunk
        } else {                               // B: 64 rows x 16 segs
            int t = idx - 2048;
            int row = t >> 4, seg = t & 15;
            gp[i]   = (const char*)(B + (size_t)row*N + n0) + seg*16;
            sof[i]  = (uint32_t)(MG_BOFF + row*MG_BRB + seg*16);
            gstep[i] = (size_t)64*N*2;
        }
    }

#define MG_LOAD(IT, ST) do { \
        const uint32_t _sb = smb + (uint32_t)(ST)*MG_STAGE; \
        _Pragma("unroll") \
        for (int _i = 0; _i < 12; _i++){ \
            asm volatile("cp.async.cg.shared.global [%0], [%1], 16;" \
                :: "r"(_sb + sof[_i]), "l"(gp[_i] + (size_t)(IT)*gstep[_i]) : "memory"); \
        } \
        asm volatile("cp.async.commit_group;" ::: "memory"); \
    } while(0)

    float c[4][8][4];
    #pragma unroll
    for (int mt = 0; mt < 4; mt++)
        #pragma unroll
        for (int nt = 0; nt < 8; nt++)
            #pragma unroll
            for (int q = 0; q < 4; q++) c[mt][nt][q] = 0.f;

    const uint32_t aoff = (uint32_t)((lane & 15)*MG_ARB + ((lane >> 4) & 1)*16);
    const uint32_t boff = (uint32_t)(MG_BOFF + (lane & 15)*MG_BRB + n0w*2);

    MG_LOAD(0, 0);

    for (int it = 0; it < NIT; ++it){
        const int st = it & 1;
        if (it + 1 < NIT){
            MG_LOAD(it + 1, st ^ 1);
            asm volatile("cp.async.wait_group 1;" ::: "memory");
        } else {
            asm volatile("cp.async.wait_group 0;" ::: "memory");
        }
        __syncthreads();

        const uint32_t sb = smb + (uint32_t)st*MG_STAGE;
        #pragma unroll
        for (int k16 = 0; k16 < 4; k16++){
            uint32_t a[4][4];
            #pragma unroll
            for (int mt = 0; mt < 4; mt++)
                ldsm_x4(a[mt], sb + (uint32_t)((m0w + mt*16)*MG_ARB) + aoff + k16*32);
            uint32_t b[8][2];
            #pragma unroll
            for (int nt = 0; nt < 8; nt++)
                ldsm_x2t(b[nt], sb + boff + (uint32_t)(k16*16*MG_BRB) + nt*16);
            #pragma unroll
            for (int mt = 0; mt < 4; mt++)
                #pragma unroll
                for (int nt = 0; nt < 8; nt++)
                    mma_f16(c[mt][nt], a[mt], b[nt]);
        }
        __syncthreads();
    }

    if (epi == 1 && n0 >= QKVN){
        // GELU -> half into g_cath[:, HH + (n-QKVN)]
        const int nc0 = HH + (n0 - QKVN);
        #pragma unroll
        for (int mt = 0; mt < 4; mt++){
            const int m = m0 + m0w + mt*16 + g;
            #pragma unroll
            for (int nt = 0; nt < 8; nt++){
                const int nl = n0w + nt*8 + 2*tig;
                const int n  = n0 + nl;
                const float b0 = __ldg(bias + n), b1 = __ldg(bias + n + 1);
                float v0 = gelu_f(c[mt][nt][0] + b0);
                float v1 = gelu_f(c[mt][nt][1] + b1);
                float v2 = gelu_f(c[mt][nt][2] + b0);
                float v3 = gelu_f(c[mt][nt][3] + b1);
                *(uint32_t*)(g_cath + (size_t)m*CATN + nc0 + nl)
                    = h2_u32(__floats2half2_rn(v0, v1));
                *(uint32_t*)(g_cath + (size_t)(m+8)*CATN + nc0 + nl)
                    = h2_u32(__floats2half2_rn(v2, v3));
            }
        }
    } else if (epi == 1){
        // qkv fp32 into g_h3 [LL][QKVN]
        #pragma unroll
        for (int mt = 0; mt < 4; mt++){
            const int m = m0 + m0w + mt*16 + g;
            #pragma unroll
            for (int nt = 0; nt < 8; nt++){
                const int n = n0 + n0w + nt*8 + 2*tig;
                const float b0 = __ldg(bias + n), b1 = __ldg(bias + n + 1);
                *(float2*)(g_h3 + (size_t)m*QKVN + n)
                    = make_float2(c[mt][nt][0] + b0, c[mt][nt][1] + b1);
                *(float2*)(g_h3 + (size_t)(m+8)*QKVN + n)
                    = make_float2(c[mt][nt][2] + b0, c[mt][nt][3] + b1);
            }
        }
    } else {
        #pragma unroll
        for (int mt = 0; mt < 4; mt++){
            const int m = m0 + m0w + mt*16 + g;
            #pragma unroll
            for (int nt = 0; nt < 8; nt++){
                const int n = n0 + n0w + nt*8 + 2*tig;
                const float b0 = __ldg(bias + n), b1 = __ldg(bias + n + 1);
                const float g0 = __ldg(gate + n), g1 = __ldg(gate + n + 1);
                float v0 = xres[(size_t)m*N + n]       + g0*(c[mt][nt][0] + b0);
                float v1 = xres[(size_t)m*N + n + 1]   + g1*(c[mt][nt][1] + b1);
                float v2 = xres[(size_t)(m+8)*N + n]   + g0*(c[mt][nt][2] + b0);
                float v3 = xres[(size_t)(m+8)*N + n+1] + g1*(c[mt][nt][3] + b1);
                *(float2*)(Cf + (size_t)m*N + n)     = make_float2(v0, v1);
                *(float2*)(Cf + (size_t)(m+8)*N + n) = make_float2(v2, v3);
            }
        }
    }
}

// ---------------- qkv split + RMSNorm + RoPE -> half ----------------------
__global__ void qkv_post(const float* __restrict__ pe,
                         const float* __restrict__ qsc,
                         const float* __restrict__ ksc){
    const int l  = blockIdx.x;
    const int nh = blockIdx.y;
    const int d2 = threadIdx.x;
    const float* hp = g_h3 + (size_t)l*QKVN + nh*DD;
    float qe = hp[2*d2],        qo = hp[2*d2+1];
    float ke = hp[HH + 2*d2],   ko = hp[HH + 2*d2+1];
    float ve = hp[2*HH + 2*d2], vo = hp[2*HH + 2*d2+1];

    float sq = qe*qe + qo*qo;
    float sk = ke*ke + ko*ko;
    #pragma unroll
    for (int w = 1; w < 32; w <<= 1){
        sq += __shfl_xor_sync(0xffffffffu, sq, w);
        sk += __shfl_xor_sync(0xffffffffu, sk, w);
    }
    __shared__ float red[4];
    int wid = d2 >> 5;
    if ((d2 & 31) == 0){ red[wid*2] = sq; red[wid*2+1] = sk; }
    __syncthreads();
    sq = red[0] + red[2];
    sk = red[1] + red[3];
    const float rq = rsqrtf(sq * (1.f/128.f) + 1e-6f);
    const float rk = rsqrtf(sk * (1.f/128.f) + 1e-6f);
    qe *= rq * qsc[2*d2]; qo *= rq * qsc[2*d2+1];
    ke *= rk * ksc[2*d2]; ko *= rk * ksc[2*d2+1];
    const float4 r = *(const float4*)(pe + ((size_t)l*64 + d2)*4);
    const float qscale = 0.08838834764831845f;
    float qe2 = (r.x*qe + r.y*qo) * qscale;
    float qo2 = (r.z*qe + r.w*qo) * qscale;
    float ke2 = r.x*ke + r.y*ko;
    float ko2 = r.z*ke + r.w*ko;
    size_t o = ((size_t)nh*LL + l)*DD + 2*d2;
    g_qh[o] = __float2half(qe2); g_qh[o+1] = __float2half(qo2);
    g_kh[o] = __float2half(ke2); g_kh[o+1] = __float2half(ko2);
    g_vh[o] = __float2half(ve);  g_vh[o+1] = __float2half(vo);
}

// ---------------- flash attention, fp16 mma + cp.async double buffer ------
#define AQ_RB 272
#define AP_RB 144
#define AKV0  (128*AQ_RB)                    // 34816
#define AKV_STAGE (64*AQ_RB*2)               // K+V = 34816
#define AV_IN 17408                          // V offset within stage
#define AP_OFF (AKV0 + 2*AKV_STAGE)          // 104448
#define ATF_SMEM (AP_OFF + 128*AP_RB)        // 122880

__global__ __launch_bounds__(256, 1)
void attn_f16(){
    extern __shared__ char smc[];
    const uint32_t smb = smem_u32(smc);
    const int tid  = threadIdx.x;
    const int wid  = tid >> 5;
    const int lane = tid & 31;
    const int g    = lane >> 2;
    const int tig  = lane & 3;
    const int nh = blockIdx.y;
    const int q0 = blockIdx.x * 128;
    const __half* Qh = g_qh + (size_t)nh*LL*DD;
    const __half* Kh = g_kh + (size_t)nh*LL*DD;
    const __half* Vh = g_vh + (size_t)nh*LL*DD;

    // K/V loader: 2048 segs (1024 K + 1024 V), 8 per thread
    const char* gpa[8];
    uint32_t sofa[8];
    #pragma unroll
    for (int i = 0; i < 8; i++){
        int idx = i*256 + tid;
        int t = idx & 1023;
        int r = t >> 4, seg = t & 15;
        if (idx < 1024){
            gpa[i]  = (const char*)(Kh + (size_t)r*DD) + seg*16;
            sofa[i] = (uint32_t)(r*AQ_RB + seg*16);
        } else {
            gpa[i]  = (const char*)(Vh + (size_t)r*DD) + seg*16;
            sofa[i] = (uint32_t)(AV_IN + r*AQ_RB + seg*16);
        }
    }

#define ATT_LOAD(IT, ST) do { \
        const uint32_t _sb = smb + AKV0 + (uint32_t)(ST)*AKV_STAGE; \
        _Pragma("unroll") \
        for (int _i = 0; _i < 8; _i++){ \
            asm volatile("cp.async.cg.shared.global [%0], [%1], 16;" \
                :: "r"(_sb + sofa[_i]), "l"(gpa[_i] + (size_t)(IT)*16384) : "memory"); \
        } \
        asm volatile("cp.async.commit_group;" ::: "memory"); \
    } while(0)

    ATT_LOAD(0, 0);

    // Q tile (128 x 128 half)
    #pragma unroll
    for (int i = 0; i < 8; i++){
        int idx = i*256 + tid;
        int r = idx >> 4, s = idx & 15;
        uint4 v = *(const uint4*)((const char*)(Qh + (size_t)(q0+r)*DD) + s*16);
        *(uint4*)(smc + r*AQ_RB + s*16) = v;
    }

    float o[16][4];
    #pragma unroll
    for (int nt = 0; nt < 16; nt++)
        #pragma unroll
        for (int q = 0; q < 4; q++) o[nt][q] = 0.f;
    float m0 = -1e30f, m1 = -1e30f, l0 = 0.f, l1 = 0.f;

    const uint32_t aoffQ = smb + (uint32_t)((wid*16 + (lane & 15))*AQ_RB + ((lane >> 4) & 1)*16);
    const uint32_t aoffP = smb + AP_OFF + (uint32_t)((wid*16 + (lane & 15))*AP_RB + ((lane >> 4) & 1)*16);
    char* Pw = smc + AP_OFF + wid*16*AP_RB;

    for (int kt = 0; kt < LL/64; kt++){
        const int st = kt & 1;
        if (kt + 1 < LL/64){
            ATT_LOAD(kt + 1, st ^ 1);
            asm volatile("cp.async.wait_group 1;" ::: "memory");
        } else {
            asm volatile("cp.async.wait_group 0;" ::: "memory");
        }
        __syncthreads();

        const uint32_t kvb = smb + AKV0 + (uint32_t)st*AKV_STAGE;
        const uint32_t boffK = kvb + (uint32_t)((lane & 7)*AQ_RB + ((lane >> 3) & 1)*16);
        const uint32_t boffV = kvb + AV_IN + (uint32_t)((lane & 15)*AQ_RB);

        float s[8][4];
        #pragma unroll
        for (int nt = 0; nt < 8; nt++)
            #pragma unroll
            for (int q = 0; q < 4; q++) s[nt][q] = 0.f;
        #pragma unroll
        for (int k16 = 0; k16 < 8; k16++){
            uint32_t a[4];
            ldsm_x4(a, aoffQ + k16*32);
            #pragma unroll
            for (int nt = 0; nt < 8; nt++){
                uint32_t b[2];
                ldsm_x2(b, boffK + (uint32_t)(nt*8*AQ_RB) + k16*32);
                mma_f16(s[nt], a, b);
            }
        }

        float mx0 = -1e30f, mx1 = -1e30f;
        #pragma unroll
        for (int nt = 0; nt < 8; nt++){
            mx0 = fmaxf(mx0, fmaxf(s[nt][0], s[nt][1]));
            mx1 = fmaxf(mx1, fmaxf(s[nt][2], s[nt][3]));
        }
        mx0 = fmaxf(mx0, __shfl_xor_sync(0xffffffffu, mx0, 1));
        mx0 = fmaxf(mx0, __shfl_xor_sync(0xffffffffu, mx0, 2));
        mx1 = fmaxf(mx1, __shfl_xor_sync(0xffffffffu, mx1, 1));
        mx1 = fmaxf(mx1, __shfl_xor_sync(0xffffffffu, mx1, 2));
        const float mn0 = fmaxf(m0, mx0), mn1 = fmaxf(m1, mx1);
        const float al0 = __expf(m0 - mn0), al1 = __expf(m1 - mn1);
        m0 = mn0; m1 = mn1;
        float rs0 = 0.f, rs1 = 0.f;
        #pragma unroll
        for (int nt = 0; nt < 8; nt++){
            float p0 = __expf(s[nt][0] - mn0);
            float p1 = __expf(s[nt][1] - mn0);
            float p2 = __expf(s[nt][2] - mn1);
            float p3 = __expf(s[nt][3] - mn1);
            rs0 += p0 + p1; rs1 += p2 + p3;
            *(uint32_t*)(Pw +  g   *AP_RB + (nt*8 + 2*tig)*2)
                = h2_u32(__floats2half2_rn(p0, p1));
            *(uint32_t*)(Pw + (g+8)*AP_RB + (nt*8 + 2*tig)*2)
                = h2_u32(__floats2half2_rn(p2, p3));
        }
        rs0 += __shfl_xor_sync(0xffffffffu, rs0, 1);
        rs0 += __shfl_xor_sync(0xffffffffu, rs0, 2);
        rs1 += __shfl_xor_sync(0xffffffffu, rs1, 1);
        rs1 += __shfl_xor_sync(0xffffffffu, rs1, 2);
        l0 = l0*al0 + rs0;
        l1 = l1*al1 + rs1;
        #pragma unroll
        for (int nt = 0; nt < 16; nt++){
            o[nt][0] *= al0; o[nt][1] *= al0;
            o[nt][2] *= al1; o[nt][3] *= al1;
        }
        __syncwarp();

        #pragma unroll
        for (int k16 = 0; k16 < 4; k16++){
            uint32_t a[4];
            ldsm_x4(a, aoffP + k16*32);
            #pragma unroll
            for (int nt = 0; nt < 16; nt++){
                uint32_t b[2];
                ldsm_x2t(b, boffV + (uint32_t)(k16*16*AQ_RB) + nt*16);
                mma_f16(o[nt], a, b);
            }
        }
        __syncthreads();
    }

    const float rl0 = 1.0f / l0, rl1 = 1.0f / l1;
    const int r0 = q0 + wid*16 + g, r1 = r0 + 8;
    #pragma unroll
    for (int nt = 0; nt < 16; nt++){
        const int col = nh*DD + nt*8 + 2*tig;
        *(uint32_t*)(g_cath + (size_t)r0*CATN + col)
            = h2_u32(__floats2half2_rn(o[nt][0]*rl0, o[nt][1]*rl0));
        *(uint32_t*)(g_cath + (size_t)r1*CATN + col)
            = h2_u32(__floats2half2_rn(o[nt][2]*rl1, o[nt][3]*rl1));
    }
}

// ---------------- launch --------------------------------------------------
extern "C" void kernel_launch(void* const* d_in, const int* in_sizes, int n_in,
                              void* d_out, int out_size){
    (void)in_sizes; (void)n_in; (void)out_size;
    const float* x       = (const float*)d_in[0];
    const float* vec     = (const float*)d_in[1];
    const float* pe      = (const float*)d_in[2];
    const float* mod_w   = (const float*)d_in[3];
    const float* mod_b   = (const float*)d_in[4];
    const float* ln_s    = (const float*)d_in[5];
    const float* ln_b    = (const float*)d_in[6];
    const float* w1      = (const float*)d_in[7];
    const float* b1      = (const float*)d_in[8];
    const float* q_scale = (const float*)d_in[9];
    const float* k_scale = (const float*)d_in[10];
    const float* w2      = (const float*)d_in[11];
    const float* b2      = (const float*)d_in[12];
    float* out = (float*)d_out;

    float *p_mod;
    __half *p_xmodh, *p_cath, *p_w1h, *p_w2h;
    cudaGetSymbolAddress((void**)&p_xmodh, g_xmodh);
    cudaGetSymbolAddress((void**)&p_cath,  g_cath);
    cudaGetSymbolAddress((void**)&p_mod,   g_mod);
    cudaGetSymbolAddress((void**)&p_w1h,   g_w1h);
    cudaGetSymbolAddress((void**)&p_w2h,   g_w2h);

    cudaFuncSetAttribute(attn_f16, cudaFuncAttributeMaxDynamicSharedMemorySize, ATF_SMEM);
    cudaFuncSetAttribute(mma_gemm_f16, cudaFuncAttributeMaxDynamicSharedMemorySize, MG_SMEM);

    const int n4w1 = (int)((size_t)HH*W1N/4);
    const int n4w2 = (int)((size_t)CATN*HH/4);
    conv_f16<<<(n4w1+255)/256, 256>>>((const float4*)w1, (uint2*)p_w1h, n4w1);
    conv_f16<<<(n4w2+255)/256, 256>>>((const float4*)w2, (uint2*)p_w2h, n4w2);
    silu_init<<<QKVN/256, 256>>>(vec, mod_b);
    mod_gemv<<<dim3(QKVN/256, HH/256), 256>>>(mod_w);
    ln_mod  <<<LL, 256>>>(x, ln_s, ln_b);
    mma_gemm_f16<<<dim3(LL/256, W1N/128), 256, MG_SMEM>>>(p_xmodh, p_w1h, b1, nullptr,
                                                          W1N, HH, HH/64,
                                                          nullptr, nullptr, 1);
    qkv_post<<<dim3(LL, NHH), 64>>>(pe, q_scale, k_scale);
    attn_f16<<<dim3(LL/128, NHH), 256, ATF_SMEM>>>();
    mma_gemm_f16<<<dim3(LL/256, HH/128), 256, MG_SMEM>>>(p_cath, p_w2h, b2, out,
                                                         HH, CATN, CATN/64,
                                                         x, p_mod + 2*HH, 2);
}

// round 9
// speedup vs baseline: 5.7984x; 1.0738x over previous
#include <cuda_runtime.h>
#include <cuda_fp16.h>
#include <cstdint>
#include <cstring>

#define LL   2048
#define HH   3072
#define NHH  24
#define DD   128
#define MLPD 12288
#define W1N  21504
#define CATN 15360
#define QKVN 9216

__device__ __forceinline__ uint32_t h2_u32(__half2 h){
    uint32_t u; memcpy(&u, &h, 4); return u;
}
__device__ __forceinline__ uint32_t smem_u32(const void* p){
    uint32_t a; asm("{ .reg .u64 t; cvta.to.shared.u64 t, %1; cvt.u32.u64 %0, t; }" : "=r"(a) : "l"(p));
    return a;
}
__device__ __forceinline__ float ex2f(float x){
    float r; asm("ex2.approx.f32 %0, %1;" : "=f"(r) : "f"(x)); return r;
}
__device__ __forceinline__ float gelu_f(float v){
    float c = 0.7978845608028654f * (v + 0.044715f*v*v*v);
    return 0.5f*v*(1.f + tanhf(c));
}
__device__ __forceinline__ void mma_f16(float* c, const uint32_t* a, const uint32_t* b){
    asm volatile("mma.sync.aligned.m16n8k16.row.col.f32.f16.f16.f32 "
        "{%0,%1,%2,%3}, {%4,%5,%6,%7}, {%8,%9}, {%0,%1,%2,%3};"
        : "+f"(c[0]), "+f"(c[1]), "+f"(c[2]), "+f"(c[3])
        : "r"(a[0]), "r"(a[1]), "r"(a[2]), "r"(a[3]), "r"(b[0]), "r"(b[1]));
}
__device__ __forceinline__ void ldsm_x4(uint32_t* r, uint32_t a){
    asm volatile("ldmatrix.sync.aligned.m8n8.x4.shared.b16 {%0,%1,%2,%3}, [%4];"
        : "=r"(r[0]), "=r"(r[1]), "=r"(r[2]), "=r"(r[3]) : "r"(a));
}
__device__ __forceinline__ void ldsm_x2(uint32_t* r, uint32_t a){
    asm volatile("ldmatrix.sync.aligned.m8n8.x2.shared.b16 {%0,%1}, [%2];"
        : "=r"(r[0]), "=r"(r[1]) : "r"(a));
}
__device__ __forceinline__ void ldsm_x2t(uint32_t* r, uint32_t a){
    asm volatile("ldmatrix.sync.aligned.m8n8.x2.trans.shared.b16 {%0,%1}, [%2];"
        : "=r"(r[0]), "=r"(r[1]) : "r"(a));
}

// ---------------- scratch ----------------
__device__ float  g_sv[HH];
__device__ float  g_mod[3*HH];
__device__ __half g_xmodh[(size_t)LL*HH];
__device__ float  g_h3[(size_t)LL*QKVN];
__device__ __half g_qh[(size_t)NHH*LL*DD];
__device__ __half g_kh[(size_t)NHH*LL*DD];
__device__ __half g_vh[(size_t)NHH*LL*DD];
__device__ __half g_cath[(size_t)LL*CATN];
__device__ __half g_w1h[(size_t)HH*W1N];
__device__ __half g_w2h[(size_t)CATN*HH];

// ---------------- fp32 -> fp16 convert ----------------
__global__ void conv_f16(const float4* __restrict__ in, uint2* __restrict__ out, int n4){
    int i = blockIdx.x*256 + threadIdx.x;
    if (i < n4){
        float4 v = in[i];
        __half2 a = __floats2half2_rn(v.x, v.y);
        __half2 b = __floats2half2_rn(v.z, v.w);
        uint2 o; memcpy(&o.x, &a, 4); memcpy(&o.y, &b, 4);
        out[i] = o;
    }
}

// ---------------- silu + mod init ----------------
__global__ void silu_init(const float* __restrict__ vec, const float* __restrict__ b){
    int i = blockIdx.x*256 + threadIdx.x;
    if (i < HH){
        float t = vec[i];
        g_sv[i] = t / (1.f + expf(-t));
    }
    if (i < QKVN) g_mod[i] = b[i];
}

// ---------------- K-split GEMV ----------------
__global__ __launch_bounds__(256) void mod_gemv(const float* __restrict__ W){
    const int j  = blockIdx.x*256 + threadIdx.x;
    const int k0 = blockIdx.y*256;
    __shared__ float svs[256];
    svs[threadIdx.x] = g_sv[k0 + threadIdx.x];
    __syncthreads();
    float acc = 0.f;
    #pragma unroll 8
    for (int i = 0; i < 256; i++)
        acc = fmaf(svs[i], W[(size_t)(k0+i)*QKVN + j], acc);
    atomicAdd(&g_mod[j], acc);
}

// ---------------- LayerNorm + modulate (half output, float4 path) ---------
__global__ __launch_bounds__(256) void ln_mod(const float* __restrict__ x,
                                              const float* __restrict__ lns,
                                              const float* __restrict__ lnb){
    const int l = blockIdx.x;
    const int tid = threadIdx.x;
    __shared__ float xs[HH];
    __shared__ float rsum[16];
    float s = 0.f, ss = 0.f;
    for (int i = tid*4; i < HH; i += 1024){
        float4 v = *(const float4*)(x + (size_t)l*HH + i);
        *(float4*)(xs + i) = v;
        s += v.x + v.y + v.z + v.w;
        ss = fmaf(v.x, v.x, ss); ss = fmaf(v.y, v.y, ss);
        ss = fmaf(v.z, v.z, ss); ss = fmaf(v.w, v.w, ss);
    }
    #pragma unroll
    for (int w = 1; w < 32; w <<= 1){
        s  += __shfl_xor_sync(0xffffffffu, s,  w);
        ss += __shfl_xor_sync(0xffffffffu, ss, w);
    }
    int wid = tid >> 5;
    if ((tid & 31) == 0){ rsum[wid] = s; rsum[wid + 8] = ss; }
    __syncthreads();
    s = 0.f; ss = 0.f;
    #pragma unroll
    for (int w = 0; w < 8; w++){ s += rsum[w]; ss += rsum[w + 8]; }
    const float mu   = s  * (1.f/(float)HH);
    const float var  = ss * (1.f/(float)HH) - mu*mu;
    const float rstd = rsqrtf(var + 1e-6f);
    for (int i = tid*4; i < HH; i += 1024){
        float4 v  = *(const float4*)(xs + i);
        float4 lv = *(const float4*)(lns + i);
        float4 bv = *(const float4*)(lnb + i);
        float4 sc = *(const float4*)(g_mod + HH + i);
        float4 sh = *(const float4*)(g_mod + i);
        float o0 = (1.f+sc.x)*((v.x-mu)*rstd*lv.x + bv.x) + sh.x;
        float o1 = (1.f+sc.y)*((v.y-mu)*rstd*lv.y + bv.y) + sh.y;
        float o2 = (1.f+sc.z)*((v.z-mu)*rstd*lv.z + bv.z) + sh.z;
        float o3 = (1.f+sc.w)*((v.w-mu)*rstd*lv.w + bv.w) + sh.w;
        uint2 o;
        __half2 ha = __floats2half2_rn(o0, o1);
        __half2 hb = __floats2half2_rn(o2, o3);
        memcpy(&o.x, &ha, 4); memcpy(&o.y, &hb, 4);
        *(uint2*)(g_xmodh + (size_t)l*HH + i) = o;
    }
}

// ---------------- GEMM1: 256x128 tile, 3-stage, dual epilogue --------------
#define MG_ARB   144
#define MG_BRB   272
#define MG_BOFF  (256*MG_ARB)
#define MG_STAGE (MG_BOFF + 64*MG_BRB)        // 54272
#define MG_SMEM  (3*MG_STAGE)                 // 162816

__global__ __launch_bounds__(256, 1)
void gemm1_f16(const __half* __restrict__ A, const __half* __restrict__ B,
               const float* __restrict__ bias, int N, int K, int NIT)
{
    extern __shared__ char smc[];
    const uint32_t smb = smem_u32(smc);
    const int tid  = threadIdx.x;
    const int wid  = tid >> 5;
    const int lane = tid & 31;
    const int g    = lane >> 2;
    const int tig  = lane & 3;
    const int m0 = blockIdx.x * 256;
    const int n0 = blockIdx.y * 128;
    const int m0w = (wid & 3) * 64;
    const int n0w = (wid >> 2) * 64;

    const char* gp[12];
    uint32_t sof[12];
    size_t gstep[12];
    #pragma unroll
    for (int i = 0; i < 12; i++){
        int idx = i*256 + tid;
        if (idx < 2048){
            int row = idx >> 3, seg = idx & 7;
            gp[i]   = (const char*)(A + (size_t)(m0 + row)*K) + seg*16;
            sof[i]  = (uint32_t)(row*MG_ARB + seg*16);
            gstep[i] = 128;
        } else {
            int t = idx - 2048;
            int row = t >> 4, seg = t & 15;
            gp[i]   = (const char*)(B + (size_t)row*N + n0) + seg*16;
            sof[i]  = (uint32_t)(MG_BOFF + row*MG_BRB + seg*16);
            gstep[i] = (size_t)64*N*2;
        }
    }

#define MG_LOAD(IT, ST) do { \
        const uint32_t _sb = smb + (uint32_t)(ST)*MG_STAGE; \
        _Pragma("unroll") \
        for (int _i = 0; _i < 12; _i++){ \
            asm volatile("cp.async.cg.shared.global [%0], [%1], 16;" \
                :: "r"(_sb + sof[_i]), "l"(gp[_i] + (size_t)(IT)*gstep[_i]) : "memory"); \
        } \
        asm volatile("cp.async.commit_group;" ::: "memory"); \
    } while(0)

    float c[4][8][4];
    #pragma unroll
    for (int mt = 0; mt < 4; mt++)
        #pragma unroll
        for (int nt = 0; nt < 8; nt++)
            #pragma unroll
            for (int q = 0; q < 4; q++) c[mt][nt][q] = 0.f;

    const uint32_t aoff = (uint32_t)((lane & 15)*MG_ARB + ((lane >> 4) & 1)*16);
    const uint32_t boff = (uint32_t)(MG_BOFF + (lane & 15)*MG_BRB + n0w*2);

    MG_LOAD(0, 0);
    MG_LOAD(1, 1);

    int s = 0, sl = 2;
    for (int it = 0; it < NIT; ++it){
        if (it == NIT-1) asm volatile("cp.async.wait_group 0;" ::: "memory");
        else             asm volatile("cp.async.wait_group 1;" ::: "memory");
        __syncthreads();
        if (it + 2 < NIT) MG_LOAD(it + 2, sl);

        const uint32_t sb = smb + (uint32_t)s*MG_STAGE;
        #pragma unroll
        for (int k16 = 0; k16 < 4; k16++){
            uint32_t a[4][4];
            #pragma unroll
            for (int mt = 0; mt < 4; mt++)
                ldsm_x4(a[mt], sb + (uint32_t)((m0w + mt*16)*MG_ARB) + aoff + k16*32);
            uint32_t b[8][2];
            #pragma unroll
            for (int nt = 0; nt < 8; nt++)
                ldsm_x2t(b[nt], sb + boff + (uint32_t)(k16*16*MG_BRB) + nt*16);
            #pragma unroll
            for (int mt = 0; mt < 4; mt++)
                #pragma unroll
                for (int nt = 0; nt < 8; nt++)
                    mma_f16(c[mt][nt], a[mt], b[nt]);
        }
        s  = (s  == 2) ? 0 : s  + 1;
        sl = (sl == 2) ? 0 : sl + 1;
    }

    if (n0 >= QKVN){
        const int nc0 = HH + (n0 - QKVN);
        #pragma unroll
        for (int mt = 0; mt < 4; mt++){
            const int m = m0 + m0w + mt*16 + g;
            #pragma unroll
            for (int nt = 0; nt < 8; nt++){
                const int nl = n0w + nt*8 + 2*tig;
                const int n  = n0 + nl;
                const float b0 = __ldg(bias + n), b1 = __ldg(bias + n + 1);
                float v0 = gelu_f(c[mt][nt][0] + b0);
                float v1 = gelu_f(c[mt][nt][1] + b1);
                float v2 = gelu_f(c[mt][nt][2] + b0);
                float v3 = gelu_f(c[mt][nt][3] + b1);
                *(uint32_t*)(g_cath + (size_t)m*CATN + nc0 + nl)
                    = h2_u32(__floats2half2_rn(v0, v1));
                *(uint32_t*)(g_cath + (size_t)(m+8)*CATN + nc0 + nl)
                    = h2_u32(__floats2half2_rn(v2, v3));
            }
        }
    } else {
        #pragma unroll
        for (int mt = 0; mt < 4; mt++){
            const int m = m0 + m0w + mt*16 + g;
            #pragma unroll
            for (int nt = 0; nt < 8; nt++){
                const int n = n0 + n0w + nt*8 + 2*tig;
                const float b0 = __ldg(bias + n), b1 = __ldg(bias + n + 1);
                *(float2*)(g_h3 + (size_t)m*QKVN + n)
                    = make_float2(c[mt][nt][0] + b0, c[mt][nt][1] + b1);
                *(float2*)(g_h3 + (size_t)(m+8)*QKVN + n)
                    = make_float2(c[mt][nt][2] + b0, c[mt][nt][3] + b1);
            }
        }
    }
}

// ---------------- GEMM2: 128x128 tile (grid 384), 3-stage, gated epilogue --
#define G2_BOFF  (128*MG_ARB)                 // 18432
#define G2_STAGE (G2_BOFF + 64*MG_BRB)        // 35840
#define G2_SMEM  (3*G2_STAGE)                 // 107520

__global__ __launch_bounds__(256, 1)
void gemm2_f16(const __half* __restrict__ A, const __half* __restrict__ B,
               const float* __restrict__ bias, float* __restrict__ Cf,
               int N, int K, int NIT,
               const float* __restrict__ xres, const float* __restrict__ gate)
{
    extern __shared__ char smc[];
    const uint32_t smb = smem_u32(smc);
    const int tid  = threadIdx.x;
    const int wid  = tid >> 5;
    const int lane = tid & 31;
    const int g    = lane >> 2;
    const int tig  = lane & 3;
    const int m0 = blockIdx.x * 128;
    const int n0 = blockIdx.y * 128;
    const int m0w = (wid & 3) * 32;
    const int n0w = (wid >> 2) * 64;

    const char* gp[8];
    uint32_t sof[8];
    size_t gstep[8];
    #pragma unroll
    for (int i = 0; i < 8; i++){
        int idx = i*256 + tid;
        if (idx < 1024){
            int row = idx >> 3, seg = idx & 7;
            gp[i]   = (const char*)(A + (size_t)(m0 + row)*K) + seg*16;
            sof[i]  = (uint32_t)(row*MG_ARB + seg*16);
            gstep[i] = 128;
        } else {
            int t = idx - 1024;
            int row = t >> 4, seg = t & 15;
            gp[i]   = (const char*)(B + (size_t)row*N + n0) + seg*16;
            sof[i]  = (uint32_t)(G2_BOFF + row*MG_BRB + seg*16);
            gstep[i] = (size_t)64*N*2;
        }
    }

#define G2_LOAD(IT, ST) do { \
        const uint32_t _sb = smb + (uint32_t)(ST)*G2_STAGE; \
        _Pragma("unroll") \
        for (int _i = 0; _i < 8; _i++){ \
            asm volatile("cp.async.cg.shared.global [%0], [%1], 16;" \
                :: "r"(_sb + sof[_i]), "l"(gp[_i] + (size_t)(IT)*gstep[_i]) : "memory"); \
        } \
        asm volatile("cp.async.commit_group;" ::: "memory"); \
    } while(0)

    float c[2][8][4];
    #pragma unroll
    for (int mt = 0; mt < 2; mt++)
        #pragma unroll
        for (int nt = 0; nt < 8; nt++)
            #pragma unroll
            for (int q = 0; q < 4; q++) c[mt][nt][q] = 0.f;

    const uint32_t aoff = (uint32_t)((lane & 15)*MG_ARB + ((lane >> 4) & 1)*16);
    const uint32_t boff = (uint32_t)(G2_BOFF + (lane & 15)*MG_BRB + n0w*2);

    G2_LOAD(0, 0);
    G2_LOAD(1, 1);

    int s = 0, sl = 2;
    for (int it = 0; it < NIT; ++it){
        if (it == NIT-1) asm volatile("cp.async.wait_group 0;" ::: "memory");
        else             asm volatile("cp.async.wait_group 1;" ::: "memory");
        __syncthreads();
        if (it + 2 < NIT) G2_LOAD(it + 2, sl);

        const uint32_t sb = smb + (uint32_t)s*G2_STAGE;
        #pragma unroll
        for (int k16 = 0; k16 < 4; k16++){
            uint32_t a[2][4];
            #pragma unroll
            for (int mt = 0; mt < 2; mt++)
                ldsm_x4(a[mt], sb + (uint32_t)((m0w + mt*16)*MG_ARB) + aoff + k16*32);
            uint32_t b[8][2];
            #pragma unroll
            for (int nt = 0; nt < 8; nt++)
                ldsm_x2t(b[nt], sb + boff + (uint32_t)(k16*16*MG_BRB) + nt*16);
            #pragma unroll
            for (int mt = 0; mt < 2; mt++)
                #pragma unroll
                for (int nt = 0; nt < 8; nt++)
                    mma_f16(c[mt][nt], a[mt], b[nt]);
        }
        s  = (s  == 2) ? 0 : s  + 1;
        sl = (sl == 2) ? 0 : sl + 1;
    }

    #pragma unroll
    for (int mt = 0; mt < 2; mt++){
        const int m = m0 + m0w + mt*16 + g;
        #pragma unroll
        for (int nt = 0; nt < 8; nt++){
            const int n = n0 + n0w + nt*8 + 2*tig;
            const float b0 = __ldg(bias + n), b1 = __ldg(bias + n + 1);
            const float g0 = __ldg(gate + n), g1 = __ldg(gate + n + 1);
            float v0 = xres[(size_t)m*N + n]       + g0*(c[mt][nt][0] + b0);
            float v1 = xres[(size_t)m*N + n + 1]   + g1*(c[mt][nt][1] + b1);
            float v2 = xres[(size_t)(m+8)*N + n]   + g0*(c[mt][nt][2] + b0);
            float v3 = xres[(size_t)(m+8)*N + n+1] + g1*(c[mt][nt][3] + b1);
            *(float2*)(Cf + (size_t)m*N + n)     = make_float2(v0, v1);
            *(float2*)(Cf + (size_t)(m+8)*N + n) = make_float2(v2, v3);
        }
    }
}

// ---------------- qkv split + RMSNorm + RoPE -> half (4 heads/block) ------
__global__ __launch_bounds__(256) void qkv_post(const float* __restrict__ pe,
                                                const float* __restrict__ qsc,
                                                const float* __restrict__ ksc){
    const int l  = blockIdx.x;
    const int tid = threadIdx.x;
    const int hs = tid >> 6;                  // 0..3
    const int d2 = tid & 63;
    const int nh = blockIdx.y*4 + hs;
    const float* hp = g_h3 + (size_t)l*QKVN + nh*DD;
    float qe = hp[2*d2],        qo = hp[2*d2+1];
    float ke = hp[HH + 2*d2],   ko = hp[HH + 2*d2+1];
    float ve = hp[2*HH + 2*d2], vo = hp[2*HH + 2*d2+1];

    float sq = qe*qe + qo*qo;
    float sk = ke*ke + ko*ko;
    #pragma unroll
    for (int w = 1; w < 32; w <<= 1){
        sq += __shfl_xor_sync(0xffffffffu, sq, w);
        sk += __shfl_xor_sync(0xffffffffu, sk, w);
    }
    __shared__ float red[8][2];
    int wid = tid >> 5;                        // 0..7, group = wid>>1
    if ((tid & 31) == 0){ red[wid][0] = sq; red[wid][1] = sk; }
    __syncthreads();
    const int gb = (wid >> 1) << 1;
    sq = red[gb][0] + red[gb+1][0];
    sk = red[gb][1] + red[gb+1][1];
    const float rq = rsqrtf(sq * (1.f/128.f) + 1e-6f);
    const float rk = rsqrtf(sk * (1.f/128.f) + 1e-6f);
    qe *= rq * qsc[2*d2]; qo *= rq * qsc[2*d2+1];
    ke *= rk * ksc[2*d2]; ko *= rk * ksc[2*d2+1];
    const float4 r = *(const float4*)(pe + ((size_t)l*64 + d2)*4);
    const float qscale = 0.08838834764831845f * 1.4426950408889634f; // /sqrt(D) * log2e
    float qe2 = (r.x*qe + r.y*qo) * qscale;
    float qo2 = (r.z*qe + r.w*qo) * qscale;
    float ke2 = r.x*ke + r.y*ko;
    float ko2 = r.z*ke + r.w*ko;
    size_t o = ((size_t)nh*LL + l)*DD + 2*d2;
    g_qh[o] = __float2half(qe2); g_qh[o+1] = __float2half(qo2);
    g_kh[o] = __float2half(ke2); g_kh[o+1] = __float2half(ko2);
    g_vh[o] = __float2half(ve);  g_vh[o+1] = __float2half(vo);
}

// ---------------- flash attention, fp16 mma + 3-stage cp.async ------------
#define AQ_RB 272
#define AP_RB 144
#define AKV0  (128*AQ_RB)                    // 34816
#define AKV_STAGE (64*AQ_RB*2)               // 34816
#define AV_IN 17408
#define AP_OFF (AKV0 + 3*AKV_STAGE)          // 139264
#define ATF_SMEM (AP_OFF + 128*AP_RB)        // 157696
#define NKT (LL/64)

__global__ __launch_bounds__(256, 1)
void attn_f16(){
    extern __shared__ char smc[];
    const uint32_t smb = smem_u32(smc);
    const int tid  = threadIdx.x;
    const int wid  = tid >> 5;
    const int lane = tid & 31;
    const int g    = lane >> 2;
    const int tig  = lane & 3;
    const int nh = blockIdx.y;
    const int q0 = blockIdx.x * 128;
    const __half* Qh = g_qh + (size_t)nh*LL*DD;
    const __half* Kh = g_kh + (size_t)nh*LL*DD;
    const __half* Vh = g_vh + (size_t)nh*LL*DD;

    const char* gpa[8];
    uint32_t sofa[8];
    #pragma unroll
    for (int i = 0; i < 8; i++){
        int idx = i*256 + tid;
        int t = idx & 1023;
        int r = t >> 4, seg = t & 15;
        if (idx < 1024){
            gpa[i]  = (const char*)(Kh + (size_t)r*DD) + seg*16;
            sofa[i] = (uint32_t)(r*AQ_RB + seg*16);
        } else {
            gpa[i]  = (const char*)(Vh + (size_t)r*DD) + seg*16;
            sofa[i] = (uint32_t)(AV_IN + r*AQ_RB + seg*16);
        }
    }

#define ATT_LOAD(IT, ST) do { \
        const uint32_t _sb = smb + AKV0 + (uint32_t)(ST)*AKV_STAGE; \
        _Pragma("unroll") \
        for (int _i = 0; _i < 8; _i++){ \
            asm volatile("cp.async.cg.shared.global [%0], [%1], 16;" \
                :: "r"(_sb + sofa[_i]), "l"(gpa[_i] + (size_t)(IT)*16384) : "memory"); \
        } \
        asm volatile("cp.async.commit_group;" ::: "memory"); \
    } while(0)

    ATT_LOAD(0, 0);
    ATT_LOAD(1, 1);

    #pragma unroll
    for (int i = 0; i < 8; i++){
        int idx = i*256 + tid;
        int r = idx >> 4, s = idx & 15;
        uint4 v = *(const uint4*)((const char*)(Qh + (size_t)(q0+r)*DD) + s*16);
        *(uint4*)(smc + r*AQ_RB + s*16) = v;
    }

    float o[16][4];
    #pragma unroll
    for (int nt = 0; nt < 16; nt++)
        #pragma unroll
        for (int q = 0; q < 4; q++) o[nt][q] = 0.f;
    float m0 = -1e30f, m1 = -1e30f, l0 = 0.f, l1 = 0.f;

    const uint32_t aoffQ = smb + (uint32_t)((wid*16 + (lane & 15))*AQ_RB + ((lane >> 4) & 1)*16);
    const uint32_t aoffP = smb + AP_OFF + (uint32_t)((wid*16 + (lane & 15))*AP_RB + ((lane >> 4) & 1)*16);
    char* Pw = smc + AP_OFF + wid*16*AP_RB;

    int st = 0, sl = 2;
    for (int kt = 0; kt < NKT; kt++){
        if (kt == NKT-1) asm volatile("cp.async.wait_group 0;" ::: "memory");
        else             asm volatile("cp.async.wait_group 1;" ::: "memory");
        __syncthreads();
        if (kt + 2 < NKT) ATT_LOAD(kt + 2, sl);

        const uint32_t kvb = smb + AKV0 + (uint32_t)st*AKV_STAGE;
        const uint32_t boffK = kvb + (uint32_t)((lane & 7)*AQ_RB + ((lane >> 3) & 1)*16);
        const uint32_t boffV = kvb + AV_IN + (uint32_t)((lane & 15)*AQ_RB);

        float s[8][4];
        #pragma unroll
        for (int nt = 0; nt < 8; nt++)
            #pragma unroll
            for (int q = 0; q < 4; q++) s[nt][q] = 0.f;
        #pragma unroll
        for (int k16 = 0; k16 < 8; k16++){
            uint32_t a[4];
            ldsm_x4(a, aoffQ + k16*32);
            #pragma unroll
            for (int nt = 0; nt < 8; nt++){
                uint32_t b[2];
                ldsm_x2(b, boffK + (uint32_t)(nt*8*AQ_RB) + k16*32);
                mma_f16(s[nt], a, b);
            }
        }

        float mx0 = -1e30f, mx1 = -1e30f;
        #pragma unroll
        for (int nt = 0; nt < 8; nt++){
            mx0 = fmaxf(mx0, fmaxf(s[nt][0], s[nt][1]));
            mx1 = fmaxf(mx1, fmaxf(s[nt][2], s[nt][3]));
        }
        mx0 = fmaxf(mx0, __shfl_xor_sync(0xffffffffu, mx0, 1));
        mx0 = fmaxf(mx0, __shfl_xor_sync(0xffffffffu, mx0, 2));
        mx1 = fmaxf(mx1, __shfl_xor_sync(0xffffffffu, mx1, 1));
        mx1 = fmaxf(mx1, __shfl_xor_sync(0xffffffffu, mx1, 2));
        const float mn0 = fmaxf(m0, mx0), mn1 = fmaxf(m1, mx1);
        const float al0 = ex2f(m0 - mn0), al1 = ex2f(m1 - mn1);
        m0 = mn0; m1 = mn1;
        float rs0 = 0.f, rs1 = 0.f;
        #pragma unroll
        for (int nt = 0; nt < 8; nt++){
            float p0 = ex2f(s[nt][0] - mn0);
            float p1 = ex2f(s[nt][1] - mn0);
            float p2 = ex2f(s[nt][2] - mn1);
            float p3 = ex2f(s[nt][3] - mn1);
            rs0 += p0 + p1; rs1 += p2 + p3;
            *(uint32_t*)(Pw +  g   *AP_RB + (nt*8 + 2*tig)*2)
                = h2_u32(__floats2half2_rn(p0, p1));
            *(uint32_t*)(Pw + (g+8)*AP_RB + (nt*8 + 2*tig)*2)
                = h2_u32(__floats2half2_rn(p2, p3));
        }
        rs0 += __shfl_xor_sync(0xffffffffu, rs0, 1);
        rs0 += __shfl_xor_sync(0xffffffffu, rs0, 2);
        rs1 += __shfl_xor_sync(0xffffffffu, rs1, 1);
        rs1 += __shfl_xor_sync(0xffffffffu, rs1, 2);
        l0 = l0*al0 + rs0;
        l1 = l1*al1 + rs1;
        #pragma unroll
        for (int nt = 0; nt < 16; nt++){
            o[nt][0] *= al0; o[nt][1] *= al0;
            o[nt][2] *= al1; o[nt][3] *= al1;
        }
        __syncwarp();

        #pragma unroll
        for (int k16 = 0; k16 < 4; k16++){
            uint32_t a[4];
            ldsm_x4(a, aoffP + k16*32);
            #pragma unroll
            for (int nt = 0; nt < 16; nt++){
                uint32_t b[2];
                ldsm_x2t(b, boffV + (uint32_t)(k16*16*AQ_RB) + nt*16);
                mma_f16(o[nt], a, b);
            }
        }
        st = (st == 2) ? 0 : st + 1;
        sl = (sl == 2) ? 0 : sl + 1;
    }

    const float rl0 = 1.0f / l0, rl1 = 1.0f / l1;
    const int r0 = q0 + wid*16 + g, r1 = r0 + 8;
    #pragma unroll
    for (int nt = 0; nt < 16; nt++){
        const int col = nh*DD + nt*8 + 2*tig;
        *(uint32_t*)(g_cath + (size_t)r0*CATN + col)
            = h2_u32(__floats2half2_rn(o[nt][0]*rl0, o[nt][1]*rl0));
        *(uint32_t*)(g_cath + (size_t)r1*CATN + col)
            = h2_u32(__floats2half2_rn(o[nt][2]*rl1, o[nt][3]*rl1));
    }
}

// ---------------- launch --------------------------------------------------
extern "C" void kernel_launch(void* const* d_in, const int* in_sizes, int n_in,
                              void* d_out, int out_size){
    (void)in_sizes; (void)n_in; (void)out_size;
    const float* x       = (const float*)d_in[0];
    const float* vec     = (const float*)d_in[1];
    const float* pe      = (const float*)d_in[2];
    const float* mod_w   = (const float*)d_in[3];
    const float* mod_b   = (const float*)d_in[4];
    const float* ln_s    = (const float*)d_in[5];
    const float* ln_b    = (const float*)d_in[6];
    const float* w1      = (const float*)d_in[7];
    const float* b1      = (const float*)d_in[8];
    const float* q_scale = (const float*)d_in[9];
    const float* k_scale = (const float*)d_in[10];
    const float* w2      = (const float*)d_in[11];
    const float* b2      = (const float*)d_in[12];
    float* out = (float*)d_out;

    float *p_mod;
    __half *p_xmodh, *p_cath, *p_w1h, *p_w2h;
    cudaGetSymbolAddress((void**)&p_xmodh, g_xmodh);
    cudaGetSymbolAddress((void**)&p_cath,  g_cath);
    cudaGetSymbolAddress((void**)&p_mod,   g_mod);
    cudaGetSymbolAddress((void**)&p_w1h,   g_w1h);
    cudaGetSymbolAddress((void**)&p_w2h,   g_w2h);

    cudaFuncSetAttribute(attn_f16, cudaFuncAttributeMaxDynamicSharedMemorySize, ATF_SMEM);
    cudaFuncSetAttribute(gemm1_f16, cudaFuncAttributeMaxDynamicSharedMemorySize, MG_SMEM);
    cudaFuncSetAttribute(gemm2_f16, cudaFuncAttributeMaxDynamicSharedMemorySize, G2_SMEM);

    const int n4w1 = (int)((size_t)HH*W1N/4);
    const int n4w2 = (int)((size_t)CATN*HH/4);
    conv_f16<<<(n4w1+255)/256, 256>>>((const float4*)w1, (uint2*)p_w1h, n4w1);
    conv_f16<<<(n4w2+255)/256, 256>>>((const float4*)w2, (uint2*)p_w2h, n4w2);
    silu_init<<<QKVN/256, 256>>>(vec, mod_b);
    mod_gemv<<<dim3(QKVN/256, HH/256), 256>>>(mod_w);
    ln_mod  <<<LL, 256>>>(x, ln_s, ln_b);
    gemm1_f16<<<dim3(LL/256, W1N/128), 256, MG_SMEM>>>(p_xmodh, p_w1h, b1,
                                                       W1N, HH, HH/64);
    qkv_post<<<dim3(LL, NHH/4), 256>>>(pe, q_scale, k_scale);
    attn_f16<<<dim3(LL/128, NHH), 256, ATF_SMEM>>>();
    gemm2_f16<<<dim3(LL/128, HH/128), 256, G2_SMEM>>>(p_cath, p_w2h, b2, out,
                                                      HH, CATN, CATN/64,
                                                      x, p_mod + 2*HH);
}

// round 10
// speedup vs baseline: 6.4074x; 1.1050x over previous
#include <cuda_runtime.h>
#include <cuda_fp16.h>
#include <cstdint>
#include <cstring>

#define LL   2048
#define HH   3072
#define NHH  24
#define DD   128
#define MLPD 12288
#define W1N  21504
#define CATN 15360
#define QKVN 9216

__device__ __forceinline__ uint32_t h2_u32(__half2 h){
    uint32_t u; memcpy(&u, &h, 4); return u;
}
__device__ __forceinline__ uint32_t smem_u32(const void* p){
    uint32_t a; asm("{ .reg .u64 t; cvta.to.shared.u64 t, %1; cvt.u32.u64 %0, t; }" : "=r"(a) : "l"(p));
    return a;
}
__device__ __forceinline__ float ex2f(float x){
    float r; asm("ex2.approx.f32 %0, %1;" : "=f"(r) : "f"(x)); return r;
}
__device__ __forceinline__ float gelu_f(float v){
    float c = 0.7978845608028654f * (v + 0.044715f*v*v*v);
    return 0.5f*v*(1.f + tanhf(c));
}
__device__ __forceinline__ void mma_f16(float* c, const uint32_t* a, const uint32_t* b){
    asm volatile("mma.sync.aligned.m16n8k16.row.col.f32.f16.f16.f32 "
        "{%0,%1,%2,%3}, {%4,%5,%6,%7}, {%8,%9}, {%0,%1,%2,%3};"
        : "+f"(c[0]), "+f"(c[1]), "+f"(c[2]), "+f"(c[3])
        : "r"(a[0]), "r"(a[1]), "r"(a[2]), "r"(a[3]), "r"(b[0]), "r"(b[1]));
}
__device__ __forceinline__ void ldsm_x4(uint32_t* r, uint32_t a){
    asm volatile("ldmatrix.sync.aligned.m8n8.x4.shared.b16 {%0,%1,%2,%3}, [%4];"
        : "=r"(r[0]), "=r"(r[1]), "=r"(r[2]), "=r"(r[3]) : "r"(a));
}
__device__ __forceinline__ void ldsm_x4t(uint32_t* r, uint32_t a){
    asm volatile("ldmatrix.sync.aligned.m8n8.x4.trans.shared.b16 {%0,%1,%2,%3}, [%4];"
        : "=r"(r[0]), "=r"(r[1]), "=r"(r[2]), "=r"(r[3]) : "r"(a));
}

// ---------------- scratch ----------------
__device__ float  g_sv[HH];
__device__ float  g_mod[3*HH];
__device__ __half g_xmodh[(size_t)LL*HH];
__device__ float  g_h3[(size_t)LL*QKVN];
__device__ __half g_qh[(size_t)NHH*LL*DD];
__device__ __half g_kh[(size_t)NHH*LL*DD];
__device__ __half g_vh[(size_t)NHH*LL*DD];
__device__ __half g_cath[(size_t)LL*CATN];
__device__ __half g_w1h[(size_t)HH*W1N];
__device__ __half g_w2h[(size_t)CATN*HH];

// ---------------- fp32 -> fp16 convert ----------------
__global__ void conv_f16(const float4* __restrict__ in, uint2* __restrict__ out, int n4){
    int i = blockIdx.x*256 + threadIdx.x;
    if (i < n4){
        float4 v = in[i];
        __half2 a = __floats2half2_rn(v.x, v.y);
        __half2 b = __floats2half2_rn(v.z, v.w);
        uint2 o; memcpy(&o.x, &a, 4); memcpy(&o.y, &b, 4);
        out[i] = o;
    }
}

// ---------------- silu + mod init ----------------
__global__ void silu_init(const float* __restrict__ vec, const float* __restrict__ b){
    int i = blockIdx.x*256 + threadIdx.x;
    if (i < HH){
        float t = vec[i];
        g_sv[i] = t / (1.f + expf(-t));
    }
    if (i < QKVN) g_mod[i] = b[i];
}

// ---------------- K-split GEMV (float2 per thread) ----------------
__global__ __launch_bounds__(256) void mod_gemv(const float* __restrict__ W){
    const int j  = (blockIdx.x*256 + threadIdx.x)*2;
    const int k0 = blockIdx.y*256;
    __shared__ float svs[256];
    svs[threadIdx.x] = g_sv[k0 + threadIdx.x];
    __syncthreads();
    float a0 = 0.f, a1 = 0.f;
    #pragma unroll 8
    for (int i = 0; i < 256; i++){
        float2 w = *(const float2*)(W + (size_t)(k0+i)*QKVN + j);
        a0 = fmaf(svs[i], w.x, a0);
        a1 = fmaf(svs[i], w.y, a1);
    }
    atomicAdd(&g_mod[j],   a0);
    atomicAdd(&g_mod[j+1], a1);
}

// ---------------- LayerNorm + modulate (half output) ----------------------
__global__ __launch_bounds__(256) void ln_mod(const float* __restrict__ x,
                                              const float* __restrict__ lns,
                                              const float* __restrict__ lnb){
    const int l = blockIdx.x;
    const int tid = threadIdx.x;
    __shared__ float xs[HH];
    __shared__ float rsum[16];
    float s = 0.f, ss = 0.f;
    for (int i = tid*4; i < HH; i += 1024){
        float4 v = *(const float4*)(x + (size_t)l*HH + i);
        *(float4*)(xs + i) = v;
        s += v.x + v.y + v.z + v.w;
        ss = fmaf(v.x, v.x, ss); ss = fmaf(v.y, v.y, ss);
        ss = fmaf(v.z, v.z, ss); ss = fmaf(v.w, v.w, ss);
    }
    #pragma unroll
    for (int w = 1; w < 32; w <<= 1){
        s  += __shfl_xor_sync(0xffffffffu, s,  w);
        ss += __shfl_xor_sync(0xffffffffu, ss, w);
    }
    int wid = tid >> 5;
    if ((tid & 31) == 0){ rsum[wid] = s; rsum[wid + 8] = ss; }
    __syncthreads();
    s = 0.f; ss = 0.f;
    #pragma unroll
    for (int w = 0; w < 8; w++){ s += rsum[w]; ss += rsum[w + 8]; }
    const float mu   = s  * (1.f/(float)HH);
    const float var  = ss * (1.f/(float)HH) - mu*mu;
    const float rstd = rsqrtf(var + 1e-6f);
    for (int i = tid*4; i < HH; i += 1024){
        float4 v  = *(const float4*)(xs + i);
        float4 lv = *(const float4*)(lns + i);
        float4 bv = *(const float4*)(lnb + i);
        float4 sc = *(const float4*)(g_mod + HH + i);
        float4 sh = *(const float4*)(g_mod + i);
        float o0 = (1.f+sc.x)*((v.x-mu)*rstd*lv.x + bv.x) + sh.x;
        float o1 = (1.f+sc.y)*((v.y-mu)*rstd*lv.y + bv.y) + sh.y;
        float o2 = (1.f+sc.z)*((v.z-mu)*rstd*lv.z + bv.z) + sh.z;
        float o3 = (1.f+sc.w)*((v.w-mu)*rstd*lv.w + bv.w) + sh.w;
        uint2 o;
        __half2 ha = __floats2half2_rn(o0, o1);
        __half2 hb = __floats2half2_rn(o2, o3);
        memcpy(&o.x, &ha, 4); memcpy(&o.y, &hb, 4);
        *(uint2*)(g_xmodh + (size_t)l*HH + i) = o;
    }
}

// ---------------- GEMM1: 256x128 tile, 3-stage, dual epilogue --------------
#define MG_ARB   144
#define MG_BRB   272
#define MG_BOFF  (256*MG_ARB)
#define MG_STAGE (MG_BOFF + 64*MG_BRB)        // 54272
#define MG_SMEM  (3*MG_STAGE)                 // 162816

__global__ __launch_bounds__(256, 1)
void gemm1_f16(const __half* __restrict__ A, const __half* __restrict__ B,
               const float* __restrict__ bias, int N, int K, int NIT)
{
    extern __shared__ char smc[];
    const uint32_t smb = smem_u32(smc);
    const int tid  = threadIdx.x;
    const int wid  = tid >> 5;
    const int lane = tid & 31;
    const int g    = lane >> 2;
    const int tig  = lane & 3;
    const int m0 = blockIdx.x * 256;
    const int n0 = blockIdx.y * 128;
    const int m0w = (wid & 3) * 64;
    const int n0w = (wid >> 2) * 64;

    const char* gp[12];
    uint32_t sof[12];
    size_t gstep[12];
    #pragma unroll
    for (int i = 0; i < 12; i++){
        int idx = i*256 + tid;
        if (idx < 2048){
            int row = idx >> 3, seg = idx & 7;
            gp[i]   = (const char*)(A + (size_t)(m0 + row)*K) + seg*16;
            sof[i]  = (uint32_t)(row*MG_ARB + seg*16);
            gstep[i] = 128;
        } else {
            int t = idx - 2048;
            int row = t >> 4, seg = t & 15;
            gp[i]   = (const char*)(B + (size_t)row*N + n0) + seg*16;
            sof[i]  = (uint32_t)(MG_BOFF + row*MG_BRB + seg*16);
            gstep[i] = (size_t)64*N*2;
        }
    }

#define MG_LOAD(IT, ST) do { \
        const uint32_t _sb = smb + (uint32_t)(ST)*MG_STAGE; \
        _Pragma("unroll") \
        for (int _i = 0; _i < 12; _i++){ \
            asm volatile("cp.async.cg.shared.global [%0], [%1], 16;" \
                :: "r"(_sb + sof[_i]), "l"(gp[_i] + (size_t)(IT)*gstep[_i]) : "memory"); \
        } \
        asm volatile("cp.async.commit_group;" ::: "memory"); \
    } while(0)

    float c[4][8][4];
    #pragma unroll
    for (int mt = 0; mt < 4; mt++)
        #pragma unroll
        for (int nt = 0; nt < 8; nt++)
            #pragma unroll
            for (int q = 0; q < 4; q++) c[mt][nt][q] = 0.f;

    const uint32_t aoff  = (uint32_t)((lane & 15)*MG_ARB + ((lane >> 4) & 1)*16);
    const uint32_t boff4 = (uint32_t)(MG_BOFF + (lane & 15)*MG_BRB + ((lane >> 4) & 1)*16 + n0w*2);

    MG_LOAD(0, 0);
    MG_LOAD(1, 1);

    int s = 0, sl = 2;
    for (int it = 0; it < NIT; ++it){
        if (it == NIT-1) asm volatile("cp.async.wait_group 0;" ::: "memory");
        else             asm volatile("cp.async.wait_group 1;" ::: "memory");
        __syncthreads();
        if (it + 2 < NIT) MG_LOAD(it + 2, sl);

        const uint32_t sb = smb + (uint32_t)s*MG_STAGE;
        #pragma unroll
        for (int k16 = 0; k16 < 4; k16++){
            uint32_t a[4][4];
            #pragma unroll
            for (int mt = 0; mt < 4; mt++)
                ldsm_x4(a[mt], sb + (uint32_t)((m0w + mt*16)*MG_ARB) + aoff + k16*32);
            uint32_t b[8][2];
            #pragma unroll
            for (int u = 0; u < 4; u++)
                ldsm_x4t(&b[2*u][0], sb + boff4 + (uint32_t)(k16*16*MG_BRB) + u*32);
            #pragma unroll
            for (int mt = 0; mt < 4; mt++)
                #pragma unroll
                for (int nt = 0; nt < 8; nt++)
                    mma_f16(c[mt][nt], a[mt], b[nt]);
        }
        s  = (s  == 2) ? 0 : s  + 1;
        sl = (sl == 2) ? 0 : sl + 1;
    }

    if (n0 >= QKVN){
        const int nc0 = HH + (n0 - QKVN);
        #pragma unroll
        for (int mt = 0; mt < 4; mt++){
            const int m = m0 + m0w + mt*16 + g;
            #pragma unroll
            for (int nt = 0; nt < 8; nt++){
                const int nl = n0w + nt*8 + 2*tig;
                const int n  = n0 + nl;
                const float b0 = __ldg(bias + n), b1 = __ldg(bias + n + 1);
                float v0 = gelu_f(c[mt][nt][0] + b0);
                float v1 = gelu_f(c[mt][nt][1] + b1);
                float v2 = gelu_f(c[mt][nt][2] + b0);
                float v3 = gelu_f(c[mt][nt][3] + b1);
                *(uint32_t*)(g_cath + (size_t)m*CATN + nc0 + nl)
                    = h2_u32(__floats2half2_rn(v0, v1));
                *(uint32_t*)(g_cath + (size_t)(m+8)*CATN + nc0 + nl)
                    = h2_u32(__floats2half2_rn(v2, v3));
            }
        }
    } else {
        #pragma unroll
        for (int mt = 0; mt < 4; mt++){
            const int m = m0 + m0w + mt*16 + g;
            #pragma unroll
            for (int nt = 0; nt < 8; nt++){
                const int n = n0 + n0w + nt*8 + 2*tig;
                const float b0 = __ldg(bias + n), b1 = __ldg(bias + n + 1);
                *(float2*)(g_h3 + (size_t)m*QKVN + n)
                    = make_float2(c[mt][nt][0] + b0, c[mt][nt][1] + b1);
                *(float2*)(g_h3 + (size_t)(m+8)*QKVN + n)
                    = make_float2(c[mt][nt][2] + b0, c[mt][nt][3] + b1);
            }
        }
    }
}

// ---------------- GEMM2: 128x128 tile, 3-stage, occupancy 2 ----------------
#define G2_BOFF  (128*MG_ARB)                 // 18432
#define G2_STAGE (G2_BOFF + 64*MG_BRB)        // 35840
#define G2_SMEM  (3*G2_STAGE)                 // 107520

__global__ __launch_bounds__(256, 2)
void gemm2_f16(const __half* __restrict__ A, const __half* __restrict__ B,
               const float* __restrict__ bias, float* __restrict__ Cf,
               int N, int K, int NIT,
               const float* __restrict__ xres, const float* __restrict__ gate)
{
    extern __shared__ char smc[];
    const uint32_t smb = smem_u32(smc);
    const int tid  = threadIdx.x;
    const int wid  = tid >> 5;
    const int lane = tid & 31;
    const int g    = lane >> 2;
    const int tig  = lane & 3;
    const int m0 = blockIdx.x * 128;
    const int n0 = blockIdx.y * 128;
    const int m0w = (wid & 3) * 32;
    const int n0w = (wid >> 2) * 64;

    const char* gp[8];
    uint32_t sof[8];
    size_t gstep[8];
    #pragma unroll
    for (int i = 0; i < 8; i++){
        int idx = i*256 + tid;
        if (idx < 1024){
            int row = idx >> 3, seg = idx & 7;
            gp[i]   = (const char*)(A + (size_t)(m0 + row)*K) + seg*16;
            sof[i]  = (uint32_t)(row*MG_ARB + seg*16);
            gstep[i] = 128;
        } else {
            int t = idx - 1024;
            int row = t >> 4, seg = t & 15;
            gp[i]   = (const char*)(B + (size_t)row*N + n0) + seg*16;
            sof[i]  = (uint32_t)(G2_BOFF + row*MG_BRB + seg*16);
            gstep[i] = (size_t)64*N*2;
        }
    }

#define G2_LOAD(IT, ST) do { \
        const uint32_t _sb = smb + (uint32_t)(ST)*G2_STAGE; \
        _Pragma("unroll") \
        for (int _i = 0; _i < 8; _i++){ \
            asm volatile("cp.async.cg.shared.global [%0], [%1], 16;" \
                :: "r"(_sb + sof[_i]), "l"(gp[_i] + (size_t)(IT)*gstep[_i]) : "memory"); \
        } \
        asm volatile("cp.async.commit_group;" ::: "memory"); \
    } while(0)

    float c[2][8][4];
    #pragma unroll
    for (int mt = 0; mt < 2; mt++)
        #pragma unroll
        for (int nt = 0; nt < 8; nt++)
            #pragma unroll
            for (int q = 0; q < 4; q++) c[mt][nt][q] = 0.f;

    const uint32_t aoff  = (uint32_t)((lane & 15)*MG_ARB + ((lane >> 4) & 1)*16);
    const uint32_t boff4 = (uint32_t)(G2_BOFF + (lane & 15)*MG_BRB + ((lane >> 4) & 1)*16 + n0w*2);

    G2_LOAD(0, 0);
    G2_LOAD(1, 1);

    int s = 0, sl = 2;
    for (int it = 0; it < NIT; ++it){
        if (it == NIT-1) asm volatile("cp.async.wait_group 0;" ::: "memory");
        else             asm volatile("cp.async.wait_group 1;" ::: "memory");
        __syncthreads();
        if (it + 2 < NIT) G2_LOAD(it + 2, sl);

        const uint32_t sb = smb + (uint32_t)s*G2_STAGE;
        #pragma unroll
        for (int k16 = 0; k16 < 4; k16++){
            uint32_t a[2][4];
            #pragma unroll
            for (int mt = 0; mt < 2; mt++)
                ldsm_x4(a[mt], sb + (uint32_t)((m0w + mt*16)*MG_ARB) + aoff + k16*32);
            uint32_t b[8][2];
            #pragma unroll
            for (int u = 0; u < 4; u++)
                ldsm_x4t(&b[2*u][0], sb + boff4 + (uint32_t)(k16*16*MG_BRB) + u*32);
            #pragma unroll
            for (int mt = 0; mt < 2; mt++)
                #pragma unroll
                for (int nt = 0; nt < 8; nt++)
                    mma_f16(c[mt][nt], a[mt], b[nt]);
        }
        s  = (s  == 2) ? 0 : s  + 1;
        sl = (sl == 2) ? 0 : sl + 1;
    }

    #pragma unroll
    for (int mt = 0; mt < 2; mt++){
        const int m = m0 + m0w + mt*16 + g;
        #pragma unroll
        for (int nt = 0; nt < 8; nt++){
            const int n = n0 + n0w + nt*8 + 2*tig;
            const float b0 = __ldg(bias + n), b1 = __ldg(bias + n + 1);
            const float g0 = __ldg(gate + n), g1 = __ldg(gate + n + 1);
            float v0 = xres[(size_t)m*N + n]       + g0*(c[mt][nt][0] + b0);
            float v1 = xres[(size_t)m*N + n + 1]   + g1*(c[mt][nt][1] + b1);
            float v2 = xres[(size_t)(m+8)*N + n]   + g0*(c[mt][nt][2] + b0);
            float v3 = xres[(size_t)(m+8)*N + n+1] + g1*(c[mt][nt][3] + b1);
            *(float2*)(Cf + (size_t)m*N + n)     = make_float2(v0, v1);
            *(float2*)(Cf + (size_t)(m+8)*N + n) = make_float2(v2, v3);
        }
    }
}

// ---------------- qkv split + RMSNorm + RoPE -> half (4 heads/block) ------
__global__ __launch_bounds__(256) void qkv_post(const float* __restrict__ pe,
                                                const float* __restrict__ qsc,
                                                const float* __restrict__ ksc){
    const int l  = blockIdx.x;
    const int tid = threadIdx.x;
    const int hs = tid >> 6;
    const int d2 = tid & 63;
    const int nh = blockIdx.y*4 + hs;
    const float* hp = g_h3 + (size_t)l*QKVN + nh*DD;
    float qe = hp[2*d2],        qo = hp[2*d2+1];
    float ke = hp[HH + 2*d2],   ko = hp[HH + 2*d2+1];
    float ve = hp[2*HH + 2*d2], vo = hp[2*HH + 2*d2+1];

    float sq = qe*qe + qo*qo;
    float sk = ke*ke + ko*ko;
    #pragma unroll
    for (int w = 1; w < 32; w <<= 1){
        sq += __shfl_xor_sync(0xffffffffu, sq, w);
        sk += __shfl_xor_sync(0xffffffffu, sk, w);
    }
    __shared__ float red[8][2];
    int wid = tid >> 5;
    if ((tid & 31) == 0){ red[wid][0] = sq; red[wid][1] = sk; }
    __syncthreads();
    const int gb = (wid >> 1) << 1;
    sq = red[gb][0] + red[gb+1][0];
    sk = red[gb][1] + red[gb+1][1];
    const float rq = rsqrtf(sq * (1.f/128.f) + 1e-6f);
    const float rk = rsqrtf(sk * (1.f/128.f) + 1e-6f);
    qe *= rq * qsc[2*d2]; qo *= rq * qsc[2*d2+1];
    ke *= rk * ksc[2*d2]; ko *= rk * ksc[2*d2+1];
    const float4 r = *(const float4*)(pe + ((size_t)l*64 + d2)*4);
    const float qscale = 0.08838834764831845f * 1.4426950408889634f; // /sqrt(D)*log2e
    float qe2 = (r.x*qe + r.y*qo) * qscale;
    float qo2 = (r.z*qe + r.w*qo) * qscale;
    float ke2 = r.x*ke + r.y*ko;
    float ko2 = r.z*ke + r.w*ko;
    size_t o = ((size_t)nh*LL + l)*DD + 2*d2;
    g_qh[o] = __float2half(qe2); g_qh[o+1] = __float2half(qo2);
    g_kh[o] = __float2half(ke2); g_kh[o+1] = __float2half(ko2);
    g_vh[o] = __float2half(ve);  g_vh[o+1] = __float2half(vo);
}

// ---------------- flash attention: P in registers, 2-stage, occ 2 ---------
#define AQ_RB 272
#define AKV0  (128*AQ_RB)                    // 34816
#define AKV_STAGE (64*AQ_RB*2)               // 34816
#define AV_IN 17408
#define ATF_SMEM (AKV0 + 2*AKV_STAGE)        // 104448
#define NKT (LL/64)

__global__ __launch_bounds__(256, 2)
void attn_f16(){
    extern __shared__ char smc[];
    const uint32_t smb = smem_u32(smc);
    const int tid  = threadIdx.x;
    const int wid  = tid >> 5;
    const int lane = tid & 31;
    const int nh = blockIdx.y;
    const int q0 = blockIdx.x * 128;
    const __half* Qh = g_qh + (size_t)nh*LL*DD;
    const __half* Kh = g_kh + (size_t)nh*LL*DD;
    const __half* Vh = g_vh + (size_t)nh*LL*DD;

#define ATT_LOAD(IT, ST) do { \
        const uint32_t _sb = smb + AKV0 + (uint32_t)(ST)*AKV_STAGE; \
        const __half* _kb = Kh + (size_t)(IT)*64*DD; \
        const __half* _vb = Vh + (size_t)(IT)*64*DD; \
        _Pragma("unroll") \
        for (int _i = 0; _i < 8; _i++){ \
            int _idx = _i*256 + tid; \
            int _t = _idx & 1023; \
            int _r = _t >> 4, _sg = _t & 15; \
            const char* _g = (const char*)((_idx < 1024 ? _kb : _vb) + (size_t)_r*DD) + _sg*16; \
            uint32_t _sa = _sb + (_idx < 1024 ? 0u : (uint32_t)AV_IN) + (uint32_t)(_r*AQ_RB + _sg*16); \
            asm volatile("cp.async.cg.shared.global [%0], [%1], 16;" :: "r"(_sa), "l"(_g) : "memory"); \
        } \
        asm volatile("cp.async.commit_group;" ::: "memory"); \
    } while(0)

    ATT_LOAD(0, 0);
    ATT_LOAD(1, 1);

    // Q tile (128 x 128 half)
    #pragma unroll
    for (int i = 0; i < 8; i++){
        int idx = i*256 + tid;
        int r = idx >> 4, s = idx & 15;
        uint4 v = *(const uint4*)((const char*)(Qh + (size_t)(q0+r)*DD) + s*16);
        *(uint4*)(smc + r*AQ_RB + s*16) = v;
    }

    float o[16][4];
    #pragma unroll
    for (int nt = 0; nt < 16; nt++)
        #pragma unroll
        for (int q = 0; q < 4; q++) o[nt][q] = 0.f;
    float m0 = -1e30f, m1 = -1e30f, l0 = 0.f, l1 = 0.f;

    const uint32_t aoffQ = smb + (uint32_t)((wid*16 + (lane & 15))*AQ_RB + ((lane >> 4) & 1)*16);
    // K x4 (non-trans): rows 16u + ((lane>>4)&1)*8 + (lane&7), k-half (lane>>3)&1
    const uint32_t kbase4 = (uint32_t)((((lane >> 4) & 1)*8 + (lane & 7))*AQ_RB + ((lane >> 3) & 1)*16);
    // V x4 (trans): rows (lane&15), col group ((lane>>4)&1)*16 bytes
    const uint32_t vbase4 = (uint32_t)((lane & 15)*AQ_RB + ((lane >> 4) & 1)*16);

    int st = 0;
    for (int kt = 0; kt < NKT; kt++){
        if (kt == NKT-1) asm volatile("cp.async.wait_group 0;" ::: "memory");
        else             asm volatile("cp.async.wait_group 1;" ::: "memory");
        __syncthreads();

        const uint32_t kvb = smb + AKV0 + (uint32_t)st*AKV_STAGE;

        // S = Q @ K^T
        float s[8][4];
        #pragma unroll
        for (int nt = 0; nt < 8; nt++)
            #pragma unroll
            for (int q = 0; q < 4; q++) s[nt][q] = 0.f;
        #pragma unroll
        for (int k16 = 0; k16 < 8; k16++){
            uint32_t a[4];
            ldsm_x4(a, aoffQ + k16*32);
            #pragma unroll
            for (int u = 0; u < 4; u++){
                uint32_t bb[4];
                ldsm_x4(bb, kvb + kbase4 + (uint32_t)(u*16*AQ_RB) + k16*32);
                mma_f16(s[2*u],   a, bb);
                mma_f16(s[2*u+1], a, bb+2);
            }
        }

        // online softmax (rows g, g+8); S already in log2 units
        float mx0 = -1e30f, mx1 = -1e30f;
        #pragma unroll
        for (int nt = 0; nt < 8; nt++){
            mx0 = fmaxf(mx0, fmaxf(s[nt][0], s[nt][1]));
            mx1 = fmaxf(mx1, fmaxf(s[nt][2], s[nt][3]));
        }
        mx0 = fmaxf(mx0, __shfl_xor_sync(0xffffffffu, mx0, 1));
        mx0 = fmaxf(mx0, __shfl_xor_sync(0xffffffffu, mx0, 2));
        mx1 = fmaxf(mx1, __shfl_xor_sync(0xffffffffu, mx1, 1));
        mx1 = fmaxf(mx1, __shfl_xor_sync(0xffffffffu, mx1, 2));
        const float mn0 = fmaxf(m0, mx0), mn1 = fmaxf(m1, mx1);
        const float al0 = ex2f(m0 - mn0), al1 = ex2f(m1 - mn1);
        m0 = mn0; m1 = mn1;
        float rs0 = 0.f, rs1 = 0.f;
        uint32_t ph[8][2];
        #pragma unroll
        for (int nt = 0; nt < 8; nt++){
            float p0 = ex2f(s[nt][0] - mn0);
            float p1 = ex2f(s[nt][1] - mn0);
            float p2 = ex2f(s[nt][2] - mn1);
            float p3 = ex2f(s[nt][3] - mn1);
            rs0 += p0 + p1; rs1 += p2 + p3;
            ph[nt][0] = h2_u32(__floats2half2_rn(p0, p1));   // row g
            ph[nt][1] = h2_u32(__floats2half2_rn(p2, p3));   // row g+8
        }
        rs0 += __shfl_xor_sync(0xffffffffu, rs0, 1);
        rs0 += __shfl_xor_sync(0xffffffffu, rs0, 2);
        rs1 += __shfl_xor_sync(0xffffffffu, rs1, 1);
        rs1 += __shfl_xor_sync(0xffffffffu, rs1, 2);
        l0 = l0*al0 + rs0;
        l1 = l1*al1 + rs1;
        #pragma unroll
        for (int nt = 0; nt < 16; nt++){
            o[nt][0] *= al0; o[nt][1] *= al0;
            o[nt][2] *= al1; o[nt][3] *= al1;
        }

        // O += P @ V : P fragments straight from registers
        #pragma unroll
        for (int c16 = 0; c16 < 4; c16++){
            uint32_t pa[4] = { ph[2*c16][0], ph[2*c16][1],
                               ph[2*c16+1][0], ph[2*c16+1][1] };
            #pragma unroll
            for (int u = 0; u < 8; u++){
                uint32_t bb[4];
                ldsm_x4t(bb, kvb + AV_IN + vbase4 + (uint32_t)(c16*16*AQ_RB) + u*32);
                mma_f16(o[2*u],   pa, bb);
                mma_f16(o[2*u+1], pa, bb+2);
            }
        }

        __syncthreads();
        if (kt + 2 < NKT) ATT_LOAD(kt + 2, st);
        st ^= 1;
    }

    const float rl0 = 1.0f / l0, rl1 = 1.0f / l1;
    const int g = lane >> 2, tig = lane & 3;
    const int r0 = q0 + wid*16 + g, r1 = r0 + 8;
    #pragma unroll
    for (int nt = 0; nt < 16; nt++){
        const int col = nh*DD + nt*8 + 2*tig;
        *(uint32_t*)(g_cath + (size_t)r0*CATN + col)
            = h2_u32(__floats2half2_rn(o[nt][0]*rl0, o[nt][1]*rl0));
        *(uint32_t*)(g_cath + (size_t)r1*CATN + col)
            = h2_u32(__floats2half2_rn(o[nt][2]*rl1, o[nt][3]*rl1));
    }
}

// ---------------- launch --------------------------------------------------
extern "C" void kernel_launch(void* const* d_in, const int* in_sizes, int n_in,
                              void* d_out, int out_size){
    (void)in_sizes; (void)n_in; (void)out_size;
    const float* x       = (const float*)d_in[0];
    const float* vec     = (const float*)d_in[1];
    const float* pe      = (const float*)d_in[2];
    const float* mod_w   = (const float*)d_in[3];
    const float* mod_b   = (const float*)d_in[4];
    const float* ln_s    = (const float*)d_in[5];
    const float* ln_b    = (const float*)d_in[6];
    const float* w1      = (const float*)d_in[7];
    const float* b1      = (const float*)d_in[8];
    const float* q_scale = (const float*)d_in[9];
    const float* k_scale = (const float*)d_in[10];
    const float* w2      = (const float*)d_in[11];
    const float* b2      = (const float*)d_in[12];
    float* out = (float*)d_out;

    float *p_mod;
    __half *p_xmodh, *p_cath, *p_w1h, *p_w2h;
    cudaGetSymbolAddress((void**)&p_xmodh, g_xmodh);
    cudaGetSymbolAddress((void**)&p_cath,  g_cath);
    cudaGetSymbolAddress((void**)&p_mod,   g_mod);
    cudaGetSymbolAddress((void**)&p_w1h,   g_w1h);
    cudaGetSymbolAddress((void**)&p_w2h,   g_w2h);

    cudaFuncSetAttribute(attn_f16, cudaFuncAttributeMaxDynamicSharedMemorySize, ATF_SMEM);
    cudaFuncSetAttribute(gemm1_f16, cudaFuncAttributeMaxDynamicSharedMemorySize, MG_SMEM);
    cudaFuncSetAttribute(gemm2_f16, cudaFuncAttributeMaxDynamicSharedMemorySize, G2_SMEM);

    const int n4w1 = (int)((size_t)HH*W1N/4);
    const int n4w2 = (int)((size_t)CATN*HH/4);
    conv_f16<<<(n4w1+255)/256, 256>>>((const float4*)w1, (uint2*)p_w1h, n4w1);
    conv_f16<<<(n4w2+255)/256, 256>>>((const float4*)w2, (uint2*)p_w2h, n4w2);
    silu_init<<<QKVN/256, 256>>>(vec, mod_b);
    mod_gemv<<<dim3(QKVN/512, HH/256), 256>>>(mod_w);
    ln_mod  <<<LL, 256>>>(x, ln_s, ln_b);
    gemm1_f16<<<dim3(LL/256, W1N/128), 256, MG_SMEM>>>(p_xmodh, p_w1h, b1,
                                                       W1N, HH, HH/64);
    qkv_post<<<dim3(LL, NHH/4), 256>>>(pe, q_scale, k_scale);
    attn_f16<<<dim3(LL/128, NHH), 256, ATF_SMEM>>>();
    gemm2_f16<<<dim3(LL/128, HH/128), 256, G2_SMEM>>>(p_cath, p_w2h, b2, out,
                                                      HH, CATN, CATN/64,
                                                      x, p_mod + 2*HH);
}

// round 11
// speedup vs baseline: 6.5790x; 1.0268x over previous
#include <cuda_runtime.h>
#include <cuda_fp16.h>
#include <cstdint>
#include <cstring>

#define LL   2048
#define HH   3072
#define NHH  24
#define DD   128
#define MLPD 12288
#define W1N  21504
#define CATN 15360
#define QKVN 9216

__device__ __forceinline__ uint32_t h2_u32(__half2 h){
    uint32_t u; memcpy(&u, &h, 4); return u;
}
__device__ __forceinline__ uint32_t smem_u32(const void* p){
    uint32_t a; asm("{ .reg .u64 t; cvta.to.shared.u64 t, %1; cvt.u32.u64 %0, t; }" : "=r"(a) : "l"(p));
    return a;
}
__device__ __forceinline__ float ex2f(float x){
    float r; asm("ex2.approx.f32 %0, %1;" : "=f"(r) : "f"(x)); return r;
}
__device__ __forceinline__ float gelu_f(float v){
    float c = 0.7978845608028654f * (v + 0.044715f*v*v*v);
    return 0.5f*v*(1.f + tanhf(c));
}
__device__ __forceinline__ void mma_f16(float* c, const uint32_t* a, const uint32_t* b){
    asm volatile("mma.sync.aligned.m16n8k16.row.col.f32.f16.f16.f32 "
        "{%0,%1,%2,%3}, {%4,%5,%6,%7}, {%8,%9}, {%0,%1,%2,%3};"
        : "+f"(c[0]), "+f"(c[1]), "+f"(c[2]), "+f"(c[3])
        : "r"(a[0]), "r"(a[1]), "r"(a[2]), "r"(a[3]), "r"(b[0]), "r"(b[1]));
}
__device__ __forceinline__ void ldsm_x4(uint32_t* r, uint32_t a){
    asm volatile("ldmatrix.sync.aligned.m8n8.x4.shared.b16 {%0,%1,%2,%3}, [%4];"
        : "=r"(r[0]), "=r"(r[1]), "=r"(r[2]), "=r"(r[3]) : "r"(a));
}
__device__ __forceinline__ void ldsm_x4t(uint32_t* r, uint32_t a){
    asm volatile("ldmatrix.sync.aligned.m8n8.x4.trans.shared.b16 {%0,%1,%2,%3}, [%4];"
        : "=r"(r[0]), "=r"(r[1]), "=r"(r[2]), "=r"(r[3]) : "r"(a));
}

// ---------------- scratch ----------------
__device__ float  g_sv[HH];
__device__ float  g_mod[3*HH];
__device__ __half g_xmodh[(size_t)LL*HH];
__device__ float  g_h3[(size_t)LL*QKVN];
__device__ __half g_qh[(size_t)NHH*LL*DD];
__device__ __half g_kh[(size_t)NHH*LL*DD];
__device__ __half g_vh[(size_t)NHH*LL*DD];
__device__ __half g_cath[(size_t)LL*CATN];
__device__ __half g_w1h[(size_t)HH*W1N];
__device__ __half g_w2h[(size_t)CATN*HH];

// ---------------- fp32 -> fp16 convert ----------------
__global__ void conv_f16(const float4* __restrict__ in, uint2* __restrict__ out, int n4){
    int i = blockIdx.x*256 + threadIdx.x;
    if (i < n4){
        float4 v = in[i];
        __half2 a = __floats2half2_rn(v.x, v.y);
        __half2 b = __floats2half2_rn(v.z, v.w);
        uint2 o; memcpy(&o.x, &a, 4); memcpy(&o.y, &b, 4);
        out[i] = o;
    }
}

// ---------------- silu + mod init ----------------
__global__ void silu_init(const float* __restrict__ vec, const float* __restrict__ b){
    int i = blockIdx.x*256 + threadIdx.x;
    if (i < HH){
        float t = vec[i];
        g_sv[i] = t / (1.f + expf(-t));
    }
    if (i < QKVN) g_mod[i] = b[i];
}

// ---------------- K-split GEMV (float2 per thread) ----------------
__global__ __launch_bounds__(256) void mod_gemv(const float* __restrict__ W){
    const int j  = (blockIdx.x*256 + threadIdx.x)*2;
    const int k0 = blockIdx.y*256;
    __shared__ float svs[256];
    svs[threadIdx.x] = g_sv[k0 + threadIdx.x];
    __syncthreads();
    float a0 = 0.f, a1 = 0.f;
    #pragma unroll 8
    for (int i = 0; i < 256; i++){
        float2 w = *(const float2*)(W + (size_t)(k0+i)*QKVN + j);
        a0 = fmaf(svs[i], w.x, a0);
        a1 = fmaf(svs[i], w.y, a1);
    }
    atomicAdd(&g_mod[j],   a0);
    atomicAdd(&g_mod[j+1], a1);
}

// ---------------- LayerNorm + modulate (half output, 384 thr) -------------
__global__ __launch_bounds__(384) void ln_mod(const float* __restrict__ x,
                                              const float* __restrict__ lns,
                                              const float* __restrict__ lnb){
    const int l = blockIdx.x;
    const int tid = threadIdx.x;
    __shared__ float xs[HH];
    __shared__ float rsum[24];
    float s = 0.f, ss = 0.f;
    #pragma unroll
    for (int t = 0; t < 2; t++){
        int i = tid*4 + t*1536;
        float4 v = *(const float4*)(x + (size_t)l*HH + i);
        *(float4*)(xs + i) = v;
        s += v.x + v.y + v.z + v.w;
        ss = fmaf(v.x, v.x, ss); ss = fmaf(v.y, v.y, ss);
        ss = fmaf(v.z, v.z, ss); ss = fmaf(v.w, v.w, ss);
    }
    #pragma unroll
    for (int w = 1; w < 32; w <<= 1){
        s  += __shfl_xor_sync(0xffffffffu, s,  w);
        ss += __shfl_xor_sync(0xffffffffu, ss, w);
    }
    int wid = tid >> 5;
    if ((tid & 31) == 0){ rsum[wid] = s; rsum[wid + 12] = ss; }
    __syncthreads();
    s = 0.f; ss = 0.f;
    #pragma unroll
    for (int w = 0; w < 12; w++){ s += rsum[w]; ss += rsum[w + 12]; }
    const float mu   = s  * (1.f/(float)HH);
    const float var  = ss * (1.f/(float)HH) - mu*mu;
    const float rstd = rsqrtf(var + 1e-6f);
    #pragma unroll
    for (int t = 0; t < 2; t++){
        int i = tid*4 + t*1536;
        float4 v  = *(const float4*)(xs + i);
        float4 lv = *(const float4*)(lns + i);
        float4 bv = *(const float4*)(lnb + i);
        float4 sc = *(const float4*)(g_mod + HH + i);
        float4 sh = *(const float4*)(g_mod + i);
        float o0 = (1.f+sc.x)*((v.x-mu)*rstd*lv.x + bv.x) + sh.x;
        float o1 = (1.f+sc.y)*((v.y-mu)*rstd*lv.y + bv.y) + sh.y;
        float o2 = (1.f+sc.z)*((v.z-mu)*rstd*lv.z + bv.z) + sh.z;
        float o3 = (1.f+sc.w)*((v.w-mu)*rstd*lv.w + bv.w) + sh.w;
        uint2 o;
        __half2 ha = __floats2half2_rn(o0, o1);
        __half2 hb = __floats2half2_rn(o2, o3);
        memcpy(&o.x, &ha, 4); memcpy(&o.y, &hb, 4);
        *(uint2*)(g_xmodh + (size_t)l*HH + i) = o;
    }
}

// ---------------- shared GEMM geometry: 128x128 tile, 3-stage, occ 2 ------
#define MG_ARB   144
#define MG_BRB   272
#define G2_BOFF  (128*MG_ARB)                 // 18432
#define G2_STAGE (G2_BOFF + 64*MG_BRB)        // 35840
#define G2_SMEM  (3*G2_STAGE)                 // 107520

// ---------------- GEMM1: dual epilogue (qkv fp32 | gelu half) -------------
__global__ __launch_bounds__(256, 2)
void gemm1_f16(const __half* __restrict__ A, const __half* __restrict__ B,
               const float* __restrict__ bias, int N, int K, int NIT)
{
    extern __shared__ char smc[];
    const uint32_t smb = smem_u32(smc);
    const int tid  = threadIdx.x;
    const int wid  = tid >> 5;
    const int lane = tid & 31;
    const int g    = lane >> 2;
    const int tig  = lane & 3;
    const int m0 = blockIdx.x * 128;
    const int n0 = blockIdx.y * 128;
    const int m0w = (wid & 3) * 32;
    const int n0w = (wid >> 2) * 64;

    const char* gp[8];
    uint32_t sof[8];
    size_t gstep[8];
    #pragma unroll
    for (int i = 0; i < 8; i++){
        int idx = i*256 + tid;
        if (idx < 1024){
            int row = idx >> 3, seg = idx & 7;
            gp[i]   = (const char*)(A + (size_t)(m0 + row)*K) + seg*16;
            sof[i]  = (uint32_t)(row*MG_ARB + seg*16);
            gstep[i] = 128;
        } else {
            int t = idx - 1024;
            int row = t >> 4, seg = t & 15;
            gp[i]   = (const char*)(B + (size_t)row*N + n0) + seg*16;
            sof[i]  = (uint32_t)(G2_BOFF + row*MG_BRB + seg*16);
            gstep[i] = (size_t)64*N*2;
        }
    }

#define G1_LOAD(IT, ST) do { \
        const uint32_t _sb = smb + (uint32_t)(ST)*G2_STAGE; \
        _Pragma("unroll") \
        for (int _i = 0; _i < 8; _i++){ \
            asm volatile("cp.async.cg.shared.global [%0], [%1], 16;" \
                :: "r"(_sb + sof[_i]), "l"(gp[_i] + (size_t)(IT)*gstep[_i]) : "memory"); \
        } \
        asm volatile("cp.async.commit_group;" ::: "memory"); \
    } while(0)

    float c[2][8][4];
    #pragma unroll
    for (int mt = 0; mt < 2; mt++)
        #pragma unroll
        for (int nt = 0; nt < 8; nt++)
            #pragma unroll
            for (int q = 0; q < 4; q++) c[mt][nt][q] = 0.f;

    const uint32_t aoff  = (uint32_t)((lane & 15)*MG_ARB + ((lane >> 4) & 1)*16);
    const uint32_t boff4 = (uint32_t)(G2_BOFF + (lane & 15)*MG_BRB + ((lane >> 4) & 1)*16 + n0w*2);

    G1_LOAD(0, 0);
    G1_LOAD(1, 1);

    int s = 0, sl = 2;
    for (int it = 0; it < NIT; ++it){
        if (it == NIT-1) asm volatile("cp.async.wait_group 0;" ::: "memory");
        else             asm volatile("cp.async.wait_group 1;" ::: "memory");
        __syncthreads();
        if (it + 2 < NIT) G1_LOAD(it + 2, sl);

        const uint32_t sb = smb + (uint32_t)s*G2_STAGE;
        #pragma unroll
        for (int k16 = 0; k16 < 4; k16++){
            uint32_t a[2][4];
            #pragma unroll
            for (int mt = 0; mt < 2; mt++)
                ldsm_x4(a[mt], sb + (uint32_t)((m0w + mt*16)*MG_ARB) + aoff + k16*32);
            uint32_t b[8][2];
            #pragma unroll
            for (int u = 0; u < 4; u++)
                ldsm_x4t(&b[2*u][0], sb + boff4 + (uint32_t)(k16*16*MG_BRB) + u*32);
            #pragma unroll
            for (int mt = 0; mt < 2; mt++)
                #pragma unroll
                for (int nt = 0; nt < 8; nt++)
                    mma_f16(c[mt][nt], a[mt], b[nt]);
        }
        s  = (s  == 2) ? 0 : s  + 1;
        sl = (sl == 2) ? 0 : sl + 1;
    }

    if (n0 >= QKVN){
        const int nc0 = HH + (n0 - QKVN);
        #pragma unroll
        for (int mt = 0; mt < 2; mt++){
            const int m = m0 + m0w + mt*16 + g;
            #pragma unroll
            for (int nt = 0; nt < 8; nt++){
                const int nl = n0w + nt*8 + 2*tig;
                const int n  = n0 + nl;
                const float b0 = __ldg(bias + n), b1 = __ldg(bias + n + 1);
                float v0 = gelu_f(c[mt][nt][0] + b0);
                float v1 = gelu_f(c[mt][nt][1] + b1);
                float v2 = gelu_f(c[mt][nt][2] + b0);
                float v3 = gelu_f(c[mt][nt][3] + b1);
                *(uint32_t*)(g_cath + (size_t)m*CATN + nc0 + nl)
                    = h2_u32(__floats2half2_rn(v0, v1));
                *(uint32_t*)(g_cath + (size_t)(m+8)*CATN + nc0 + nl)
                    = h2_u32(__floats2half2_rn(v2, v3));
            }
        }
    } else {
        #pragma unroll
        for (int mt = 0; mt < 2; mt++){
            const int m = m0 + m0w + mt*16 + g;
            #pragma unroll
            for (int nt = 0; nt < 8; nt++){
                const int n = n0 + n0w + nt*8 + 2*tig;
                const float b0 = __ldg(bias + n), b1 = __ldg(bias + n + 1);
                *(float2*)(g_h3 + (size_t)m*QKVN + n)
                    = make_float2(c[mt][nt][0] + b0, c[mt][nt][1] + b1);
                *(float2*)(g_h3 + (size_t)(m+8)*QKVN + n)
                    = make_float2(c[mt][nt][2] + b0, c[mt][nt][3] + b1);
            }
        }
    }
}

// ---------------- GEMM2: gated residual epilogue ---------------------------
__global__ __launch_bounds__(256, 2)
void gemm2_f16(const __half* __restrict__ A, const __half* __restrict__ B,
               const float* __restrict__ bias, float* __restrict__ Cf,
               int N, int K, int NIT,
               const float* __restrict__ xres, const float* __restrict__ gate)
{
    extern __shared__ char smc[];
    const uint32_t smb = smem_u32(smc);
    const int tid  = threadIdx.x;
    const int wid  = tid >> 5;
    const int lane = tid & 31;
    const int g    = lane >> 2;
    const int tig  = lane & 3;
    const int m0 = blockIdx.x * 128;
    const int n0 = blockIdx.y * 128;
    const int m0w = (wid & 3) * 32;
    const int n0w = (wid >> 2) * 64;

    const char* gp[8];
    uint32_t sof[8];
    size_t gstep[8];
    #pragma unroll
    for (int i = 0; i < 8; i++){
        int idx = i*256 + tid;
        if (idx < 1024){
            int row = idx >> 3, seg = idx & 7;
            gp[i]   = (const char*)(A + (size_t)(m0 + row)*K) + seg*16;
            sof[i]  = (uint32_t)(row*MG_ARB + seg*16);
            gstep[i] = 128;
        } else {
            int t = idx - 1024;
            int row = t >> 4, seg = t & 15;
            gp[i]   = (const char*)(B + (size_t)row*N + n0) + seg*16;
            sof[i]  = (uint32_t)(G2_BOFF + row*MG_BRB + seg*16);
            gstep[i] = (size_t)64*N*2;
        }
    }

#define G2_LOAD(IT, ST) do { \
        const uint32_t _sb = smb + (uint32_t)(ST)*G2_STAGE; \
        _Pragma("unroll") \
        for (int _i = 0; _i < 8; _i++){ \
            asm volatile("cp.async.cg.shared.global [%0], [%1], 16;" \
                :: "r"(_sb + sof[_i]), "l"(gp[_i] + (size_t)(IT)*gstep[_i]) : "memory"); \
        } \
        asm volatile("cp.async.commit_group;" ::: "memory"); \
    } while(0)

    float c[2][8][4];
    #pragma unroll
    for (int mt = 0; mt < 2; mt++)
        #pragma unroll
        for (int nt = 0; nt < 8; nt++)
            #pragma unroll
            for (int q = 0; q < 4; q++) c[mt][nt][q] = 0.f;

    const uint32_t aoff  = (uint32_t)((lane & 15)*MG_ARB + ((lane >> 4) & 1)*16);
    const uint32_t boff4 = (uint32_t)(G2_BOFF + (lane & 15)*MG_BRB + ((lane >> 4) & 1)*16 + n0w*2);

    G2_LOAD(0, 0);
    G2_LOAD(1, 1);

    int s = 0, sl = 2;
    for (int it = 0; it < NIT; ++it){
        if (it == NIT-1) asm volatile("cp.async.wait_group 0;" ::: "memory");
        else             asm volatile("cp.async.wait_group 1;" ::: "memory");
        __syncthreads();
        if (it + 2 < NIT) G2_LOAD(it + 2, sl);

        const uint32_t sb = smb + (uint32_t)s*G2_STAGE;
        #pragma unroll
        for (int k16 = 0; k16 < 4; k16++){
            uint32_t a[2][4];
            #pragma unroll
            for (int mt = 0; mt < 2; mt++)
                ldsm_x4(a[mt], sb + (uint32_t)((m0w + mt*16)*MG_ARB) + aoff + k16*32);
            uint32_t b[8][2];
            #pragma unroll
            for (int u = 0; u < 4; u++)
                ldsm_x4t(&b[2*u][0], sb + boff4 + (uint32_t)(k16*16*MG_BRB) + u*32);
            #pragma unroll
            for (int mt = 0; mt < 2; mt++)
                #pragma unroll
                for (int nt = 0; nt < 8; nt++)
                    mma_f16(c[mt][nt], a[mt], b[nt]);
        }
        s  = (s  == 2) ? 0 : s  + 1;
        sl = (sl == 2) ? 0 : sl + 1;
    }

    #pragma unroll
    for (int mt = 0; mt < 2; mt++){
        const int m = m0 + m0w + mt*16 + g;
        #pragma unroll
        for (int nt = 0; nt < 8; nt++){
            const int n = n0 + n0w + nt*8 + 2*tig;
            const float b0 = __ldg(bias + n), b1 = __ldg(bias + n + 1);
            const float g0 = __ldg(gate + n), g1 = __ldg(gate + n + 1);
            float v0 = xres[(size_t)m*N + n]       + g0*(c[mt][nt][0] + b0);
            float v1 = xres[(size_t)m*N + n + 1]   + g1*(c[mt][nt][1] + b1);
            float v2 = xres[(size_t)(m+8)*N + n]   + g0*(c[mt][nt][2] + b0);
            float v3 = xres[(size_t)(m+8)*N + n+1] + g1*(c[mt][nt][3] + b1);
            *(float2*)(Cf + (size_t)m*N + n)     = make_float2(v0, v1);
            *(float2*)(Cf + (size_t)(m+8)*N + n) = make_float2(v2, v3);
        }
    }
}

// ---------------- qkv split + RMSNorm + RoPE -> half (4 heads/block) ------
__global__ __launch_bounds__(256) void qkv_post(const float* __restrict__ pe,
                                                const float* __restrict__ qsc,
                                                const float* __restrict__ ksc){
    const int l  = blockIdx.x;
    const int tid = threadIdx.x;
    const int hs = tid >> 6;
    const int d2 = tid & 63;
    const int nh = blockIdx.y*4 + hs;
    const float* hp = g_h3 + (size_t)l*QKVN + nh*DD;
    float qe = hp[2*d2],        qo = hp[2*d2+1];
    float ke = hp[HH + 2*d2],   ko = hp[HH + 2*d2+1];
    float ve = hp[2*HH + 2*d2], vo = hp[2*HH + 2*d2+1];

    float sq = qe*qe + qo*qo;
    float sk = ke*ke + ko*ko;
    #pragma unroll
    for (int w = 1; w < 32; w <<= 1){
        sq += __shfl_xor_sync(0xffffffffu, sq, w);
        sk += __shfl_xor_sync(0xffffffffu, sk, w);
    }
    __shared__ float red[8][2];
    int wid = tid >> 5;
    if ((tid & 31) == 0){ red[wid][0] = sq; red[wid][1] = sk; }
    __syncthreads();
    const int gb = (wid >> 1) << 1;
    sq = red[gb][0] + red[gb+1][0];
    sk = red[gb][1] + red[gb+1][1];
    const float rq = rsqrtf(sq * (1.f/128.f) + 1e-6f);
    const float rk = rsqrtf(sk * (1.f/128.f) + 1e-6f);
    qe *= rq * qsc[2*d2]; qo *= rq * qsc[2*d2+1];
    ke *= rk * ksc[2*d2]; ko *= rk * ksc[2*d2+1];
    const float4 r = *(const float4*)(pe + ((size_t)l*64 + d2)*4);
    const float qscale = 0.08838834764831845f * 1.4426950408889634f; // /sqrt(D)*log2e
    float qe2 = (r.x*qe + r.y*qo) * qscale;
    float qo2 = (r.z*qe + r.w*qo) * qscale;
    float ke2 = r.x*ke + r.y*ko;
    float ko2 = r.z*ke + r.w*ko;
    size_t o = ((size_t)nh*LL + l)*DD + 2*d2;
    g_qh[o] = __float2half(qe2); g_qh[o+1] = __float2half(qo2);
    g_kh[o] = __float2half(ke2); g_kh[o+1] = __float2half(ko2);
    g_vh[o] = __float2half(ve);  g_vh[o+1] = __float2half(vo);
}

// ---------------- flash attention: P in registers, 2-stage, occ 2 ---------
#define AQ_RB 272
#define AKV0  (128*AQ_RB)                    // 34816
#define AKV_STAGE (64*AQ_RB*2)               // 34816
#define AV_IN 17408
#define ATF_SMEM (AKV0 + 2*AKV_STAGE)        // 104448
#define NKT (LL/64)

__global__ __launch_bounds__(256, 2)
void attn_f16(){
    extern __shared__ char smc[];
    const uint32_t smb = smem_u32(smc);
    const int tid  = threadIdx.x;
    const int wid  = tid >> 5;
    const int lane = tid & 31;
    const int nh = blockIdx.y;
    const int q0 = blockIdx.x * 128;
    const __half* Qh = g_qh + (size_t)nh*LL*DD;
    const __half* Kh = g_kh + (size_t)nh*LL*DD;
    const __half* Vh = g_vh + (size_t)nh*LL*DD;

#define ATT_LOAD(IT, ST) do { \
        const uint32_t _sb = smb + AKV0 + (uint32_t)(ST)*AKV_STAGE; \
        const __half* _kb = Kh + (size_t)(IT)*64*DD; \
        const __half* _vb = Vh + (size_t)(IT)*64*DD; \
        _Pragma("unroll") \
        for (int _i = 0; _i < 8; _i++){ \
            int _idx = _i*256 + tid; \
            int _t = _idx & 1023; \
            int _r = _t >> 4, _sg = _t & 15; \
            const char* _g = (const char*)((_idx < 1024 ? _kb : _vb) + (size_t)_r*DD) + _sg*16; \
            uint32_t _sa = _sb + (_idx < 1024 ? 0u : (uint32_t)AV_IN) + (uint32_t)(_r*AQ_RB + _sg*16); \
            asm volatile("cp.async.cg.shared.global [%0], [%1], 16;" :: "r"(_sa), "l"(_g) : "memory"); \
        } \
        asm volatile("cp.async.commit_group;" ::: "memory"); \
    } while(0)

    ATT_LOAD(0, 0);
    ATT_LOAD(1, 1);

    #pragma unroll
    for (int i = 0; i < 8; i++){
        int idx = i*256 + tid;
        int r = idx >> 4, s = idx & 15;
        uint4 v = *(const uint4*)((const char*)(Qh + (size_t)(q0+r)*DD) + s*16);
        *(uint4*)(smc + r*AQ_RB + s*16) = v;
    }

    float o[16][4];
    #pragma unroll
    for (int nt = 0; nt < 16; nt++)
        #pragma unroll
        for (int q = 0; q < 4; q++) o[nt][q] = 0.f;
    float m0 = -1e30f, m1 = -1e30f, l0 = 0.f, l1 = 0.f;

    const uint32_t aoffQ = smb + (uint32_t)((wid*16 + (lane & 15))*AQ_RB + ((lane >> 4) & 1)*16);
    const uint32_t kbase4 = (uint32_t)((((lane >> 4) & 1)*8 + (lane & 7))*AQ_RB + ((lane >> 3) & 1)*16);
    const uint32_t vbase4 = (uint32_t)((lane & 15)*AQ_RB + ((lane >> 4) & 1)*16);

    int st = 0;
    for (int kt = 0; kt < NKT; kt++){
        if (kt == NKT-1) asm volatile("cp.async.wait_group 0;" ::: "memory");
        else             asm volatile("cp.async.wait_group 1;" ::: "memory");
        __syncthreads();

        const uint32_t kvb = smb + AKV0 + (uint32_t)st*AKV_STAGE;

        float s[8][4];
        #pragma unroll
        for (int nt = 0; nt < 8; nt++)
            #pragma unroll
            for (int q = 0; q < 4; q++) s[nt][q] = 0.f;
        #pragma unroll
        for (int k16 = 0; k16 < 8; k16++){
            uint32_t a[4];
            ldsm_x4(a, aoffQ + k16*32);
            #pragma unroll
            for (int u = 0; u < 4; u++){
                uint32_t bb[4];
                ldsm_x4(bb, kvb + kbase4 + (uint32_t)(u*16*AQ_RB) + k16*32);
                mma_f16(s[2*u],   a, bb);
                mma_f16(s[2*u+1], a, bb+2);
            }
        }

        float mx0 = -1e30f, mx1 = -1e30f;
        #pragma unroll
        for (int nt = 0; nt < 8; nt++){
            mx0 = fmaxf(mx0, fmaxf(s[nt][0], s[nt][1]));
            mx1 = fmaxf(mx1, fmaxf(s[nt][2], s[nt][3]));
        }
        mx0 = fmaxf(mx0, __shfl_xor_sync(0xffffffffu, mx0, 1));
        mx0 = fmaxf(mx0, __shfl_xor_sync(0xffffffffu, mx0, 2));
        mx1 = fmaxf(mx1, __shfl_xor_sync(0xffffffffu, mx1, 1));
        mx1 = fmaxf(mx1, __shfl_xor_sync(0xffffffffu, mx1, 2));
        const float mn0 = fmaxf(m0, mx0), mn1 = fmaxf(m1, mx1);
        const float al0 = ex2f(m0 - mn0), al1 = ex2f(m1 - mn1);
        m0 = mn0; m1 = mn1;
        float rs0 = 0.f, rs1 = 0.f;
        uint32_t ph[8][2];
        #pragma unroll
        for (int nt = 0; nt < 8; nt++){
            float p0 = ex2f(s[nt][0] - mn0);
            float p1 = ex2f(s[nt][1] - mn0);
            float p2 = ex2f(s[nt][2] - mn1);
            float p3 = ex2f(s[nt][3] - mn1);
            rs0 += p0 + p1; rs1 += p2 + p3;
            ph[nt][0] = h2_u32(__floats2half2_rn(p0, p1));
            ph[nt][1] = h2_u32(__floats2half2_rn(p2, p3));
        }
        rs0 += __shfl_xor_sync(0xffffffffu, rs0, 1);
        rs0 += __shfl_xor_sync(0xffffffffu, rs0, 2);
        rs1 += __shfl_xor_sync(0xffffffffu, rs1, 1);
        rs1 += __shfl_xor_sync(0xffffffffu, rs1, 2);
        l0 = l0*al0 + rs0;
        l1 = l1*al1 + rs1;
        #pragma unroll
        for (int nt = 0; nt < 16; nt++){
            o[nt][0] *= al0; o[nt][1] *= al0;
            o[nt][2] *= al1; o[nt][3] *= al1;
        }

        #pragma unroll
        for (int c16 = 0; c16 < 4; c16++){
            uint32_t pa[4] = { ph[2*c16][0], ph[2*c16][1],
                               ph[2*c16+1][0], ph[2*c16+1][1] };
            #pragma unroll
            for (int u = 0; u < 8; u++){
                uint32_t bb[4];
                ldsm_x4t(bb, kvb + AV_IN + vbase4 + (uint32_t)(c16*16*AQ_RB) + u*32);
                mma_f16(o[2*u],   pa, bb);
                mma_f16(o[2*u+1], pa, bb+2);
            }
        }

        __syncthreads();
        if (kt + 2 < NKT) ATT_LOAD(kt + 2, st);
        st ^= 1;
    }

    const float rl0 = 1.0f / l0, rl1 = 1.0f / l1;
    const int g = lane >> 2, tig = lane & 3;
    const int r0 = q0 + wid*16 + g, r1 = r0 + 8;
    #pragma unroll
    for (int nt = 0; nt < 16; nt++){
        const int col = nh*DD + nt*8 + 2*tig;
        *(uint32_t*)(g_cath + (size_t)r0*CATN + col)
            = h2_u32(__floats2half2_rn(o[nt][0]*rl0, o[nt][1]*rl0));
        *(uint32_t*)(g_cath + (size_t)r1*CATN + col)
            = h2_u32(__floats2half2_rn(o[nt][2]*rl1, o[nt][3]*rl1));
    }
}

// ---------------- launch --------------------------------------------------
extern "C" void kernel_launch(void* const* d_in, const int* in_sizes, int n_in,
                              void* d_out, int out_size){
    (void)in_sizes; (void)n_in; (void)out_size;
    const float* x       = (const float*)d_in[0];
    const float* vec     = (const float*)d_in[1];
    const float* pe      = (const float*)d_in[2];
    const float* mod_w   = (const float*)d_in[3];
    const float* mod_b   = (const float*)d_in[4];
    const float* ln_s    = (const float*)d_in[5];
    const float* ln_b    = (const float*)d_in[6];
    const float* w1      = (const float*)d_in[7];
    const float* b1      = (const float*)d_in[8];
    const float* q_scale = (const float*)d_in[9];
    const float* k_scale = (const float*)d_in[10];
    const float* w2      = (const float*)d_in[11];
    const float* b2      = (const float*)d_in[12];
    float* out = (float*)d_out;

    float *p_mod;
    __half *p_xmodh, *p_cath, *p_w1h, *p_w2h;
    cudaGetSymbolAddress((void**)&p_xmodh, g_xmodh);
    cudaGetSymbolAddress((void**)&p_cath,  g_cath);
    cudaGetSymbolAddress((void**)&p_mod,   g_mod);
    cudaGetSymbolAddress((void**)&p_w1h,   g_w1h);
    cudaGetSymbolAddress((void**)&p_w2h,   g_w2h);

    cudaFuncSetAttribute(attn_f16, cudaFuncAttributeMaxDynamicSharedMemorySize, ATF_SMEM);
    cudaFuncSetAttribute(gemm1_f16, cudaFuncAttributeMaxDynamicSharedMemorySize, G2_SMEM);
    cudaFuncSetAttribute(gemm2_f16, cudaFuncAttributeMaxDynamicSharedMemorySize, G2_SMEM);

    const int n4w1 = (int)((size_t)HH*W1N/4);
    const int n4w2 = (int)((size_t)CATN*HH/4);
    conv_f16<<<(n4w1+255)/256, 256>>>((const float4*)w1, (uint2*)p_w1h, n4w1);
    conv_f16<<<(n4w2+255)/256, 256>>>((const float4*)w2, (uint2*)p_w2h, n4w2);
    silu_init<<<QKVN/256, 256>>>(vec, mod_b);
    mod_gemv<<<dim3(QKVN/512, HH/256), 256>>>(mod_w);
    ln_mod  <<<LL, 384>>>(x, ln_s, ln_b);
    gemm1_f16<<<dim3(LL/128, W1N/128), 256, G2_SMEM>>>(p_xmodh, p_w1h, b1,
                                                       W1N, HH, HH/64);
    qkv_post<<<dim3(LL, NHH/4), 256>>>(pe, q_scale, k_scale);
    attn_f16<<<dim3(LL/128, NHH), 256, ATF_SMEM>>>();
    gemm2_f16<<<dim3(LL/128, HH/128), 256, G2_SMEM>>>(p_cath, p_w2h, b2, out,
                                                      HH, CATN, CATN/64,
                                                      x, p_mod + 2*HH);
}

// round 12
// speedup vs baseline: 6.6321x; 1.0081x over previous
#include <cuda_runtime.h>
#include <cuda_fp16.h>
#include <cstdint>
#include <cstring>

#define LL   2048
#define HH   3072
#define NHH  24
#define DD   128
#define MLPD 12288
#define W1N  21504
#define CATN 15360
#define QKVN 9216

__device__ __forceinline__ uint32_t h2_u32(__half2 h){
    uint32_t u; memcpy(&u, &h, 4); return u;
}
__device__ __forceinline__ __half2 u32_h2(uint32_t u){
    __half2 h; memcpy(&h, &u, 4); return h;
}
__device__ __forceinline__ uint32_t smem_u32(const void* p){
    uint32_t a; asm("{ .reg .u64 t; cvta.to.shared.u64 t, %1; cvt.u32.u64 %0, t; }" : "=r"(a) : "l"(p));
    return a;
}
__device__ __forceinline__ float ex2f(float x){
    float r; asm("ex2.approx.f32 %0, %1;" : "=f"(r) : "f"(x)); return r;
}
__device__ __forceinline__ uint32_t ex2_h2(uint32_t x){
    uint32_t r; asm("ex2.approx.f16x2 %0, %1;" : "=r"(r) : "r"(x)); return r;
}
__device__ __forceinline__ float tanh_ap(float x){
    float r; asm("tanh.approx.f32 %0, %1;" : "=f"(r) : "f"(x)); return r;
}
__device__ __forceinline__ float gelu_f(float v){
    float c = 0.7978845608028654f * (v + 0.044715f*v*v*v);
    return 0.5f*v*(1.f + tanh_ap(c));
}
__device__ __forceinline__ void mma_f16(float* c, const uint32_t* a, const uint32_t* b){
    asm volatile("mma.sync.aligned.m16n8k16.row.col.f32.f16.f16.f32 "
        "{%0,%1,%2,%3}, {%4,%5,%6,%7}, {%8,%9}, {%0,%1,%2,%3};"
        : "+f"(c[0]), "+f"(c[1]), "+f"(c[2]), "+f"(c[3])
        : "r"(a[0]), "r"(a[1]), "r"(a[2]), "r"(a[3]), "r"(b[0]), "r"(b[1]));
}
__device__ __forceinline__ void ldsm_x4(uint32_t* r, uint32_t a){
    asm volatile("ldmatrix.sync.aligned.m8n8.x4.shared.b16 {%0,%1,%2,%3}, [%4];"
        : "=r"(r[0]), "=r"(r[1]), "=r"(r[2]), "=r"(r[3]) : "r"(a));
}
__device__ __forceinline__ void ldsm_x4t(uint32_t* r, uint32_t a){
    asm volatile("ldmatrix.sync.aligned.m8n8.x4.trans.shared.b16 {%0,%1,%2,%3}, [%4];"
        : "=r"(r[0]), "=r"(r[1]), "=r"(r[2]), "=r"(r[3]) : "r"(a));
}

// ---------------- scratch ----------------
__device__ float  g_sv[HH];
__device__ float  g_mod[3*HH];
__device__ __half g_xmodh[(size_t)LL*HH];
__device__ float  g_h3[(size_t)LL*QKVN];
__device__ __half g_qh[(size_t)NHH*LL*DD];
__device__ __half g_kh[(size_t)NHH*LL*DD];
__device__ __half g_vh[(size_t)NHH*LL*DD];
__device__ __half g_cath[(size_t)LL*CATN];
__device__ __half g_w1h[(size_t)HH*W1N];
__device__ __half g_w2h[(size_t)CATN*HH];

// ---------------- fp32 -> fp16 convert ----------------
__global__ void conv_f16(const float4* __restrict__ in, uint2* __restrict__ out, int n4){
    int i = blockIdx.x*256 + threadIdx.x;
    if (i < n4){
        float4 v = in[i];
        __half2 a = __floats2half2_rn(v.x, v.y);
        __half2 b = __floats2half2_rn(v.z, v.w);
        uint2 o; memcpy(&o.x, &a, 4); memcpy(&o.y, &b, 4);
        out[i] = o;
    }
}

// ---------------- silu + mod init ----------------
__global__ void silu_init(const float* __restrict__ vec, const float* __restrict__ b){
    int i = blockIdx.x*256 + threadIdx.x;
    if (i < HH){
        float t = vec[i];
        g_sv[i] = t / (1.f + expf(-t));
    }
    if (i < QKVN) g_mod[i] = b[i];
}

// ---------------- K-split GEMV (float2 per thread) ----------------
__global__ __launch_bounds__(256) void mod_gemv(const float* __restrict__ W){
    const int j  = (blockIdx.x*256 + threadIdx.x)*2;
    const int k0 = blockIdx.y*256;
    __shared__ float svs[256];
    svs[threadIdx.x] = g_sv[k0 + threadIdx.x];
    __syncthreads();
    float a0 = 0.f, a1 = 0.f;
    #pragma unroll 8
    for (int i = 0; i < 256; i++){
        float2 w = *(const float2*)(W + (size_t)(k0+i)*QKVN + j);
        a0 = fmaf(svs[i], w.x, a0);
        a1 = fmaf(svs[i], w.y, a1);
    }
    atomicAdd(&g_mod[j],   a0);
    atomicAdd(&g_mod[j+1], a1);
}

// ---------------- LayerNorm + modulate (half output, 384 thr) -------------
__global__ __launch_bounds__(384) void ln_mod(const float* __restrict__ x,
                                              const float* __restrict__ lns,
                                              const float* __restrict__ lnb){
    const int l = blockIdx.x;
    const int tid = threadIdx.x;
    __shared__ float xs[HH];
    __shared__ float rsum[24];
    float s = 0.f, ss = 0.f;
    #pragma unroll
    for (int t = 0; t < 2; t++){
        int i = tid*4 + t*1536;
        float4 v = *(const float4*)(x + (size_t)l*HH + i);
        *(float4*)(xs + i) = v;
        s += v.x + v.y + v.z + v.w;
        ss = fmaf(v.x, v.x, ss); ss = fmaf(v.y, v.y, ss);
        ss = fmaf(v.z, v.z, ss); ss = fmaf(v.w, v.w, ss);
    }
    #pragma unroll
    for (int w = 1; w < 32; w <<= 1){
        s  += __shfl_xor_sync(0xffffffffu, s,  w);
        ss += __shfl_xor_sync(0xffffffffu, ss, w);
    }
    int wid = tid >> 5;
    if ((tid & 31) == 0){ rsum[wid] = s; rsum[wid + 12] = ss; }
    __syncthreads();
    s = 0.f; ss = 0.f;
    #pragma unroll
    for (int w = 0; w < 12; w++){ s += rsum[w]; ss += rsum[w + 12]; }
    const float mu   = s  * (1.f/(float)HH);
    const float var  = ss * (1.f/(float)HH) - mu*mu;
    const float rstd = rsqrtf(var + 1e-6f);
    #pragma unroll
    for (int t = 0; t < 2; t++){
        int i = tid*4 + t*1536;
        float4 v  = *(const float4*)(xs + i);
        float4 lv = *(const float4*)(lns + i);
        float4 bv = *(const float4*)(lnb + i);
        float4 sc = *(const float4*)(g_mod + HH + i);
        float4 sh = *(const float4*)(g_mod + i);
        float o0 = (1.f+sc.x)*((v.x-mu)*rstd*lv.x + bv.x) + sh.x;
        float o1 = (1.f+sc.y)*((v.y-mu)*rstd*lv.y + bv.y) + sh.y;
        float o2 = (1.f+sc.z)*((v.z-mu)*rstd*lv.z + bv.z) + sh.z;
        float o3 = (1.f+sc.w)*((v.w-mu)*rstd*lv.w + bv.w) + sh.w;
        uint2 o;
        __half2 ha = __floats2half2_rn(o0, o1);
        __half2 hb = __floats2half2_rn(o2, o3);
        memcpy(&o.x, &ha, 4); memcpy(&o.y, &hb, 4);
        *(uint2*)(g_xmodh + (size_t)l*HH + i) = o;
    }
}

// ---------------- shared GEMM geometry: 128x128 tile, 3-stage, occ 2 ------
#define MG_ARB   144
#define MG_BRB   272
#define G2_BOFF  (128*MG_ARB)                 // 18432
#define G2_STAGE (G2_BOFF + 64*MG_BRB)        // 35840
#define G2_SMEM  (3*G2_STAGE)                 // 107520

// ---------------- GEMM1: dual epilogue (qkv fp32 | gelu half) -------------
__global__ __launch_bounds__(256, 2)
void gemm1_f16(const __half* __restrict__ A, const __half* __restrict__ B,
               const float* __restrict__ bias, int N, int K, int NIT)
{
    extern __shared__ char smc[];
    const uint32_t smb = smem_u32(smc);
    const int tid  = threadIdx.x;
    const int wid  = tid >> 5;
    const int lane = tid & 31;
    const int g    = lane >> 2;
    const int tig  = lane & 3;
    const int m0 = blockIdx.x * 128;
    const int n0 = blockIdx.y * 128;
    const int m0w = (wid & 3) * 32;
    const int n0w = (wid >> 2) * 64;

    const char* gp[8];
    uint32_t sof[8];
    size_t gstep[8];
    #pragma unroll
    for (int i = 0; i < 8; i++){
        int idx = i*256 + tid;
        if (idx < 1024){
            int row = idx >> 3, seg = idx & 7;
            gp[i]   = (const char*)(A + (size_t)(m0 + row)*K) + seg*16;
            sof[i]  = (uint32_t)(row*MG_ARB + seg*16);
            gstep[i] = 128;
        } else {
            int t = idx - 1024;
            int row = t >> 4, seg = t & 15;
            gp[i]   = (const char*)(B + (size_t)row*N + n0) + seg*16;
            sof[i]  = (uint32_t)(G2_BOFF + row*MG_BRB + seg*16);
            gstep[i] = (size_t)64*N*2;
        }
    }

#define G1_LOAD(IT, ST) do { \
        const uint32_t _sb = smb + (uint32_t)(ST)*G2_STAGE; \
        _Pragma("unroll") \
        for (int _i = 0; _i < 8; _i++){ \
            asm volatile("cp.async.cg.shared.global [%0], [%1], 16;" \
                :: "r"(_sb + sof[_i]), "l"(gp[_i] + (size_t)(IT)*gstep[_i]) : "memory"); \
        } \
        asm volatile("cp.async.commit_group;" ::: "memory"); \
    } while(0)

    float c[2][8][4];
    #pragma unroll
    for (int mt = 0; mt < 2; mt++)
        #pragma unroll
        for (int nt = 0; nt < 8; nt++)
            #pragma unroll
            for (int q = 0; q < 4; q++) c[mt][nt][q] = 0.f;

    const uint32_t aoff  = (uint32_t)((lane & 15)*MG_ARB + ((lane >> 4) & 1)*16);
    const uint32_t boff4 = (uint32_t)(G2_BOFF + (lane & 15)*MG_BRB + ((lane >> 4) & 1)*16 + n0w*2);

    G1_LOAD(0, 0);
    G1_LOAD(1, 1);

    int s = 0, sl = 2;
    for (int it = 0; it < NIT; ++it){
        if (it == NIT-1) asm volatile("cp.async.wait_group 0;" ::: "memory");
        else             asm volatile("cp.async.wait_group 1;" ::: "memory");
        __syncthreads();
        if (it + 2 < NIT) G1_LOAD(it + 2, sl);

        const uint32_t sb = smb + (uint32_t)s*G2_STAGE;
        #pragma unroll
        for (int k16 = 0; k16 < 4; k16++){
            uint32_t a[2][4];
            #pragma unroll
            for (int mt = 0; mt < 2; mt++)
                ldsm_x4(a[mt], sb + (uint32_t)((m0w + mt*16)*MG_ARB) + aoff + k16*32);
            uint32_t b[8][2];
            #pragma unroll
            for (int u = 0; u < 4; u++)
                ldsm_x4t(&b[2*u][0], sb + boff4 + (uint32_t)(k16*16*MG_BRB) + u*32);
            #pragma unroll
            for (int mt = 0; mt < 2; mt++)
                #pragma unroll
                for (int nt = 0; nt < 8; nt++)
                    mma_f16(c[mt][nt], a[mt], b[nt]);
        }
        s  = (s  == 2) ? 0 : s  + 1;
        sl = (sl == 2) ? 0 : sl + 1;
    }

    if (n0 >= QKVN){
        const int nc0 = HH + (n0 - QKVN);
        #pragma unroll
        for (int mt = 0; mt < 2; mt++){
            const int m = m0 + m0w + mt*16 + g;
            #pragma unroll
            for (int nt = 0; nt < 8; nt++){
                const int nl = n0w + nt*8 + 2*tig;
                const int n  = n0 + nl;
                const float b0 = __ldg(bias + n), b1 = __ldg(bias + n + 1);
                float v0 = gelu_f(c[mt][nt][0] + b0);
                float v1 = gelu_f(c[mt][nt][1] + b1);
                float v2 = gelu_f(c[mt][nt][2] + b0);
                float v3 = gelu_f(c[mt][nt][3] + b1);
                *(uint32_t*)(g_cath + (size_t)m*CATN + nc0 + nl)
                    = h2_u32(__floats2half2_rn(v0, v1));
                *(uint32_t*)(g_cath + (size_t)(m+8)*CATN + nc0 + nl)
                    = h2_u32(__floats2half2_rn(v2, v3));
            }
        }
    } else {
        #pragma unroll
        for (int mt = 0; mt < 2; mt++){
            const int m = m0 + m0w + mt*16 + g;
            #pragma unroll
            for (int nt = 0; nt < 8; nt++){
                const int n = n0 + n0w + nt*8 + 2*tig;
                const float b0 = __ldg(bias + n), b1 = __ldg(bias + n + 1);
                *(float2*)(g_h3 + (size_t)m*QKVN + n)
                    = make_float2(c[mt][nt][0] + b0, c[mt][nt][1] + b1);
                *(float2*)(g_h3 + (size_t)(m+8)*QKVN + n)
                    = make_float2(c[mt][nt][2] + b0, c[mt][nt][3] + b1);
            }
        }
    }
}

// ---------------- GEMM2: gated residual epilogue ---------------------------
__global__ __launch_bounds__(256, 2)
void gemm2_f16(const __half* __restrict__ A, const __half* __restrict__ B,
               const float* __restrict__ bias, float* __restrict__ Cf,
               int N, int K, int NIT,
               const float* __restrict__ xres, const float* __restrict__ gate)
{
    extern __shared__ char smc[];
    const uint32_t smb = smem_u32(smc);
    const int tid  = threadIdx.x;
    const int wid  = tid >> 5;
    const int lane = tid & 31;
    const int g    = lane >> 2;
    const int tig  = lane & 3;
    const int m0 = blockIdx.x * 128;
    const int n0 = blockIdx.y * 128;
    const int m0w = (wid & 3) * 32;
    const int n0w = (wid >> 2) * 64;

    const char* gp[8];
    uint32_t sof[8];
    size_t gstep[8];
    #pragma unroll
    for (int i = 0; i < 8; i++){
        int idx = i*256 + tid;
        if (idx < 1024){
            int row = idx >> 3, seg = idx & 7;
            gp[i]   = (const char*)(A + (size_t)(m0 + row)*K) + seg*16;
            sof[i]  = (uint32_t)(row*MG_ARB + seg*16);
            gstep[i] = 128;
        } else {
            int t = idx - 1024;
            int row = t >> 4, seg = t & 15;
            gp[i]   = (const char*)(B + (size_t)row*N + n0) + seg*16;
            sof[i]  = (uint32_t)(G2_BOFF + row*MG_BRB + seg*16);
            gstep[i] = (size_t)64*N*2;
        }
    }

#define G2_LOAD(IT, ST) do { \
        const uint32_t _sb = smb + (uint32_t)(ST)*G2_STAGE; \
        _Pragma("unroll") \
        for (int _i = 0; _i < 8; _i++){ \
            asm volatile("cp.async.cg.shared.global [%0], [%1], 16;" \
                :: "r"(_sb + sof[_i]), "l"(gp[_i] + (size_t)(IT)*gstep[_i]) : "memory"); \
        } \
        asm volatile("cp.async.commit_group;" ::: "memory"); \
    } while(0)

    float c[2][8][4];
    #pragma unroll
    for (int mt = 0; mt < 2; mt++)
        #pragma unroll
        for (int nt = 0; nt < 8; nt++)
            #pragma unroll
            for (int q = 0; q < 4; q++) c[mt][nt][q] = 0.f;

    const uint32_t aoff  = (uint32_t)((lane & 15)*MG_ARB + ((lane >> 4) & 1)*16);
    const uint32_t boff4 = (uint32_t)(G2_BOFF + (lane & 15)*MG_BRB + ((lane >> 4) & 1)*16 + n0w*2);

    G2_LOAD(0, 0);
    G2_LOAD(1, 1);

    int s = 0, sl = 2;
    for (int it = 0; it < NIT; ++it){
        if (it == NIT-1) asm volatile("cp.async.wait_group 0;" ::: "memory");
        else             asm volatile("cp.async.wait_group 1;" ::: "memory");
        __syncthreads();
        if (it + 2 < NIT) G2_LOAD(it + 2, sl);

        const uint32_t sb = smb + (uint32_t)s*G2_STAGE;
        #pragma unroll
        for (int k16 = 0; k16 < 4; k16++){
            uint32_t a[2][4];
            #pragma unroll
            for (int mt = 0; mt < 2; mt++)
                ldsm_x4(a[mt], sb + (uint32_t)((m0w + mt*16)*MG_ARB) + aoff + k16*32);
            uint32_t b[8][2];
            #pragma unroll
            for (int u = 0; u < 4; u++)
                ldsm_x4t(&b[2*u][0], sb + boff4 + (uint32_t)(k16*16*MG_BRB) + u*32);
            #pragma unroll
            for (int mt = 0; mt < 2; mt++)
                #pragma unroll
                for (int nt = 0; nt < 8; nt++)
                    mma_f16(c[mt][nt], a[mt], b[nt]);
        }
        s  = (s  == 2) ? 0 : s  + 1;
        sl = (sl == 2) ? 0 : sl + 1;
    }

    #pragma unroll
    for (int mt = 0; mt < 2; mt++){
        const int m = m0 + m0w + mt*16 + g;
        #pragma unroll
        for (int nt = 0; nt < 8; nt++){
            const int n = n0 + n0w + nt*8 + 2*tig;
            const float b0 = __ldg(bias + n), b1 = __ldg(bias + n + 1);
            const float g0 = __ldg(gate + n), g1 = __ldg(gate + n + 1);
            float v0 = xres[(size_t)m*N + n]       + g0*(c[mt][nt][0] + b0);
            float v1 = xres[(size_t)m*N + n + 1]   + g1*(c[mt][nt][1] + b1);
            float v2 = xres[(size_t)(m+8)*N + n]   + g0*(c[mt][nt][2] + b0);
            float v3 = xres[(size_t)(m+8)*N + n+1] + g1*(c[mt][nt][3] + b1);
            *(float2*)(Cf + (size_t)m*N + n)     = make_float2(v0, v1);
            *(float2*)(Cf + (size_t)(m+8)*N + n) = make_float2(v2, v3);
        }
    }
}

// ---------------- qkv split + RMSNorm + RoPE -> half (4 heads/block) ------
__global__ __launch_bounds__(256) void qkv_post(const float* __restrict__ pe,
                                                const float* __restrict__ qsc,
                                                const float* __restrict__ ksc){
    const int l  = blockIdx.x;
    const int tid = threadIdx.x;
    const int hs = tid >> 6;
    const int d2 = tid & 63;
    const int nh = blockIdx.y*4 + hs;
    const float* hp = g_h3 + (size_t)l*QKVN + nh*DD;
    float qe = hp[2*d2],        qo = hp[2*d2+1];
    float ke = hp[HH + 2*d2],   ko = hp[HH + 2*d2+1];
    float ve = hp[2*HH + 2*d2], vo = hp[2*HH + 2*d2+1];

    float sq = qe*qe + qo*qo;
    float sk = ke*ke + ko*ko;
    #pragma unroll
    for (int w = 1; w < 32; w <<= 1){
        sq += __shfl_xor_sync(0xffffffffu, sq, w);
        sk += __shfl_xor_sync(0xffffffffu, sk, w);
    }
    __shared__ float red[8][2];
    int wid = tid >> 5;
    if ((tid & 31) == 0){ red[wid][0] = sq; red[wid][1] = sk; }
    __syncthreads();
    const int gb = (wid >> 1) << 1;
    sq = red[gb][0] + red[gb+1][0];
    sk = red[gb][1] + red[gb+1][1];
    const float rq = rsqrtf(sq * (1.f/128.f) + 1e-6f);
    const float rk = rsqrtf(sk * (1.f/128.f) + 1e-6f);
    qe *= rq * qsc[2*d2]; qo *= rq * qsc[2*d2+1];
    ke *= rk * ksc[2*d2]; ko *= rk * ksc[2*d2+1];
    const float4 r = *(const float4*)(pe + ((size_t)l*64 + d2)*4);
    const float qscale = 0.08838834764831845f * 1.4426950408889634f; // /sqrt(D)*log2e
    float qe2 = (r.x*qe + r.y*qo) * qscale;
    float qo2 = (r.z*qe + r.w*qo) * qscale;
    float ke2 = r.x*ke + r.y*ko;
    float ko2 = r.z*ke + r.w*ko;
    size_t o = ((size_t)nh*LL + l)*DD + 2*d2;
    g_qh[o] = __float2half(qe2); g_qh[o+1] = __float2half(qo2);
    g_kh[o] = __float2half(ke2); g_kh[o+1] = __float2half(ko2);
    g_vh[o] = __float2half(ve);  g_vh[o+1] = __float2half(vo);
}

// ---------------- flash attention: P in regs, f16x2 exp, 2-stage, occ 2 ----
#define AQ_RB 272
#define AKV0  (128*AQ_RB)                    // 34816
#define AKV_STAGE (64*AQ_RB*2)               // 34816
#define AV_IN 17408
#define ATF_SMEM (AKV0 + 2*AKV_STAGE)        // 104448
#define NKT (LL/64)

__global__ __launch_bounds__(256, 2)
void attn_f16(){
    extern __shared__ char smc[];
    const uint32_t smb = smem_u32(smc);
    const int tid  = threadIdx.x;
    const int wid  = tid >> 5;
    const int lane = tid & 31;
    const int nh = blockIdx.y;
    const int q0 = blockIdx.x * 128;
    const __half* Qh = g_qh + (size_t)nh*LL*DD;
    const __half* Kh = g_kh + (size_t)nh*LL*DD;
    const __half* Vh = g_vh + (size_t)nh*LL*DD;

#define ATT_LOAD(IT, ST) do { \
        const uint32_t _sb = smb + AKV0 + (uint32_t)(ST)*AKV_STAGE; \
        const __half* _kb = Kh + (size_t)(IT)*64*DD; \
        const __half* _vb = Vh + (size_t)(IT)*64*DD; \
        _Pragma("unroll") \
        for (int _i = 0; _i < 8; _i++){ \
            int _idx = _i*256 + tid; \
            int _t = _idx & 1023; \
            int _r = _t >> 4, _sg = _t & 15; \
            const char* _g = (const char*)((_idx < 1024 ? _kb : _vb) + (size_t)_r*DD) + _sg*16; \
            uint32_t _sa = _sb + (_idx < 1024 ? 0u : (uint32_t)AV_IN) + (uint32_t)(_r*AQ_RB + _sg*16); \
            asm volatile("cp.async.cg.shared.global [%0], [%1], 16;" :: "r"(_sa), "l"(_g) : "memory"); \
        } \
        asm volatile("cp.async.commit_group;" ::: "memory"); \
    } while(0)

    ATT_LOAD(0, 0);
    ATT_LOAD(1, 1);

    #pragma unroll
    for (int i = 0; i < 8; i++){
        int idx = i*256 + tid;
        int r = idx >> 4, s = idx & 15;
        uint4 v = *(const uint4*)((const char*)(Qh + (size_t)(q0+r)*DD) + s*16);
        *(uint4*)(smc + r*AQ_RB + s*16) = v;
    }

    float o[16][4];
    #pragma unroll
    for (int nt = 0; nt < 16; nt++)
        #pragma unroll
        for (int q = 0; q < 4; q++) o[nt][q] = 0.f;
    float m0 = -1e30f, m1 = -1e30f, l0 = 0.f, l1 = 0.f;

    const uint32_t aoffQ = smb + (uint32_t)((wid*16 + (lane & 15))*AQ_RB + ((lane >> 4) & 1)*16);
    const uint32_t kbase4 = (uint32_t)((((lane >> 4) & 1)*8 + (lane & 7))*AQ_RB + ((lane >> 3) & 1)*16);
    const uint32_t vbase4 = (uint32_t)((lane & 15)*AQ_RB + ((lane >> 4) & 1)*16);

    int st = 0;
    for (int kt = 0; kt < NKT; kt++){
        if (kt == NKT-1) asm volatile("cp.async.wait_group 0;" ::: "memory");
        else             asm volatile("cp.async.wait_group 1;" ::: "memory");
        __syncthreads();

        const uint32_t kvb = smb + AKV0 + (uint32_t)st*AKV_STAGE;

        float s[8][4];
        #pragma unroll
        for (int nt = 0; nt < 8; nt++)
            #pragma unroll
            for (int q = 0; q < 4; q++) s[nt][q] = 0.f;
        #pragma unroll
        for (int k16 = 0; k16 < 8; k16++){
            uint32_t a[4];
            ldsm_x4(a, aoffQ + k16*32);
            #pragma unroll
            for (int u = 0; u < 4; u++){
                uint32_t bb[4];
                ldsm_x4(bb, kvb + kbase4 + (uint32_t)(u*16*AQ_RB) + k16*32);
                mma_f16(s[2*u],   a, bb);
                mma_f16(s[2*u+1], a, bb+2);
            }
        }

        float mx0 = -1e30f, mx1 = -1e30f;
        #pragma unroll
        for (int nt = 0; nt < 8; nt++){
            mx0 = fmaxf(mx0, fmaxf(s[nt][0], s[nt][1]));
            mx1 = fmaxf(mx1, fmaxf(s[nt][2], s[nt][3]));
        }
        mx0 = fmaxf(mx0, __shfl_xor_sync(0xffffffffu, mx0, 1));
        mx0 = fmaxf(mx0, __shfl_xor_sync(0xffffffffu, mx0, 2));
        mx1 = fmaxf(mx1, __shfl_xor_sync(0xffffffffu, mx1, 1));
        mx1 = fmaxf(mx1, __shfl_xor_sync(0xffffffffu, mx1, 2));
        const float mn0 = fmaxf(m0, mx0), mn1 = fmaxf(m1, mx1);
        const float al0 = ex2f(m0 - mn0), al1 = ex2f(m1 - mn1);
        m0 = mn0; m1 = mn1;
        float rs0 = 0.f, rs1 = 0.f;
        uint32_t ph[8][2];
        #pragma unroll
        for (int nt = 0; nt < 8; nt++){
            // fp16x2 exp: P was getting rounded to fp16 anyway for the mma
            ph[nt][0] = ex2_h2(h2_u32(__floats2half2_rn(s[nt][0]-mn0, s[nt][1]-mn0)));
            ph[nt][1] = ex2_h2(h2_u32(__floats2half2_rn(s[nt][2]-mn1, s[nt][3]-mn1)));
            float2 f0 = __half22float2(u32_h2(ph[nt][0]));
            float2 f1 = __half22float2(u32_h2(ph[nt][1]));
            rs0 += f0.x + f0.y;
            rs1 += f1.x + f1.y;
        }
        rs0 += __shfl_xor_sync(0xffffffffu, rs0, 1);
        rs0 += __shfl_xor_sync(0xffffffffu, rs0, 2);
        rs1 += __shfl_xor_sync(0xffffffffu, rs1, 1);
        rs1 += __shfl_xor_sync(0xffffffffu, rs1, 2);
        l0 = l0*al0 + rs0;
        l1 = l1*al1 + rs1;
        #pragma unroll
        for (int nt = 0; nt < 16; nt++){
            o[nt][0] *= al0; o[nt][1] *= al0;
            o[nt][2] *= al1; o[nt][3] *= al1;
        }

        #pragma unroll
        for (int c16 = 0; c16 < 4; c16++){
            uint32_t pa[4] = { ph[2*c16][0], ph[2*c16][1],
                               ph[2*c16+1][0], ph[2*c16+1][1] };
            #pragma unroll
            for (int u = 0; u < 8; u++){
                uint32_t bb[4];
                ldsm_x4t(bb, kvb + AV_IN + vbase4 + (uint32_t)(c16*16*AQ_RB) + u*32);
                mma_f16(o[2*u],   pa, bb);
                mma_f16(o[2*u+1], pa, bb+2);
            }
        }

        __syncthreads();
        if (kt + 2 < NKT) ATT_LOAD(kt + 2, st);
        st ^= 1;
    }

    const float rl0 = 1.0f / l0, rl1 = 1.0f / l1;
    const int g = lane >> 2, tig = lane & 3;
    const int r0 = q0 + wid*16 + g, r1 = r0 + 8;
    #pragma unroll
    for (int nt = 0; nt < 16; nt++){
        const int col = nh*DD + nt*8 + 2*tig;
        *(uint32_t*)(g_cath + (size_t)r0*CATN + col)
            = h2_u32(__floats2half2_rn(o[nt][0]*rl0, o[nt][1]*rl0));
        *(uint32_t*)(g_cath + (size_t)r1*CATN + col)
            = h2_u32(__floats2half2_rn(o[nt][2]*rl1, o[nt][3]*rl1));
    }
}

// ---------------- launch --------------------------------------------------
extern "C" void kernel_launch(void* const* d_in, const int* in_sizes, int n_in,
                              void* d_out, int out_size){
    (void)in_sizes; (void)n_in; (void)out_size;
    const float* x       = (const float*)d_in[0];
    const float* vec     = (const float*)d_in[1];
    const float* pe      = (const float*)d_in[2];
    const float* mod_w   = (const float*)d_in[3];
    const float* mod_b   = (const float*)d_in[4];
    const float* ln_s    = (const float*)d_in[5];
    const float* ln_b    = (const float*)d_in[6];
    const float* w1      = (const float*)d_in[7];
    const float* b1      = (const float*)d_in[8];
    const float* q_scale = (const float*)d_in[9];
    const float* k_scale = (const float*)d_in[10];
    const float* w2      = (const float*)d_in[11];
    const float* b2      = (const float*)d_in[12];
    float* out = (float*)d_out;

    float *p_mod;
    __half *p_xmodh, *p_cath, *p_w1h, *p_w2h;
    cudaGetSymbolAddress((void**)&p_xmodh, g_xmodh);
    cudaGetSymbolAddress((void**)&p_cath,  g_cath);
    cudaGetSymbolAddress((void**)&p_mod,   g_mod);
    cudaGetSymbolAddress((void**)&p_w1h,   g_w1h);
    cudaGetSymbolAddress((void**)&p_w2h,   g_w2h);

    cudaFuncSetAttribute(attn_f16, cudaFuncAttributeMaxDynamicSharedMemorySize, ATF_SMEM);
    cudaFuncSetAttribute(gemm1_f16, cudaFuncAttributeMaxDynamicSharedMemorySize, G2_SMEM);
    cudaFuncSetAttribute(gemm2_f16, cudaFuncAttributeMaxDynamicSharedMemorySize, G2_SMEM);

    const int n4w1 = (int)((size_t)HH*W1N/4);
    const int n4w2 = (int)((size_t)CATN*HH/4);
    conv_f16<<<(n4w1+255)/256, 256>>>((const float4*)w1, (uint2*)p_w1h, n4w1);
    conv_f16<<<(n4w2+255)/256, 256>>>((const float4*)w2, (uint2*)p_w2h, n4w2);
    silu_init<<<QKVN/256, 256>>>(vec, mod_b);
    mod_gemv<<<dim3(QKVN/512, HH/256), 256>>>(mod_w);
    ln_mod  <<<LL, 384>>>(x, ln_s, ln_b);
    gemm1_f16<<<dim3(LL/128, W1N/128), 256, G2_SMEM>>>(p_xmodh, p_w1h, b1,
                                                       W1N, HH, HH/64);
    qkv_post<<<dim3(LL, NHH/4), 256>>>(pe, q_scale, k_scale);
    attn_f16<<<dim3(LL/128, NHH), 256, ATF_SMEM>>>();
    gemm2_f16<<<dim3(LL/128, HH/128), 256, G2_SMEM>>>(p_cath, p_w2h, b2, out,
                                                      HH, CATN, CATN/64,
                                                      x, p_mod + 2*HH);
}

// round 13
// speedup vs baseline: 6.6623x; 1.0045x over previous
#include <cuda_runtime.h>
#include <cuda_fp16.h>
#include <cstdint>
#include <cstring>

#define LL   2048
#define HH   3072
#define NHH  24
#define DD   128
#define MLPD 12288
#define W1N  21504
#define CATN 15360
#define QKVN 9216

__device__ __forceinline__ uint32_t h2_u32(__half2 h){
    uint32_t u; memcpy(&u, &h, 4); return u;
}
__device__ __forceinline__ __half2 u32_h2(uint32_t u){
    __half2 h; memcpy(&h, &u, 4); return h;
}
__device__ __forceinline__ uint32_t smem_u32(const void* p){
    uint32_t a; asm("{ .reg .u64 t; cvta.to.shared.u64 t, %1; cvt.u32.u64 %0, t; }" : "=r"(a) : "l"(p));
    return a;
}
__device__ __forceinline__ float ex2f(float x){
    float r; asm("ex2.approx.f32 %0, %1;" : "=f"(r) : "f"(x)); return r;
}
__device__ __forceinline__ uint32_t ex2_h2(uint32_t x){
    uint32_t r; asm("ex2.approx.f16x2 %0, %1;" : "=r"(r) : "r"(x)); return r;
}
__device__ __forceinline__ float tanh_ap(float x){
    float r; asm("tanh.approx.f32 %0, %1;" : "=f"(r) : "f"(x)); return r;
}
__device__ __forceinline__ float gelu_f(float v){
    float c = 0.7978845608028654f * (v + 0.044715f*v*v*v);
    return 0.5f*v*(1.f + tanh_ap(c));
}
__device__ __forceinline__ void mma_f16(float* c, const uint32_t* a, const uint32_t* b){
    asm volatile("mma.sync.aligned.m16n8k16.row.col.f32.f16.f16.f32 "
        "{%0,%1,%2,%3}, {%4,%5,%6,%7}, {%8,%9}, {%0,%1,%2,%3};"
        : "+f"(c[0]), "+f"(c[1]), "+f"(c[2]), "+f"(c[3])
        : "r"(a[0]), "r"(a[1]), "r"(a[2]), "r"(a[3]), "r"(b[0]), "r"(b[1]));
}
__device__ __forceinline__ void ldsm_x4(uint32_t* r, uint32_t a){
    asm volatile("ldmatrix.sync.aligned.m8n8.x4.shared.b16 {%0,%1,%2,%3}, [%4];"
        : "=r"(r[0]), "=r"(r[1]), "=r"(r[2]), "=r"(r[3]) : "r"(a));
}
__device__ __forceinline__ void ldsm_x4t(uint32_t* r, uint32_t a){
    asm volatile("ldmatrix.sync.aligned.m8n8.x4.trans.shared.b16 {%0,%1,%2,%3}, [%4];"
        : "=r"(r[0]), "=r"(r[1]), "=r"(r[2]), "=r"(r[3]) : "r"(a));
}

// ---------------- scratch ----------------
__device__ float  g_sv[HH];
__device__ float  g_mod[3*HH];
__device__ __half g_xmodh[(size_t)LL*HH];
__device__ __half g_qh[(size_t)NHH*LL*DD];
__device__ __half g_kh[(size_t)NHH*LL*DD];
__device__ __half g_vh[(size_t)NHH*LL*DD];
__device__ __half g_cath[(size_t)LL*CATN];
__device__ __half g_w1h[(size_t)HH*W1N];
__device__ __half g_w2h[(size_t)CATN*HH];

// ---------------- prep: conv w1 + conv w2 + silu + mod init ---------------
#define N4W1 ((int)((size_t)HH*W1N/4))
#define N4W2 ((int)((size_t)CATN*HH/4))
#define NB1  ((N4W1 + 255)/256)
#define NB2  ((N4W2 + 255)/256)
__global__ void prep(const float4* __restrict__ w1, uint2* __restrict__ o1,
                     const float4* __restrict__ w2, uint2* __restrict__ o2,
                     const float* __restrict__ vec, const float* __restrict__ b){
    const int bid = blockIdx.x;
    const int tid = threadIdx.x;
    if (bid < NB1 + NB2){
        const bool w1p = bid < NB1;
        int i = (w1p ? bid : bid - NB1)*256 + tid;
        int n = w1p ? N4W1 : N4W2;
        if (i < n){
            float4 v = w1p ? w1[i] : w2[i];
            __half2 a = __floats2half2_rn(v.x, v.y);
            __half2 c = __floats2half2_rn(v.z, v.w);
            uint2 o; memcpy(&o.x, &a, 4); memcpy(&o.y, &c, 4);
            if (w1p) o1[i] = o; else o2[i] = o;
        }
    } else {
        int i = (bid - NB1 - NB2)*256 + tid;
        if (i < HH){
            float t = vec[i];
            g_sv[i] = t / (1.f + expf(-t));
        }
        if (i < QKVN) g_mod[i] = b[i];
    }
}

// ---------------- K-split GEMV (float4 per thread) ----------------
__global__ __launch_bounds__(256) void mod_gemv(const float* __restrict__ W){
    const int j  = (blockIdx.x*256 + threadIdx.x)*4;
    const int k0 = blockIdx.y*256;
    __shared__ float svs[256];
    svs[threadIdx.x] = g_sv[k0 + threadIdx.x];
    __syncthreads();
    float a0 = 0.f, a1 = 0.f, a2 = 0.f, a3 = 0.f;
    #pragma unroll 4
    for (int i = 0; i < 256; i++){
        float4 w = *(const float4*)(W + (size_t)(k0+i)*QKVN + j);
        a0 = fmaf(svs[i], w.x, a0);
        a1 = fmaf(svs[i], w.y, a1);
        a2 = fmaf(svs[i], w.z, a2);
        a3 = fmaf(svs[i], w.w, a3);
    }
    atomicAdd(&g_mod[j],   a0);
    atomicAdd(&g_mod[j+1], a1);
    atomicAdd(&g_mod[j+2], a2);
    atomicAdd(&g_mod[j+3], a3);
}

// ---------------- LayerNorm + modulate (half output, 384 thr) -------------
__global__ __launch_bounds__(384) void ln_mod(const float* __restrict__ x,
                                              const float* __restrict__ lns,
                                              const float* __restrict__ lnb){
    const int l = blockIdx.x;
    const int tid = threadIdx.x;
    __shared__ float xs[HH];
    __shared__ float rsum[24];
    float s = 0.f, ss = 0.f;
    #pragma unroll
    for (int t = 0; t < 2; t++){
        int i = tid*4 + t*1536;
        float4 v = *(const float4*)(x + (size_t)l*HH + i);
        *(float4*)(xs + i) = v;
        s += v.x + v.y + v.z + v.w;
        ss = fmaf(v.x, v.x, ss); ss = fmaf(v.y, v.y, ss);
        ss = fmaf(v.z, v.z, ss); ss = fmaf(v.w, v.w, ss);
    }
    #pragma unroll
    for (int w = 1; w < 32; w <<= 1){
        s  += __shfl_xor_sync(0xffffffffu, s,  w);
        ss += __shfl_xor_sync(0xffffffffu, ss, w);
    }
    int wid = tid >> 5;
    if ((tid & 31) == 0){ rsum[wid] = s; rsum[wid + 12] = ss; }
    __syncthreads();
    s = 0.f; ss = 0.f;
    #pragma unroll
    for (int w = 0; w < 12; w++){ s += rsum[w]; ss += rsum[w + 12]; }
    const float mu   = s  * (1.f/(float)HH);
    const float var  = ss * (1.f/(float)HH) - mu*mu;
    const float rstd = rsqrtf(var + 1e-6f);
    #pragma unroll
    for (int t = 0; t < 2; t++){
        int i = tid*4 + t*1536;
        float4 v  = *(const float4*)(xs + i);
        float4 lv = *(const float4*)(lns + i);
        float4 bv = *(const float4*)(lnb + i);
        float4 sc = *(const float4*)(g_mod + HH + i);
        float4 sh = *(const float4*)(g_mod + i);
        float o0 = (1.f+sc.x)*((v.x-mu)*rstd*lv.x + bv.x) + sh.x;
        float o1 = (1.f+sc.y)*((v.y-mu)*rstd*lv.y + bv.y) + sh.y;
        float o2 = (1.f+sc.z)*((v.z-mu)*rstd*lv.z + bv.z) + sh.z;
        float o3 = (1.f+sc.w)*((v.w-mu)*rstd*lv.w + bv.w) + sh.w;
        uint2 o;
        __half2 ha = __floats2half2_rn(o0, o1);
        __half2 hb = __floats2half2_rn(o2, o3);
        memcpy(&o.x, &ha, 4); memcpy(&o.y, &hb, 4);
        *(uint2*)(g_xmodh + (size_t)l*HH + i) = o;
    }
}

// ---------------- shared GEMM geometry: 128x128 tile, 3-stage, occ 2 ------
#define MG_ARB   144
#define MG_BRB   272
#define G2_BOFF  (128*MG_ARB)                 // 18432
#define G2_STAGE (G2_BOFF + 64*MG_BRB)        // 35840
#define G2_SMEM  (3*G2_STAGE)                 // 107520

// ---------------- GEMM1: fused epilogue (qkv rmsnorm+rope | gelu) ---------
__global__ __launch_bounds__(256, 2)
void gemm1_f16(const __half* __restrict__ A, const __half* __restrict__ B,
               const float* __restrict__ bias,
               const float* __restrict__ pe,
               const float* __restrict__ qsc, const float* __restrict__ ksc,
               int N, int K, int NIT)
{
    extern __shared__ char smc[];
    const uint32_t smb = smem_u32(smc);
    const int tid  = threadIdx.x;
    const int wid  = tid >> 5;
    const int lane = tid & 31;
    const int g    = lane >> 2;
    const int tig  = lane & 3;
    const int m0 = blockIdx.x * 128;
    const int n0 = blockIdx.y * 128;
    const int m0w = (wid & 3) * 32;
    const int n0w = (wid >> 2) * 64;

    const char* gp[8];
    uint32_t sof[8];
    size_t gstep[8];
    #pragma unroll
    for (int i = 0; i < 8; i++){
        int idx = i*256 + tid;
        if (idx < 1024){
            int row = idx >> 3, seg = idx & 7;
            gp[i]   = (const char*)(A + (size_t)(m0 + row)*K) + seg*16;
            sof[i]  = (uint32_t)(row*MG_ARB + seg*16);
            gstep[i] = 128;
        } else {
            int t = idx - 1024;
            int row = t >> 4, seg = t & 15;
            gp[i]   = (const char*)(B + (size_t)row*N + n0) + seg*16;
            sof[i]  = (uint32_t)(G2_BOFF + row*MG_BRB + seg*16);
            gstep[i] = (size_t)64*N*2;
        }
    }

#define G1_LOAD(IT, ST) do { \
        const uint32_t _sb = smb + (uint32_t)(ST)*G2_STAGE; \
        _Pragma("unroll") \
        for (int _i = 0; _i < 8; _i++){ \
            asm volatile("cp.async.cg.shared.global [%0], [%1], 16;" \
                :: "r"(_sb + sof[_i]), "l"(gp[_i] + (size_t)(IT)*gstep[_i]) : "memory"); \
        } \
        asm volatile("cp.async.commit_group;" ::: "memory"); \
    } while(0)

    float c[2][8][4];
    #pragma unroll
    for (int mt = 0; mt < 2; mt++)
        #pragma unroll
        for (int nt = 0; nt < 8; nt++)
            #pragma unroll
            for (int q = 0; q < 4; q++) c[mt][nt][q] = 0.f;

    const uint32_t aoff  = (uint32_t)((lane & 15)*MG_ARB + ((lane >> 4) & 1)*16);
    const uint32_t boff4 = (uint32_t)(G2_BOFF + (lane & 15)*MG_BRB + ((lane >> 4) & 1)*16 + n0w*2);

    G1_LOAD(0, 0);
    G1_LOAD(1, 1);

    int s = 0, sl = 2;
    for (int it = 0; it < NIT; ++it){
        if (it == NIT-1) asm volatile("cp.async.wait_group 0;" ::: "memory");
        else             asm volatile("cp.async.wait_group 1;" ::: "memory");
        __syncthreads();
        if (it + 2 < NIT) G1_LOAD(it + 2, sl);

        const uint32_t sb = smb + (uint32_t)s*G2_STAGE;
        #pragma unroll
        for (int k16 = 0; k16 < 4; k16++){
            uint32_t a[2][4];
            #pragma unroll
            for (int mt = 0; mt < 2; mt++)
                ldsm_x4(a[mt], sb + (uint32_t)((m0w + mt*16)*MG_ARB) + aoff + k16*32);
            uint32_t b[8][2];
            #pragma unroll
            for (int u = 0; u < 4; u++)
                ldsm_x4t(&b[2*u][0], sb + boff4 + (uint32_t)(k16*16*MG_BRB) + u*32);
            #pragma unroll
            for (int mt = 0; mt < 2; mt++)
                #pragma unroll
                for (int nt = 0; nt < 8; nt++)
                    mma_f16(c[mt][nt], a[mt], b[nt]);
        }
        s  = (s  == 2) ? 0 : s  + 1;
        sl = (sl == 2) ? 0 : sl + 1;
    }

    // add bias once
    #pragma unroll
    for (int nt = 0; nt < 8; nt++){
        const int n = n0 + n0w + nt*8 + 2*tig;
        const float b0 = __ldg(bias + n), b1 = __ldg(bias + n + 1);
        #pragma unroll
        for (int mt = 0; mt < 2; mt++){
            c[mt][nt][0] += b0; c[mt][nt][1] += b1;
            c[mt][nt][2] += b0; c[mt][nt][3] += b1;
        }
    }

    if (n0 >= QKVN){
        // GELU -> half into g_cath[:, HH + (n-QKVN)]
        const int nc0 = HH + (n0 - QKVN);
        #pragma unroll
        for (int mt = 0; mt < 2; mt++){
            const int m = m0 + m0w + mt*16 + g;
            #pragma unroll
            for (int nt = 0; nt < 8; nt++){
                const int nl = n0w + nt*8 + 2*tig;
                float v0 = gelu_f(c[mt][nt][0]);
                float v1 = gelu_f(c[mt][nt][1]);
                float v2 = gelu_f(c[mt][nt][2]);
                float v3 = gelu_f(c[mt][nt][3]);
                *(uint32_t*)(g_cath + (size_t)m*CATN + nc0 + nl)
                    = h2_u32(__floats2half2_rn(v0, v1));
                *(uint32_t*)(g_cath + (size_t)(m+8)*CATN + nc0 + nl)
                    = h2_u32(__floats2half2_rn(v2, v3));
            }
        }
        return;
    }

    const int ht = n0 / HH;                 // 0=q, 1=k, 2=v
    const int nh = (n0 - ht*HH) >> 7;       // head index

    if (ht == 2){
        // V: plain half store
        __half* dst = g_vh + (size_t)nh*LL*DD;
        #pragma unroll
        for (int mt = 0; mt < 2; mt++){
            const int m = m0 + m0w + mt*16 + g;
            #pragma unroll
            for (int nt = 0; nt < 8; nt++){
                const int nl = n0w + nt*8 + 2*tig;
                *(uint32_t*)(dst + (size_t)m*DD + nl)
                    = h2_u32(__floats2half2_rn(c[mt][nt][0], c[mt][nt][1]));
                *(uint32_t*)(dst + (size_t)(m+8)*DD + nl)
                    = h2_u32(__floats2half2_rn(c[mt][nt][2], c[mt][nt][3]));
            }
        }
        return;
    }

    // Q/K: RMSNorm over the 128 cols of this block + RoPE
    float* red = (float*)smc;               // [8][32] (stages are dead)
    float sA[2], sB[2];
    #pragma unroll
    for (int mt = 0; mt < 2; mt++){
        float a = 0.f, b = 0.f;
        #pragma unroll
        for (int nt = 0; nt < 8; nt++){
            a = fmaf(c[mt][nt][0], c[mt][nt][0], a);
            a = fmaf(c[mt][nt][1], c[mt][nt][1], a);
            b = fmaf(c[mt][nt][2], c[mt][nt][2], b);
            b = fmaf(c[mt][nt][3], c[mt][nt][3], b);
        }
        a += __shfl_xor_sync(0xffffffffu, a, 1);
        a += __shfl_xor_sync(0xffffffffu, a, 2);
        b += __shfl_xor_sync(0xffffffffu, b, 1);
        b += __shfl_xor_sync(0xffffffffu, b, 2);
        sA[mt] = a; sB[mt] = b;
    }
    __syncthreads();                         // stage smem now dead for all warps
    if (tig == 0){
        #pragma unroll
        for (int mt = 0; mt < 2; mt++){
            red[wid*32 + mt*16 + g]     = sA[mt];
            red[wid*32 + mt*16 + g + 8] = sB[mt];
        }
    }
    __syncthreads();
    const int pw = wid ^ 4;
    float rrA[2], rrB[2];
    #pragma unroll
    for (int mt = 0; mt < 2; mt++){
        float ta = red[wid*32 + mt*16 + g]     + red[pw*32 + mt*16 + g];
        float tb = red[wid*32 + mt*16 + g + 8] + red[pw*32 + mt*16 + g + 8];
        rrA[mt] = rsqrtf(ta*(1.f/128.f) + 1e-6f);
        rrB[mt] = rsqrtf(tb*(1.f/128.f) + 1e-6f);
    }

    const float* sc = (ht == 0) ? qsc : ksc;
    const float post = (ht == 0) ? (0.08838834764831845f * 1.4426950408889634f) : 1.f;
    __half* dst = ((ht == 0) ? g_qh : g_kh) + (size_t)nh*LL*DD;

    #pragma unroll
    for (int mt = 0; mt < 2; mt++){
        const int mA = m0 + m0w + mt*16 + g;    // sequence positions
        const int mB = mA + 8;
        #pragma unroll
        for (int nt = 0; nt < 8; nt++){
            const int nl = n0w + nt*8 + 2*tig;
            const int d2 = nl >> 1;
            const float s0 = __ldg(sc + nl), s1 = __ldg(sc + nl + 1);
            // row A
            {
                const float4 r = *(const float4*)(pe + ((size_t)mA*64 + d2)*4);
                float e = c[mt][nt][0]*rrA[mt]*s0;
                float o = c[mt][nt][1]*rrA[mt]*s1;
                float ee = (r.x*e + r.y*o)*post;
                float oo = (r.z*e + r.w*o)*post;
                *(uint32_t*)(dst + (size_t)mA*DD + nl)
                    = h2_u32(__floats2half2_rn(ee, oo));
            }
            // row B
            {
                const float4 r = *(const float4*)(pe + ((size_t)mB*64 + d2)*4);
                float e = c[mt][nt][2]*rrB[mt]*s0;
                float o = c[mt][nt][3]*rrB[mt]*s1;
                float ee = (r.x*e + r.y*o)*post;
                float oo = (r.z*e + r.w*o)*post;
                *(uint32_t*)(dst + (size_t)mB*DD + nl)
                    = h2_u32(__floats2half2_rn(ee, oo));
            }
        }
    }
}

// ---------------- GEMM2: gated residual epilogue ---------------------------
__global__ __launch_bounds__(256, 2)
void gemm2_f16(const __half* __restrict__ A, const __half* __restrict__ B,
               const float* __restrict__ bias, float* __restrict__ Cf,
               int N, int K, int NIT,
               const float* __restrict__ xres, const float* __restrict__ gate)
{
    extern __shared__ char smc[];
    const uint32_t smb = smem_u32(smc);
    const int tid  = threadIdx.x;
    const int wid  = tid >> 5;
    const int lane = tid & 31;
    const int g    = lane >> 2;
    const int tig  = lane & 3;
    const int m0 = blockIdx.x * 128;
    const int n0 = blockIdx.y * 128;
    const int m0w = (wid & 3) * 32;
    const int n0w = (wid >> 2) * 64;

    const char* gp[8];
    uint32_t sof[8];
    size_t gstep[8];
    #pragma unroll
    for (int i = 0; i < 8; i++){
        int idx = i*256 + tid;
        if (idx < 1024){
            int row = idx >> 3, seg = idx & 7;
            gp[i]   = (const char*)(A + (size_t)(m0 + row)*K) + seg*16;
            sof[i]  = (uint32_t)(row*MG_ARB + seg*16);
            gstep[i] = 128;
        } else {
            int t = idx - 1024;
            int row = t >> 4, seg = t & 15;
            gp[i]   = (const char*)(B + (size_t)row*N + n0) + seg*16;
            sof[i]  = (uint32_t)(G2_BOFF + row*MG_BRB + seg*16);
            gstep[i] = (size_t)64*N*2;
        }
    }

#define G2_LOAD(IT, ST) do { \
        const uint32_t _sb = smb + (uint32_t)(ST)*G2_STAGE; \
        _Pragma("unroll") \
        for (int _i = 0; _i < 8; _i++){ \
            asm volatile("cp.async.cg.shared.global [%0], [%1], 16;" \
                :: "r"(_sb + sof[_i]), "l"(gp[_i] + (size_t)(IT)*gstep[_i]) : "memory"); \
        } \
        asm volatile("cp.async.commit_group;" ::: "memory"); \
    } while(0)

    float c[2][8][4];
    #pragma unroll
    for (int mt = 0; mt < 2; mt++)
        #pragma unroll
        for (int nt = 0; nt < 8; nt++)
            #pragma unroll
            for (int q = 0; q < 4; q++) c[mt][nt][q] = 0.f;

    const uint32_t aoff  = (uint32_t)((lane & 15)*MG_ARB + ((lane >> 4) & 1)*16);
    const uint32_t boff4 = (uint32_t)(G2_BOFF + (lane & 15)*MG_BRB + ((lane >> 4) & 1)*16 + n0w*2);

    G2_LOAD(0, 0);
    G2_LOAD(1, 1);

    int s = 0, sl = 2;
    for (int it = 0; it < NIT; ++it){
        if (it == NIT-1) asm volatile("cp.async.wait_group 0;" ::: "memory");
        else             asm volatile("cp.async.wait_group 1;" ::: "memory");
        __syncthreads();
        if (it + 2 < NIT) G2_LOAD(it + 2, sl);

        const uint32_t sb = smb + (uint32_t)s*G2_STAGE;
        #pragma unroll
        for (int k16 = 0; k16 < 4; k16++){
            uint32_t a[2][4];
            #pragma unroll
            for (int mt = 0; mt < 2; mt++)
                ldsm_x4(a[mt], sb + (uint32_t)((m0w + mt*16)*MG_ARB) + aoff + k16*32);
            uint32_t b[8][2];
            #pragma unroll
            for (int u = 0; u < 4; u++)
                ldsm_x4t(&b[2*u][0], sb + boff4 + (uint32_t)(k16*16*MG_BRB) + u*32);
            #pragma unroll
            for (int mt = 0; mt < 2; mt++)
                #pragma unroll
                for (int nt = 0; nt < 8; nt++)
                    mma_f16(c[mt][nt], a[mt], b[nt]);
        }
        s  = (s  == 2) ? 0 : s  + 1;
        sl = (sl == 2) ? 0 : sl + 1;
    }

    #pragma unroll
    for (int mt = 0; mt < 2; mt++){
        const int m = m0 + m0w + mt*16 + g;
        #pragma unroll
        for (int nt = 0; nt < 8; nt++){
            const int n = n0 + n0w + nt*8 + 2*tig;
            const float b0 = __ldg(bias + n), b1 = __ldg(bias + n + 1);
            const float g0 = __ldg(gate + n), g1 = __ldg(gate + n + 1);
            float v0 = xres[(size_t)m*N + n]       + g0*(c[mt][nt][0] + b0);
            float v1 = xres[(size_t)m*N + n + 1]   + g1*(c[mt][nt][1] + b1);
            float v2 = xres[(size_t)(m+8)*N + n]   + g0*(c[mt][nt][2] + b0);
            float v3 = xres[(size_t)(m+8)*N + n+1] + g1*(c[mt][nt][3] + b1);
            *(float2*)(Cf + (size_t)m*N + n)     = make_float2(v0, v1);
            *(float2*)(Cf + (size_t)(m+8)*N + n) = make_float2(v2, v3);
        }
    }
}

// ---------------- flash attention: P in regs, f16x2 exp, 2-stage, occ 2 ----
#define AQ_RB 272
#define AKV0  (128*AQ_RB)                    // 34816
#define AKV_STAGE (64*AQ_RB*2)               // 34816
#define AV_IN 17408
#define ATF_SMEM (AKV0 + 2*AKV_STAGE)        // 104448
#define NKT (LL/64)

__global__ __launch_bounds__(256, 2)
void attn_f16(){
    extern __shared__ char smc[];
    const uint32_t smb = smem_u32(smc);
    const int tid  = threadIdx.x;
    const int wid  = tid >> 5;
    const int lane = tid & 31;
    const int nh = blockIdx.y;
    const int q0 = blockIdx.x * 128;
    const __half* Qh = g_qh + (size_t)nh*LL*DD;
    const __half* Kh = g_kh + (size_t)nh*LL*DD;
    const __half* Vh = g_vh + (size_t)nh*LL*DD;

#define ATT_LOAD(IT, ST) do { \
        const uint32_t _sb = smb + AKV0 + (uint32_t)(ST)*AKV_STAGE; \
        const __half* _kb = Kh + (size_t)(IT)*64*DD; \
        const __half* _vb = Vh + (size_t)(IT)*64*DD; \
        _Pragma("unroll") \
        for (int _i = 0; _i < 8; _i++){ \
            int _idx = _i*256 + tid; \
            int _t = _idx & 1023; \
            int _r = _t >> 4, _sg = _t & 15; \
            const char* _g = (const char*)((_idx < 1024 ? _kb : _vb) + (size_t)_r*DD) + _sg*16; \
            uint32_t _sa = _sb + (_idx < 1024 ? 0u : (uint32_t)AV_IN) + (uint32_t)(_r*AQ_RB + _sg*16); \
            asm volatile("cp.async.cg.shared.global [%0], [%1], 16;" :: "r"(_sa), "l"(_g) : "memory"); \
        } \
        asm volatile("cp.async.commit_group;" ::: "memory"); \
    } while(0)

    ATT_LOAD(0, 0);
    ATT_LOAD(1, 1);

    #pragma unroll
    for (int i = 0; i < 8; i++){
        int idx = i*256 + tid;
        int r = idx >> 4, s = idx & 15;
        uint4 v = *(const uint4*)((const char*)(Qh + (size_t)(q0+r)*DD) + s*16);
        *(uint4*)(smc + r*AQ_RB + s*16) = v;
    }

    float o[16][4];
    #pragma unroll
    for (int nt = 0; nt < 16; nt++)
        #pragma unroll
        for (int q = 0; q < 4; q++) o[nt][q] = 0.f;
    float m0 = -1e30f, m1 = -1e30f, l0 = 0.f, l1 = 0.f;

    const uint32_t aoffQ = smb + (uint32_t)((wid*16 + (lane & 15))*AQ_RB + ((lane >> 4) & 1)*16);
    const uint32_t kbase4 = (uint32_t)((((lane >> 4) & 1)*8 + (lane & 7))*AQ_RB + ((lane >> 3) & 1)*16);
    const uint32_t vbase4 = (uint32_t)((lane & 15)*AQ_RB + ((lane >> 4) & 1)*16);

    int st = 0;
    for (int kt = 0; kt < NKT; kt++){
        if (kt == NKT-1) asm volatile("cp.async.wait_group 0;" ::: "memory");
        else             asm volatile("cp.async.wait_group 1;" ::: "memory");
        __syncthreads();

        const uint32_t kvb = smb + AKV0 + (uint32_t)st*AKV_STAGE;

        float s[8][4];
        #pragma unroll
        for (int nt = 0; nt < 8; nt++)
            #pragma unroll
            for (int q = 0; q < 4; q++) s[nt][q] = 0.f;
        #pragma unroll
        for (int k16 = 0; k16 < 8; k16++){
            uint32_t a[4];
            ldsm_x4(a, aoffQ + k16*32);
            #pragma unroll
            for (int u = 0; u < 4; u++){
                uint32_t bb[4];
                ldsm_x4(bb, kvb + kbase4 + (uint32_t)(u*16*AQ_RB) + k16*32);
                mma_f16(s[2*u],   a, bb);
                mma_f16(s[2*u+1], a, bb+2);
            }
        }

        float mx0 = -1e30f, mx1 = -1e30f;
        #pragma unroll
        for (int nt = 0; nt < 8; nt++){
            mx0 = fmaxf(mx0, fmaxf(s[nt][0], s[nt][1]));
            mx1 = fmaxf(mx1, fmaxf(s[nt][2], s[nt][3]));
        }
        mx0 = fmaxf(mx0, __shfl_xor_sync(0xffffffffu, mx0, 1));
        mx0 = fmaxf(mx0, __shfl_xor_sync(0xffffffffu, mx0, 2));
        mx1 = fmaxf(mx1, __shfl_xor_sync(0xffffffffu, mx1, 1));
        mx1 = fmaxf(mx1, __shfl_xor_sync(0xffffffffu, mx1, 2));
        const float mn0 = fmaxf(m0, mx0), mn1 = fmaxf(m1, mx1);
        const float al0 = ex2f(m0 - mn0), al1 = ex2f(m1 - mn1);
        m0 = mn0; m1 = mn1;
        float rs0 = 0.f, rs1 = 0.f;
        uint32_t ph[8][2];
        #pragma unroll
        for (int nt = 0; nt < 8; nt++){
            ph[nt][0] = ex2_h2(h2_u32(__floats2half2_rn(s[nt][0]-mn0, s[nt][1]-mn0)));
            ph[nt][1] = ex2_h2(h2_u32(__floats2half2_rn(s[nt][2]-mn1, s[nt][3]-mn1)));
            float2 f0 = __half22float2(u32_h2(ph[nt][0]));
            float2 f1 = __half22float2(u32_h2(ph[nt][1]));
            rs0 += f0.x + f0.y;
            rs1 += f1.x + f1.y;
        }
        rs0 += __shfl_xor_sync(0xffffffffu, rs0, 1);
        rs0 += __shfl_xor_sync(0xffffffffu, rs0, 2);
        rs1 += __shfl_xor_sync(0xffffffffu, rs1, 1);
        rs1 += __shfl_xor_sync(0xffffffffu, rs1, 2);
        l0 = l0*al0 + rs0;
        l1 = l1*al1 + rs1;
        #pragma unroll
        for (int nt = 0; nt < 16; nt++){
            o[nt][0] *= al0; o[nt][1] *= al0;
            o[nt][2] *= al1; o[nt][3] *= al1;
        }

        #pragma unroll
        for (int c16 = 0; c16 < 4; c16++){
            uint32_t pa[4] = { ph[2*c16][0], ph[2*c16][1],
                               ph[2*c16+1][0], ph[2*c16+1][1] };
            #pragma unroll
            for (int u = 0; u < 8; u++){
                uint32_t bb[4];
                ldsm_x4t(bb, kvb + AV_IN + vbase4 + (uint32_t)(c16*16*AQ_RB) + u*32);
                mma_f16(o[2*u],   pa, bb);
                mma_f16(o[2*u+1], pa, bb+2);
            }
        }

        __syncthreads();
        if (kt + 2 < NKT) ATT_LOAD(kt + 2, st);
        st ^= 1;
    }

    const float rl0 = 1.0f / l0, rl1 = 1.0f / l1;
    const int g = lane >> 2, tig = lane & 3;
    const int r0 = q0 + wid*16 + g, r1 = r0 + 8;
    #pragma unroll
    for (int nt = 0; nt < 16; nt++){
        const int col = nh*DD + nt*8 + 2*tig;
        *(uint32_t*)(g_cath + (size_t)r0*CATN + col)
            = h2_u32(__floats2half2_rn(o[nt][0]*rl0, o[nt][1]*rl0));
        *(uint32_t*)(g_cath + (size_t)r1*CATN + col)
            = h2_u32(__floats2half2_rn(o[nt][2]*rl1, o[nt][3]*rl1));
    }
}

// ---------------- launch --------------------------------------------------
extern "C" void kernel_launch(void* const* d_in, const int* in_sizes, int n_in,
                              void* d_out, int out_size){
    (void)in_sizes; (void)n_in; (void)out_size;
    const float* x       = (const float*)d_in[0];
    const float* vec     = (const float*)d_in[1];
    const float* pe      = (const float*)d_in[2];
    const float* mod_w   = (const float*)d_in[3];
    const float* mod_b   = (const float*)d_in[4];
    const float* ln_s    = (const float*)d_in[5];
    const float* ln_b    = (const float*)d_in[6];
    const float* w1      = (const float*)d_in[7];
    const float* b1      = (const float*)d_in[8];
    const float* q_scale = (const float*)d_in[9];
    const float* k_scale = (const float*)d_in[10];
    const float* w2      = (const float*)d_in[11];
    const float* b2      = (const float*)d_in[12];
    float* out = (float*)d_out;

    float *p_mod;
    __half *p_xmodh, *p_cath, *p_w1h, *p_w2h;
    cudaGetSymbolAddress((void**)&p_xmodh, g_xmodh);
    cudaGetSymbolAddress((void**)&p_cath,  g_cath);
    cudaGetSymbolAddress((void**)&p_mod,   g_mod);
    cudaGetSymbolAddress((void**)&p_w1h,   g_w1h);
    cudaGetSymbolAddress((void**)&p_w2h,   g_w2h);

    cudaFuncSetAttribute(attn_f16, cudaFuncAttributeMaxDynamicSharedMemorySize, ATF_SMEM);
    cudaFuncSetAttribute(gemm1_f16, cudaFuncAttributeMaxDynamicSharedMemorySize, G2_SMEM);
    cudaFuncSetAttribute(gemm2_f16, cudaFuncAttributeMaxDynamicSharedMemorySize, G2_SMEM);

    prep<<<NB1 + NB2 + (QKVN + 255)/256, 256>>>((const float4*)w1, (uint2*)p_w1h,
                                                (const float4*)w2, (uint2*)p_w2h,
                                                vec, mod_b);
    mod_gemv<<<dim3(QKVN/1024, HH/256), 256>>>(mod_w);
    ln_mod  <<<LL, 384>>>(x, ln_s, ln_b);
    gemm1_f16<<<dim3(LL/128, W1N/128), 256, G2_SMEM>>>(p_xmodh, p_w1h, b1,
                                                       pe, q_scale, k_scale,
                                                       W1N, HH, HH/64);
    attn_f16<<<dim3(LL/128, NHH), 256, ATF_SMEM>>>();
    gemm2_f16<<<dim3(LL/128, HH/128), 256, G2_SMEM>>>(p_cath, p_w2h, b2, out,
                                                      HH, CATN, CATN/64,
                                                      x, p_mod + 2*HH);
}